// round 11
// baseline (speedup 1.0000x reference)
#include <cuda_runtime.h>
#include <cuda_bf16.h>
#include <cstdint>

#define B_  2
#define L_  2048
#define D_  1024
#define H_  16
#define DH_ 64
#define BL_ (B_ * L_)

// ============================ helpers ============================
__device__ __forceinline__ uint32_t smem_u32(const void* p) {
    uint32_t a;
    asm("{ .reg .u64 t; cvta.to.shared.u64 t, %1; cvt.u32.u64 %0, t; }" : "=r"(a) : "l"(p));
    return a;
}
#define SMEM_SWIZZLE_128B(x) ((x) ^ (((x) >> 3) & 0x70))

// paired-row layout for 64B logical rows inside a SW128 tile (conflict-free ldmatrix)
__device__ __forceinline__ uint32_t pr64(int r, int c16) {
    uint32_t off = (uint32_t)(((r >> 1) << 7) + ((r & 1) << 6) + (c16 << 4));
    return SMEM_SWIZZLE_128B(off);
}

__device__ __forceinline__ void cp_async16(uint32_t dst, const void* src) {
    asm volatile("cp.async.ca.shared.global [%0], [%1], 16;" :: "r"(dst), "l"(src) : "memory");
}
#define CP_COMMIT() asm volatile("cp.async.commit_group;" ::: "memory")

__device__ __forceinline__ void ldm_x4(uint32_t* r, uint32_t addr) {
    asm volatile("ldmatrix.sync.aligned.m8n8.x4.shared.b16 {%0,%1,%2,%3}, [%4];"
        : "=r"(r[0]), "=r"(r[1]), "=r"(r[2]), "=r"(r[3]) : "r"(addr));
}
__device__ __forceinline__ void ldm_x4_t(uint32_t* r, uint32_t addr) {
    asm volatile("ldmatrix.sync.aligned.m8n8.x4.trans.shared.b16 {%0,%1,%2,%3}, [%4];"
        : "=r"(r[0]), "=r"(r[1]), "=r"(r[2]), "=r"(r[3]) : "r"(addr));
}

__device__ __forceinline__ void mma16816(float* c, const uint32_t* a, const uint32_t* b) {
    asm volatile("mma.sync.aligned.m16n8k16.row.col.f32.bf16.bf16.f32 "
        "{%0,%1,%2,%3}, {%4,%5,%6,%7}, {%8,%9}, {%0,%1,%2,%3};"
        : "+f"(c[0]), "+f"(c[1]), "+f"(c[2]), "+f"(c[3])
        : "r"(a[0]), "r"(a[1]), "r"(a[2]), "r"(a[3]), "r"(b[0]), "r"(b[1]));
}

// exp(x) for x <= 0, FMA/ALU pipes only. abs err <= ~3e-5.
__device__ __forceinline__ float exp_fast(float x) {
    float t = x * 1.44269504f;
    t = fmaxf(t, -126.0f);
    float fi = floorf(t);
    float f = t - fi;
    float r = 1.54035304e-4f;
    r = fmaf(r, f, 1.33335581e-3f);
    r = fmaf(r, f, 9.61812911e-3f);
    r = fmaf(r, f, 5.55041087e-2f);
    r = fmaf(r, f, 2.40226507e-1f);
    r = fmaf(r, f, 6.93147181e-1f);
    r = fmaf(r, f, 1.0f);
    return r * __int_as_float(((int)fi + 127) << 23);
}

__device__ __forceinline__ void hilo_pack(float a, float b, uint32_t& hi, uint32_t& lo) {
    __nv_bfloat16 ah = __float2bfloat16(a);
    __nv_bfloat16 bh = __float2bfloat16(b);
    __nv_bfloat16 al = __float2bfloat16(a - __bfloat162float(ah));
    __nv_bfloat16 bl = __float2bfloat16(b - __bfloat162float(bh));
    __nv_bfloat162 h2(ah, bh), l2(al, bl);
    hi = *(uint32_t*)&h2;
    lo = *(uint32_t*)&l2;
}

// ============================ scratch globals ============================
__device__ __nv_bfloat16 g_xhi[BL_ * D_];
__device__ __nv_bfloat16 g_xlo[BL_ * D_];
__device__ __nv_bfloat16 g_whi[4 * D_ * D_];
__device__ __nv_bfloat16 g_wlo[4 * D_ * D_];
__device__ __nv_bfloat16 g_qhi[BL_ * D_];
__device__ __nv_bfloat16 g_qlo[BL_ * D_];
__device__ __nv_bfloat16 g_khi[BL_ * D_];
__device__ __nv_bfloat16 g_klo[BL_ * D_];
__device__ __nv_bfloat16 g_vhi[BL_ * D_];
__device__ __nv_bfloat16 g_vlo[BL_ * D_];
__device__ __nv_bfloat16 g_ohi[BL_ * D_];
__device__ __nv_bfloat16 g_olo[BL_ * D_];

__device__ const float g_invfreq[32] = {
    1.0f, 0.7498942093324559f, 0.5623413251903491f, 0.4216965034285823f,
    0.31622776601683794f, 0.2371373705661655f, 0.1778279410038923f, 0.13335214321633237f,
    0.1f, 0.07498942093324559f, 0.05623413251903491f, 0.04216965034285823f,
    0.031622776601683794f, 0.02371373705661655f, 0.01778279410038923f, 0.013335214321633237f,
    0.01f, 0.007498942093324559f, 0.005623413251903491f, 0.004216965034285823f,
    0.0031622776601683794f, 0.002371373705661655f, 0.001778279410038923f, 0.0013335214321633237f,
    0.001f, 0.0007498942093324559f, 0.0005623413251903491f, 0.0004216965034285823f,
    0.00031622776601683794f, 0.0002371373705661655f, 0.0001778279410038923f, 0.00013335214321633237f
};

// ============================ fp32 -> bf16 hi/lo splits ============================
__global__ __launch_bounds__(256) void split_bf16(const float* __restrict__ src,
                                                  __nv_bfloat16* __restrict__ hi,
                                                  __nv_bfloat16* __restrict__ lo,
                                                  int n4)
{
    int i = blockIdx.x * 256 + threadIdx.x;
    if (i >= n4) return;
    float4 v = ((const float4*)src)[i];
    float f[4] = {v.x, v.y, v.z, v.w};
    __nv_bfloat16 h[4], l[4];
#pragma unroll
    for (int j = 0; j < 4; j++) {
        h[j] = __float2bfloat16(f[j]);
        l[j] = __float2bfloat16(f[j] - __bfloat162float(h[j]));
    }
    ((__nv_bfloat162*)hi)[2 * i + 0] = __nv_bfloat162(h[0], h[1]);
    ((__nv_bfloat162*)hi)[2 * i + 1] = __nv_bfloat162(h[2], h[3]);
    ((__nv_bfloat162*)lo)[2 * i + 0] = __nv_bfloat162(l[0], l[1]);
    ((__nv_bfloat162*)lo)[2 * i + 1] = __nv_bfloat162(l[2], l[3]);
}

__global__ __launch_bounds__(256) void split_w4(const float* __restrict__ Wq,
                                                const float* __restrict__ Wk,
                                                const float* __restrict__ Wv,
                                                const float* __restrict__ Wo,
                                                __nv_bfloat16* __restrict__ whi,
                                                __nv_bfloat16* __restrict__ wlo)
{
    const int z = blockIdx.y;
    const float* src = (z == 0) ? Wq : (z == 1) ? Wk : (z == 2) ? Wv : Wo;
    __nv_bfloat16* hi = whi + (size_t)z * D_ * D_;
    __nv_bfloat16* lo = wlo + (size_t)z * D_ * D_;
    int i = blockIdx.x * 256 + threadIdx.x;
    float4 v = ((const float4*)src)[i];
    float f[4] = {v.x, v.y, v.z, v.w};
    __nv_bfloat16 h[4], l[4];
#pragma unroll
    for (int j = 0; j < 4; j++) {
        h[j] = __float2bfloat16(f[j]);
        l[j] = __float2bfloat16(f[j] - __bfloat162float(h[j]));
    }
    ((__nv_bfloat162*)hi)[2 * i + 0] = __nv_bfloat162(h[0], h[1]);
    ((__nv_bfloat162*)hi)[2 * i + 1] = __nv_bfloat162(h[2], h[3]);
    ((__nv_bfloat162*)lo)[2 * i + 0] = __nv_bfloat162(l[0], l[1]);
    ((__nv_bfloat162*)lo)[2 * i + 1] = __nv_bfloat162(l[2], l[3]);
}

// ============================ HMMA bf16x3 GEMM (R8 exact: 2-stage, 2 syncs) =========
#define GS_STAGE 32768
#define GS_SMEM  (2 * GS_STAGE)
#define GS_NCHUNK 32

__device__ __forceinline__ void gt_fill32(uint32_t base,
                                          const __nv_bfloat16* Ahi, const __nv_bfloat16* Alo,
                                          const __nv_bfloat16* Bhi, const __nv_bfloat16* Blo,
                                          int m0, int n0, int k0, int tid)
{
#pragma unroll
    for (int j = 0; j < 2; j++) {
        int id = tid + j * 256;
        int r  = id >> 2;
        int c  = id & 3;
        uint32_t sw = pr64(r, c);
        size_t aoff = (size_t)(m0 + r) * D_ + k0 + c * 8;
        size_t boff = (size_t)(n0 + r) * D_ + k0 + c * 8;
        cp_async16(base + 0     + sw, Ahi + aoff);
        cp_async16(base + 8192  + sw, Alo + aoff);
        cp_async16(base + 16384 + sw, Bhi + boff);
        cp_async16(base + 24576 + sw, Blo + boff);
    }
}

__device__ __forceinline__ void gemm32_core(uint32_t sb,
                                            const __nv_bfloat16* __restrict__ Ahi,
                                            const __nv_bfloat16* __restrict__ Alo,
                                            const __nv_bfloat16* __restrict__ Bhi,
                                            const __nv_bfloat16* __restrict__ Blo,
                                            int m0, int n0, float acc[4][4][4])
{
    const int tid = threadIdx.x;
    const int wid = tid >> 5;
    const int lid = tid & 31;
    const int wm  = wid >> 2;
    const int wn  = wid & 3;

#pragma unroll
    for (int mt = 0; mt < 4; mt++)
#pragma unroll
        for (int nt = 0; nt < 4; nt++)
#pragma unroll
            for (int r = 0; r < 4; r++) acc[mt][nt][r] = 0.0f;

    gt_fill32(sb, Ahi, Alo, Bhi, Blo, m0, n0, 0, tid);
    CP_COMMIT();
    gt_fill32(sb + GS_STAGE, Ahi, Alo, Bhi, Blo, m0, n0, 32, tid);
    CP_COMMIT();

    const int a_row = (lid & 15);
    const int a_kc  = (lid >> 4);
    const int b_row = (lid & 7) + ((lid >> 4) << 3);
    const int b_kc  = (lid >> 3) & 1;

    for (int i = 0; i < GS_NCHUNK; i++) {
        if (i == GS_NCHUNK - 1) asm volatile("cp.async.wait_group 0;" ::: "memory");
        else                    asm volatile("cp.async.wait_group 1;" ::: "memory");
        __syncthreads();

        const uint32_t tb = sb + (i & 1) * GS_STAGE;

#pragma unroll
        for (int ks = 0; ks < 2; ks++) {
            uint32_t bhi[4][2], blo[4][2];
#pragma unroll
            for (int ng = 0; ng < 2; ng++) {
                const int nrow = wn * 32 + ng * 16 + b_row;
                const uint32_t sw = pr64(nrow, ks * 2 + b_kc);
                uint32_t r[4];
                ldm_x4(r, tb + 16384 + sw);
                bhi[2 * ng][0] = r[0]; bhi[2 * ng][1] = r[1];
                bhi[2 * ng + 1][0] = r[2]; bhi[2 * ng + 1][1] = r[3];
                ldm_x4(r, tb + 24576 + sw);
                blo[2 * ng][0] = r[0]; blo[2 * ng][1] = r[1];
                blo[2 * ng + 1][0] = r[2]; blo[2 * ng + 1][1] = r[3];
            }
#pragma unroll
            for (int mt = 0; mt < 4; mt++) {
                const int mrow = wm * 64 + mt * 16 + a_row;
                const uint32_t sw = pr64(mrow, ks * 2 + a_kc);
                uint32_t ahi[4], alo[4];
                ldm_x4(ahi, tb + 0 + sw);
                ldm_x4(alo, tb + 8192 + sw);
#pragma unroll
                for (int nt = 0; nt < 4; nt++) {
                    mma16816(acc[mt][nt], ahi, bhi[nt]);
                    mma16816(acc[mt][nt], ahi, blo[nt]);
                    mma16816(acc[mt][nt], alo, bhi[nt]);
                }
            }
        }
        __syncthreads();

        if (i + 2 < GS_NCHUNK) {
            gt_fill32(sb + (i & 1) * GS_STAGE, Ahi, Alo, Bhi, Blo, m0, n0, (i + 2) * 32, tid);
            CP_COMMIT();
        }
    }
}

__global__ __launch_bounds__(256, 2) void gemm_qkv_fused(
    const __nv_bfloat16* __restrict__ xhi, const __nv_bfloat16* __restrict__ xlo,
    const __nv_bfloat16* __restrict__ whi, const __nv_bfloat16* __restrict__ wlo,
    const int* __restrict__ pos,
    __nv_bfloat16* __restrict__ qhi, __nv_bfloat16* __restrict__ qlo,
    __nv_bfloat16* __restrict__ khi, __nv_bfloat16* __restrict__ klo,
    __nv_bfloat16* __restrict__ vhi, __nv_bfloat16* __restrict__ vlo)
{
    extern __shared__ __align__(1024) char smem[];
    uint32_t sb = smem_u32(smem);
    const int z  = blockIdx.z;
    const int m0 = blockIdx.y * 128;
    const int n0 = blockIdx.x * 128;

    float acc[4][4][4];
    gemm32_core(sb, xhi, xlo,
                whi + (size_t)z * D_ * D_, wlo + (size_t)z * D_ * D_,
                m0, n0, acc);

    const int lid = threadIdx.x & 31;
    const int wid = threadIdx.x >> 5;
    const int wm  = wid >> 2;
    const int wn  = wid & 3;

    __nv_bfloat16 *oh, *ol;
    if      (z == 0) { oh = qhi; ol = qlo; }
    else if (z == 1) { oh = khi; ol = klo; }
    else             { oh = vhi; ol = vlo; }
    const float scale = (z == 0) ? 0.125f : 1.0f;

#pragma unroll
    for (int mt = 0; mt < 4; mt++) {
        const int row = m0 + wm * 64 + mt * 16 + (lid >> 2);
#pragma unroll
        for (int nt = 0; nt < 4; nt++) {
            const int col = n0 + wn * 32 + nt * 8 + (lid & 3) * 2;
            float c0 = acc[mt][nt][0], c1 = acc[mt][nt][1];
            float c2 = acc[mt][nt][2], c3 = acc[mt][nt][3];
            if (z < 2) {
                const float invf = g_invfreq[(col & 63) >> 1];
                float s0, q0, s1, q1;
                sincosf((float)pos[row & (L_ - 1)] * invf, &s0, &q0);
                sincosf((float)pos[(row + 8) & (L_ - 1)] * invf, &s1, &q1);
                float t0 = (c0 * q0 - c1 * s0) * scale;
                float t1 = (c0 * s0 + c1 * q0) * scale;
                float t2 = (c2 * q1 - c3 * s1) * scale;
                float t3 = (c2 * s1 + c3 * q1) * scale;
                c0 = t0; c1 = t1; c2 = t2; c3 = t3;
            }
            uint32_t hi, lo;
            size_t adr = (size_t)row * D_ + col;
            hilo_pack(c0, c1, hi, lo);
            *(uint32_t*)(oh + adr) = hi;
            *(uint32_t*)(ol + adr) = lo;
            adr += (size_t)8 * D_;
            hilo_pack(c2, c3, hi, lo);
            *(uint32_t*)(oh + adr) = hi;
            *(uint32_t*)(ol + adr) = lo;
        }
    }
}

__global__ __launch_bounds__(256, 2) void gemm_out(
    const __nv_bfloat16* __restrict__ ahi, const __nv_bfloat16* __restrict__ alo,
    const __nv_bfloat16* __restrict__ whi, const __nv_bfloat16* __restrict__ wlo,
    float* __restrict__ C)
{
    extern __shared__ __align__(1024) char smem[];
    uint32_t sb = smem_u32(smem);
    const int m0 = blockIdx.y * 128;
    const int n0 = blockIdx.x * 128;

    float acc[4][4][4];
    gemm32_core(sb, ahi, alo, whi, wlo, m0, n0, acc);

    const int lid = threadIdx.x & 31;
    const int wid = threadIdx.x >> 5;
    const int wm  = wid >> 2;
    const int wn  = wid & 3;
#pragma unroll
    for (int mt = 0; mt < 4; mt++) {
        const int row = m0 + wm * 64 + mt * 16 + (lid >> 2);
#pragma unroll
        for (int nt = 0; nt < 4; nt++) {
            const int col = n0 + wn * 32 + nt * 8 + (lid & 3) * 2;
            *(float2*)&C[(size_t)row * D_ + col]       = make_float2(acc[mt][nt][0], acc[mt][nt][1]);
            *(float2*)&C[(size_t)(row + 8) * D_ + col] = make_float2(acc[mt][nt][2], acc[mt][nt][3]);
        }
    }
}

// ============================ paired-tile attention, phase-staggered ==================
#define AT_KV0   32768
#define AT_STAGE 32768
#define AT_SMEM  (AT_KV0 + 2 * AT_STAGE)

__device__ __forceinline__ void at_fill(uint32_t sb, int stage, size_t gbase, int k0,
                                        const __nv_bfloat16* khi, const __nv_bfloat16* klo,
                                        const __nv_bfloat16* vhi, const __nv_bfloat16* vlo,
                                        int tid)
{
    uint32_t kb = sb + AT_KV0 + stage * AT_STAGE;
#pragma unroll
    for (int j = 0; j < 4; j++) {
        int id = tid + j * 128;
        int r  = id >> 3;
        int c  = id & 7;
        uint32_t sw = SMEM_SWIZZLE_128B((uint32_t)(r * 128 + c * 16));
        size_t off = gbase + (size_t)(k0 + r) * D_ + c * 8;
        cp_async16(kb + 0     + sw, khi + off);
        cp_async16(kb + 8192  + sw, klo + off);
        cp_async16(kb + 16384 + sw, vhi + off);
        cp_async16(kb + 24576 + sw, vlo + off);
    }
}

__device__ __forceinline__ void attn_step(uint32_t kb,
                                          const uint32_t (&qh)[4][4], const uint32_t (&ql)[4][4],
                                          float (&o)[8][4], float (&m_run)[2], float (&l_run)[2],
                                          bool diag, int wid, int lid)
{
    const int brow = (lid & 7) + ((lid >> 4) << 3);
    const int bkc  = (lid >> 3) & 1;
    const int vrow = lid & 15;
    const int vcol = (lid >> 4) << 3;

    float s[8][4];
#pragma unroll
    for (int j = 0; j < 8; j++)
#pragma unroll
        for (int r = 0; r < 4; r++) s[j][r] = 0.0f;

#pragma unroll
    for (int ks = 0; ks < 4; ks++) {
#pragma unroll
        for (int ng = 0; ng < 4; ng++) {
            uint32_t sw = SMEM_SWIZZLE_128B(
                (uint32_t)((ng * 16 + brow) * 128 + (ks * 2 + bkc) * 16));
            uint32_t kh4[4], kl4[4];
            ldm_x4(kh4, kb + 0 + sw);
            ldm_x4(kl4, kb + 8192 + sw);
            mma16816(s[ng * 2],     qh[ks], kh4 + 0);
            mma16816(s[ng * 2],     qh[ks], kl4 + 0);
            mma16816(s[ng * 2],     ql[ks], kh4 + 0);
            mma16816(s[ng * 2 + 1], qh[ks], kh4 + 2);
            mma16816(s[ng * 2 + 1], qh[ks], kl4 + 2);
            mma16816(s[ng * 2 + 1], ql[ks], kh4 + 2);
        }
    }

    if (diag) {
        const int rlo = wid * 16 + (lid >> 2);
#pragma unroll
        for (int j = 0; j < 8; j++) {
            const int cb = ((j >> 1) << 4) + ((j & 1) << 3) + ((lid & 3) << 1);
            if (cb     > rlo)     s[j][0] = -1e30f;
            if (cb + 1 > rlo)     s[j][1] = -1e30f;
            if (cb     > rlo + 8) s[j][2] = -1e30f;
            if (cb + 1 > rlo + 8) s[j][3] = -1e30f;
        }
    }

    float mx0 = -1e30f, mx1 = -1e30f;
#pragma unroll
    for (int j = 0; j < 8; j++) {
        mx0 = fmaxf(mx0, fmaxf(s[j][0], s[j][1]));
        mx1 = fmaxf(mx1, fmaxf(s[j][2], s[j][3]));
    }
    mx0 = fmaxf(mx0, __shfl_xor_sync(0xffffffffu, mx0, 1));
    mx0 = fmaxf(mx0, __shfl_xor_sync(0xffffffffu, mx0, 2));
    mx1 = fmaxf(mx1, __shfl_xor_sync(0xffffffffu, mx1, 1));
    mx1 = fmaxf(mx1, __shfl_xor_sync(0xffffffffu, mx1, 2));
    const float mn0 = fmaxf(m_run[0], mx0);
    const float mn1 = fmaxf(m_run[1], mx1);
    const float cr0 = exp_fast(m_run[0] - mn0);
    const float cr1 = exp_fast(m_run[1] - mn1);
    m_run[0] = mn0; m_run[1] = mn1;

    float ps0 = 0.0f, ps1 = 0.0f;
#pragma unroll
    for (int j = 0; j < 8; j++) {
        s[j][0] = exp_fast(s[j][0] - mn0); ps0 += s[j][0];
        s[j][1] = exp_fast(s[j][1] - mn0); ps0 += s[j][1];
        s[j][2] = exp_fast(s[j][2] - mn1); ps1 += s[j][2];
        s[j][3] = exp_fast(s[j][3] - mn1); ps1 += s[j][3];
    }
    ps0 += __shfl_xor_sync(0xffffffffu, ps0, 1);
    ps0 += __shfl_xor_sync(0xffffffffu, ps0, 2);
    ps1 += __shfl_xor_sync(0xffffffffu, ps1, 1);
    ps1 += __shfl_xor_sync(0xffffffffu, ps1, 2);
    l_run[0] = l_run[0] * cr0 + ps0;
    l_run[1] = l_run[1] * cr1 + ps1;

#pragma unroll
    for (int j = 0; j < 8; j++) {
        o[j][0] *= cr0; o[j][1] *= cr0;
        o[j][2] *= cr1; o[j][3] *= cr1;
    }

    uint32_t ph[4][4], pl[4][4];
#pragma unroll
    for (int kc = 0; kc < 4; kc++) {
        hilo_pack(s[2 * kc][0],     s[2 * kc][1],     ph[kc][0], pl[kc][0]);
        hilo_pack(s[2 * kc][2],     s[2 * kc][3],     ph[kc][1], pl[kc][1]);
        hilo_pack(s[2 * kc + 1][0], s[2 * kc + 1][1], ph[kc][2], pl[kc][2]);
        hilo_pack(s[2 * kc + 1][2], s[2 * kc + 1][3], ph[kc][3], pl[kc][3]);
    }

    const uint32_t vb = kb + 16384;
#pragma unroll
    for (int kc = 0; kc < 4; kc++) {
#pragma unroll
        for (int nd = 0; nd < 4; nd++) {
            uint32_t sw = SMEM_SWIZZLE_128B(
                (uint32_t)((kc * 16 + vrow) * 128 + (nd * 16 + vcol) * 2));
            uint32_t vh4[4], vl4[4];
            ldm_x4_t(vh4, vb + 0 + sw);
            ldm_x4_t(vl4, vb + 8192 + sw);
            mma16816(o[nd * 2],     ph[kc], vh4 + 0);
            mma16816(o[nd * 2],     ph[kc], vl4 + 0);
            mma16816(o[nd * 2],     pl[kc], vh4 + 0);
            mma16816(o[nd * 2 + 1], ph[kc], vh4 + 2);
            mma16816(o[nd * 2 + 1], ph[kc], vl4 + 2);
            mma16816(o[nd * 2 + 1], pl[kc], vh4 + 2);
        }
    }
}

__device__ __forceinline__ void attn_epilogue(const float (&o)[8][4],
                                              const float (&l_run)[2],
                                              size_t gbase, int q0, int wid, int lid,
                                              __nv_bfloat16* ohi, __nv_bfloat16* olo)
{
    const float inv0 = 1.0f / l_run[0];
    const float inv1 = 1.0f / l_run[1];
    const int rlo = q0 + wid * 16 + (lid >> 2);
#pragma unroll
    for (int j = 0; j < 8; j++) {
        const int col = ((j >> 1) << 4) + ((j & 1) << 3) + ((lid & 3) << 1);
        uint32_t hi, lo;
        size_t adr0 = gbase + (size_t)rlo * D_ + col;
        hilo_pack(o[j][0] * inv0, o[j][1] * inv0, hi, lo);
        *(uint32_t*)(ohi + adr0) = hi;
        *(uint32_t*)(olo + adr0) = lo;
        size_t adr1 = adr0 + (size_t)8 * D_;
        hilo_pack(o[j][2] * inv1, o[j][3] * inv1, hi, lo);
        *(uint32_t*)(ohi + adr1) = hi;
        *(uint32_t*)(olo + adr1) = lo;
    }
}

__global__ __launch_bounds__(128) void attn_mma(const __nv_bfloat16* __restrict__ qhi,
                                                const __nv_bfloat16* __restrict__ qlo,
                                                const __nv_bfloat16* __restrict__ khi,
                                                const __nv_bfloat16* __restrict__ klo,
                                                const __nv_bfloat16* __restrict__ vhi,
                                                const __nv_bfloat16* __restrict__ vlo,
                                                __nv_bfloat16* __restrict__ ohi,
                                                __nv_bfloat16* __restrict__ olo)
{
    extern __shared__ __align__(1024) char smem[];
    uint32_t sb = smem_u32(smem);
    const int tid = threadIdx.x;
    const int wid = tid >> 5;
    const int lid = tid & 31;
    const int p   = blockIdx.x;           // pair id: tiles p and 31-p
    const int qta = p;
    const int qtb = (L_ / 64 - 1) - p;
    const int h   = blockIdx.y;
    const int b   = blockIdx.z;
    const size_t gbase = (size_t)(b * L_) * D_ + h * DH_;

#pragma unroll
    for (int j = 0; j < 4; j++) {
        int id = tid + j * 128;
        int r  = id >> 3;
        int c  = id & 7;
        uint32_t sw = SMEM_SWIZZLE_128B((uint32_t)(r * 128 + c * 16));
        size_t offa = gbase + (size_t)(qta * 64 + r) * D_ + c * 8;
        size_t offb = gbase + (size_t)(qtb * 64 + r) * D_ + c * 8;
        cp_async16(sb + 0     + sw, qhi + offa);
        cp_async16(sb + 8192  + sw, qlo + offa);
        cp_async16(sb + 16384 + sw, qhi + offb);
        cp_async16(sb + 24576 + sw, qlo + offb);
    }
    CP_COMMIT();
    at_fill(sb, 0, gbase, 0, khi, klo, vhi, vlo, tid);
    CP_COMMIT();
    asm volatile("cp.async.wait_group 0;" ::: "memory");
    __syncthreads();

    uint32_t qhA[4][4], qlA[4][4], qhB[4][4], qlB[4][4];
    {
        const int arow = wid * 16 + (lid & 15);
        const int akc  = lid >> 4;
#pragma unroll
        for (int ks = 0; ks < 4; ks++) {
            uint32_t sw = SMEM_SWIZZLE_128B((uint32_t)(arow * 128 + (ks * 2 + akc) * 16));
            ldm_x4(qhA[ks], sb + 0 + sw);
            ldm_x4(qlA[ks], sb + 8192 + sw);
            ldm_x4(qhB[ks], sb + 16384 + sw);
            ldm_x4(qlB[ks], sb + 24576 + sw);
        }
    }

    float mA[2] = {-1e30f, -1e30f}, lA[2] = {0.0f, 0.0f};
    float mB[2] = {-1e30f, -1e30f}, lB[2] = {0.0f, 0.0f};
    float oA[8][4], oB[8][4];
#pragma unroll
    for (int j = 0; j < 8; j++)
#pragma unroll
        for (int r = 0; r < 4; r++) { oA[j][r] = 0.0f; oB[j][r] = 0.0f; }

    const bool b_first = (wid & 1);    // phase stagger: odd warps run tile B first
    const int nkt = qtb + 1;
    for (int kt = 0; kt < nkt; kt++) {
        __syncthreads();
        if (kt + 1 < nkt) {
            at_fill(sb, (kt + 1) & 1, gbase, (kt + 1) * 64, khi, klo, vhi, vlo, tid);
            CP_COMMIT();
            asm volatile("cp.async.wait_group 1;" ::: "memory");
        } else {
            asm volatile("cp.async.wait_group 0;" ::: "memory");
        }
        __syncthreads();

        const uint32_t kb = sb + AT_KV0 + (kt & 1) * AT_STAGE;

        if (b_first) {
            attn_step(kb, qhB, qlB, oB, mB, lB, kt == qtb, wid, lid);
            if (kt <= qta)
                attn_step(kb, qhA, qlA, oA, mA, lA, kt == qta, wid, lid);
        } else {
            if (kt <= qta)
                attn_step(kb, qhA, qlA, oA, mA, lA, kt == qta, wid, lid);
            attn_step(kb, qhB, qlB, oB, mB, lB, kt == qtb, wid, lid);
        }
    }

    attn_epilogue(oA, lA, gbase, qta * 64, wid, lid, ohi, olo);
    attn_epilogue(oB, lB, gbase, qtb * 64, wid, lid, ohi, olo);
}

// ============================ launch ============================
extern "C" void kernel_launch(void* const* d_in, const int* in_sizes, int n_in,
                              void* d_out, int out_size)
{
    const float* x   = (const float*)d_in[0];
    const float* Wq  = (const float*)d_in[1];
    const float* Wk  = (const float*)d_in[2];
    const float* Wv  = (const float*)d_in[3];
    const float* Wo  = (const float*)d_in[4];
    const int*   pos = (const int*)  d_in[5];
    float* out = (float*)d_out;

    __nv_bfloat16 *xhi, *xlo, *whi, *wlo;
    __nv_bfloat16 *qhi, *qlo, *khi, *klo, *vhi, *vlo, *ohi, *olo;
    cudaGetSymbolAddress((void**)&xhi, g_xhi);
    cudaGetSymbolAddress((void**)&xlo, g_xlo);
    cudaGetSymbolAddress((void**)&whi, g_whi);
    cudaGetSymbolAddress((void**)&wlo, g_wlo);
    cudaGetSymbolAddress((void**)&qhi, g_qhi);
    cudaGetSymbolAddress((void**)&qlo, g_qlo);
    cudaGetSymbolAddress((void**)&khi, g_khi);
    cudaGetSymbolAddress((void**)&klo, g_klo);
    cudaGetSymbolAddress((void**)&vhi, g_vhi);
    cudaGetSymbolAddress((void**)&vlo, g_vlo);
    cudaGetSymbolAddress((void**)&ohi, g_ohi);
    cudaGetSymbolAddress((void**)&olo, g_olo);

    cudaFuncSetAttribute(gemm_qkv_fused, cudaFuncAttributeMaxDynamicSharedMemorySize, GS_SMEM);
    cudaFuncSetAttribute(gemm_out,       cudaFuncAttributeMaxDynamicSharedMemorySize, GS_SMEM);
    cudaFuncSetAttribute(attn_mma,       cudaFuncAttributeMaxDynamicSharedMemorySize, AT_SMEM);

    const int nx4 = BL_ * D_ / 4;
    const int nw4 = D_ * D_ / 4;

    split_bf16<<<nx4 / 256, 256>>>(x, xhi, xlo, nx4);
    split_w4<<<dim3(nw4 / 256, 4), 256>>>(Wq, Wk, Wv, Wo, whi, wlo);

    dim3 qkv_grid(D_ / 128, BL_ / 128, 3);
    gemm_qkv_fused<<<qkv_grid, 256, GS_SMEM>>>(xhi, xlo, whi, wlo, pos,
                                               qhi, qlo, khi, klo, vhi, vlo);

    attn_mma<<<dim3(L_ / 128, H_, B_), 128, AT_SMEM>>>(qhi, qlo, khi, klo, vhi, vlo, ohi, olo);

    dim3 ggrid(D_ / 128, BL_ / 128);
    gemm_out<<<ggrid, 256, GS_SMEM>>>(ohi, olo,
                                      whi + 3 * (size_t)D_ * D_,
                                      wlo + 3 * (size_t)D_ * D_, out);
}

// round 12
// speedup vs baseline: 1.0494x; 1.0494x over previous
#include <cuda_runtime.h>
#include <cuda_bf16.h>
#include <cstdint>

#define B_  2
#define L_  2048
#define D_  1024
#define H_  16
#define DH_ 64
#define BL_ (B_ * L_)

// ============================ helpers ============================
__device__ __forceinline__ uint32_t smem_u32(const void* p) {
    uint32_t a;
    asm("{ .reg .u64 t; cvta.to.shared.u64 t, %1; cvt.u32.u64 %0, t; }" : "=r"(a) : "l"(p));
    return a;
}
#define SMEM_SWIZZLE_128B(x) ((x) ^ (((x) >> 3) & 0x70))

// paired-row layout for 64B logical rows inside a SW128 tile (conflict-free ldmatrix)
__device__ __forceinline__ uint32_t pr64(int r, int c16) {
    uint32_t off = (uint32_t)(((r >> 1) << 7) + ((r & 1) << 6) + (c16 << 4));
    return SMEM_SWIZZLE_128B(off);
}

__device__ __forceinline__ void cp_async16(uint32_t dst, const void* src) {
    asm volatile("cp.async.ca.shared.global [%0], [%1], 16;" :: "r"(dst), "l"(src) : "memory");
}
#define CP_COMMIT() asm volatile("cp.async.commit_group;" ::: "memory")

__device__ __forceinline__ void ldm_x4(uint32_t* r, uint32_t addr) {
    asm volatile("ldmatrix.sync.aligned.m8n8.x4.shared.b16 {%0,%1,%2,%3}, [%4];"
        : "=r"(r[0]), "=r"(r[1]), "=r"(r[2]), "=r"(r[3]) : "r"(addr));
}
__device__ __forceinline__ void ldm_x4_t(uint32_t* r, uint32_t addr) {
    asm volatile("ldmatrix.sync.aligned.m8n8.x4.trans.shared.b16 {%0,%1,%2,%3}, [%4];"
        : "=r"(r[0]), "=r"(r[1]), "=r"(r[2]), "=r"(r[3]) : "r"(addr));
}

__device__ __forceinline__ void mma16816(float* c, const uint32_t* a, const uint32_t* b) {
    asm volatile("mma.sync.aligned.m16n8k16.row.col.f32.bf16.bf16.f32 "
        "{%0,%1,%2,%3}, {%4,%5,%6,%7}, {%8,%9}, {%0,%1,%2,%3};"
        : "+f"(c[0]), "+f"(c[1]), "+f"(c[2]), "+f"(c[3])
        : "r"(a[0]), "r"(a[1]), "r"(a[2]), "r"(a[3]), "r"(b[0]), "r"(b[1]));
}

// exp(x) for x <= 0, FMA/ALU pipes only. abs err <= ~3e-5.
__device__ __forceinline__ float exp_fast(float x) {
    float t = x * 1.44269504f;
    t = fmaxf(t, -126.0f);
    float fi = floorf(t);
    float f = t - fi;
    float r = 1.54035304e-4f;
    r = fmaf(r, f, 1.33335581e-3f);
    r = fmaf(r, f, 9.61812911e-3f);
    r = fmaf(r, f, 5.55041087e-2f);
    r = fmaf(r, f, 2.40226507e-1f);
    r = fmaf(r, f, 6.93147181e-1f);
    r = fmaf(r, f, 1.0f);
    return r * __int_as_float(((int)fi + 127) << 23);
}

__device__ __forceinline__ void hilo_pack(float a, float b, uint32_t& hi, uint32_t& lo) {
    __nv_bfloat16 ah = __float2bfloat16(a);
    __nv_bfloat16 bh = __float2bfloat16(b);
    __nv_bfloat16 al = __float2bfloat16(a - __bfloat162float(ah));
    __nv_bfloat16 bl = __float2bfloat16(b - __bfloat162float(bh));
    __nv_bfloat162 h2(ah, bh), l2(al, bl);
    hi = *(uint32_t*)&h2;
    lo = *(uint32_t*)&l2;
}

// ============================ scratch globals ============================
__device__ __nv_bfloat16 g_xhi[BL_ * D_];
__device__ __nv_bfloat16 g_xlo[BL_ * D_];
__device__ __nv_bfloat16 g_whi[4 * D_ * D_];
__device__ __nv_bfloat16 g_wlo[4 * D_ * D_];
__device__ __nv_bfloat16 g_qhi[BL_ * D_];
__device__ __nv_bfloat16 g_qlo[BL_ * D_];
__device__ __nv_bfloat16 g_khi[BL_ * D_];
__device__ __nv_bfloat16 g_klo[BL_ * D_];
__device__ __nv_bfloat16 g_vhi[BL_ * D_];
__device__ __nv_bfloat16 g_vlo[BL_ * D_];
__device__ __nv_bfloat16 g_ohi[BL_ * D_];
__device__ __nv_bfloat16 g_olo[BL_ * D_];

__device__ const float g_invfreq[32] = {
    1.0f, 0.7498942093324559f, 0.5623413251903491f, 0.4216965034285823f,
    0.31622776601683794f, 0.2371373705661655f, 0.1778279410038923f, 0.13335214321633237f,
    0.1f, 0.07498942093324559f, 0.05623413251903491f, 0.04216965034285823f,
    0.031622776601683794f, 0.02371373705661655f, 0.01778279410038923f, 0.013335214321633237f,
    0.01f, 0.007498942093324559f, 0.005623413251903491f, 0.004216965034285823f,
    0.0031622776601683794f, 0.002371373705661655f, 0.001778279410038923f, 0.0013335214321633237f,
    0.001f, 0.0007498942093324559f, 0.0005623413251903491f, 0.0004216965034285823f,
    0.00031622776601683794f, 0.0002371373705661655f, 0.0001778279410038923f, 0.00013335214321633237f
};

// ============================ fp32 -> bf16 hi/lo splits ============================
__global__ __launch_bounds__(256) void split_bf16(const float* __restrict__ src,
                                                  __nv_bfloat16* __restrict__ hi,
                                                  __nv_bfloat16* __restrict__ lo,
                                                  int n4)
{
    int i = blockIdx.x * 256 + threadIdx.x;
    if (i >= n4) return;
    float4 v = ((const float4*)src)[i];
    float f[4] = {v.x, v.y, v.z, v.w};
    __nv_bfloat16 h[4], l[4];
#pragma unroll
    for (int j = 0; j < 4; j++) {
        h[j] = __float2bfloat16(f[j]);
        l[j] = __float2bfloat16(f[j] - __bfloat162float(h[j]));
    }
    ((__nv_bfloat162*)hi)[2 * i + 0] = __nv_bfloat162(h[0], h[1]);
    ((__nv_bfloat162*)hi)[2 * i + 1] = __nv_bfloat162(h[2], h[3]);
    ((__nv_bfloat162*)lo)[2 * i + 0] = __nv_bfloat162(l[0], l[1]);
    ((__nv_bfloat162*)lo)[2 * i + 1] = __nv_bfloat162(l[2], l[3]);
}

__global__ __launch_bounds__(256) void split_w4(const float* __restrict__ Wq,
                                                const float* __restrict__ Wk,
                                                const float* __restrict__ Wv,
                                                const float* __restrict__ Wo,
                                                __nv_bfloat16* __restrict__ whi,
                                                __nv_bfloat16* __restrict__ wlo)
{
    const int z = blockIdx.y;
    const float* src = (z == 0) ? Wq : (z == 1) ? Wk : (z == 2) ? Wv : Wo;
    __nv_bfloat16* hi = whi + (size_t)z * D_ * D_;
    __nv_bfloat16* lo = wlo + (size_t)z * D_ * D_;
    int i = blockIdx.x * 256 + threadIdx.x;
    float4 v = ((const float4*)src)[i];
    float f[4] = {v.x, v.y, v.z, v.w};
    __nv_bfloat16 h[4], l[4];
#pragma unroll
    for (int j = 0; j < 4; j++) {
        h[j] = __float2bfloat16(f[j]);
        l[j] = __float2bfloat16(f[j] - __bfloat162float(h[j]));
    }
    ((__nv_bfloat162*)hi)[2 * i + 0] = __nv_bfloat162(h[0], h[1]);
    ((__nv_bfloat162*)hi)[2 * i + 1] = __nv_bfloat162(h[2], h[3]);
    ((__nv_bfloat162*)lo)[2 * i + 0] = __nv_bfloat162(l[0], l[1]);
    ((__nv_bfloat162*)lo)[2 * i + 1] = __nv_bfloat162(l[2], l[3]);
}

// ============================ HMMA bf16x3 GEMM (R8 exact) ============
#define GS_STAGE 32768
#define GS_SMEM  (2 * GS_STAGE)
#define GS_NCHUNK 32

__device__ __forceinline__ void gt_fill32(uint32_t base,
                                          const __nv_bfloat16* Ahi, const __nv_bfloat16* Alo,
                                          const __nv_bfloat16* Bhi, const __nv_bfloat16* Blo,
                                          int m0, int n0, int k0, int tid)
{
#pragma unroll
    for (int j = 0; j < 2; j++) {
        int id = tid + j * 256;
        int r  = id >> 2;
        int c  = id & 3;
        uint32_t sw = pr64(r, c);
        size_t aoff = (size_t)(m0 + r) * D_ + k0 + c * 8;
        size_t boff = (size_t)(n0 + r) * D_ + k0 + c * 8;
        cp_async16(base + 0     + sw, Ahi + aoff);
        cp_async16(base + 8192  + sw, Alo + aoff);
        cp_async16(base + 16384 + sw, Bhi + boff);
        cp_async16(base + 24576 + sw, Blo + boff);
    }
}

__device__ __forceinline__ void gemm32_core(uint32_t sb,
                                            const __nv_bfloat16* __restrict__ Ahi,
                                            const __nv_bfloat16* __restrict__ Alo,
                                            const __nv_bfloat16* __restrict__ Bhi,
                                            const __nv_bfloat16* __restrict__ Blo,
                                            int m0, int n0, float acc[4][4][4])
{
    const int tid = threadIdx.x;
    const int wid = tid >> 5;
    const int lid = tid & 31;
    const int wm  = wid >> 2;
    const int wn  = wid & 3;

#pragma unroll
    for (int mt = 0; mt < 4; mt++)
#pragma unroll
        for (int nt = 0; nt < 4; nt++)
#pragma unroll
            for (int r = 0; r < 4; r++) acc[mt][nt][r] = 0.0f;

    gt_fill32(sb, Ahi, Alo, Bhi, Blo, m0, n0, 0, tid);
    CP_COMMIT();
    gt_fill32(sb + GS_STAGE, Ahi, Alo, Bhi, Blo, m0, n0, 32, tid);
    CP_COMMIT();

    const int a_row = (lid & 15);
    const int a_kc  = (lid >> 4);
    const int b_row = (lid & 7) + ((lid >> 4) << 3);
    const int b_kc  = (lid >> 3) & 1;

    for (int i = 0; i < GS_NCHUNK; i++) {
        if (i == GS_NCHUNK - 1) asm volatile("cp.async.wait_group 0;" ::: "memory");
        else                    asm volatile("cp.async.wait_group 1;" ::: "memory");
        __syncthreads();

        const uint32_t tb = sb + (i & 1) * GS_STAGE;

#pragma unroll
        for (int ks = 0; ks < 2; ks++) {
            uint32_t bhi[4][2], blo[4][2];
#pragma unroll
            for (int ng = 0; ng < 2; ng++) {
                const int nrow = wn * 32 + ng * 16 + b_row;
                const uint32_t sw = pr64(nrow, ks * 2 + b_kc);
                uint32_t r[4];
                ldm_x4(r, tb + 16384 + sw);
                bhi[2 * ng][0] = r[0]; bhi[2 * ng][1] = r[1];
                bhi[2 * ng + 1][0] = r[2]; bhi[2 * ng + 1][1] = r[3];
                ldm_x4(r, tb + 24576 + sw);
                blo[2 * ng][0] = r[0]; blo[2 * ng][1] = r[1];
                blo[2 * ng + 1][0] = r[2]; blo[2 * ng + 1][1] = r[3];
            }
#pragma unroll
            for (int mt = 0; mt < 4; mt++) {
                const int mrow = wm * 64 + mt * 16 + a_row;
                const uint32_t sw = pr64(mrow, ks * 2 + a_kc);
                uint32_t ahi[4], alo[4];
                ldm_x4(ahi, tb + 0 + sw);
                ldm_x4(alo, tb + 8192 + sw);
#pragma unroll
                for (int nt = 0; nt < 4; nt++) {
                    mma16816(acc[mt][nt], ahi, bhi[nt]);
                    mma16816(acc[mt][nt], ahi, blo[nt]);
                    mma16816(acc[mt][nt], alo, bhi[nt]);
                }
            }
        }
        __syncthreads();

        if (i + 2 < GS_NCHUNK) {
            gt_fill32(sb + (i & 1) * GS_STAGE, Ahi, Alo, Bhi, Blo, m0, n0, (i + 2) * 32, tid);
            CP_COMMIT();
        }
    }
}

__global__ __launch_bounds__(256, 2) void gemm_qkv_fused(
    const __nv_bfloat16* __restrict__ xhi, const __nv_bfloat16* __restrict__ xlo,
    const __nv_bfloat16* __restrict__ whi, const __nv_bfloat16* __restrict__ wlo,
    const int* __restrict__ pos,
    __nv_bfloat16* __restrict__ qhi, __nv_bfloat16* __restrict__ qlo,
    __nv_bfloat16* __restrict__ khi, __nv_bfloat16* __restrict__ klo,
    __nv_bfloat16* __restrict__ vhi, __nv_bfloat16* __restrict__ vlo)
{
    extern __shared__ __align__(1024) char smem[];
    uint32_t sb = smem_u32(smem);
    const int z  = blockIdx.z;
    const int m0 = blockIdx.y * 128;
    const int n0 = blockIdx.x * 128;

    float acc[4][4][4];
    gemm32_core(sb, xhi, xlo,
                whi + (size_t)z * D_ * D_, wlo + (size_t)z * D_ * D_,
                m0, n0, acc);

    const int lid = threadIdx.x & 31;
    const int wid = threadIdx.x >> 5;
    const int wm  = wid >> 2;
    const int wn  = wid & 3;

    __nv_bfloat16 *oh, *ol;
    if      (z == 0) { oh = qhi; ol = qlo; }
    else if (z == 1) { oh = khi; ol = klo; }
    else             { oh = vhi; ol = vlo; }
    const float scale = (z == 0) ? 0.125f : 1.0f;

#pragma unroll
    for (int mt = 0; mt < 4; mt++) {
        const int row = m0 + wm * 64 + mt * 16 + (lid >> 2);
#pragma unroll
        for (int nt = 0; nt < 4; nt++) {
            const int col = n0 + wn * 32 + nt * 8 + (lid & 3) * 2;
            float c0 = acc[mt][nt][0], c1 = acc[mt][nt][1];
            float c2 = acc[mt][nt][2], c3 = acc[mt][nt][3];
            if (z < 2) {
                const float invf = g_invfreq[(col & 63) >> 1];
                float s0, q0, s1, q1;
                sincosf((float)pos[row & (L_ - 1)] * invf, &s0, &q0);
                sincosf((float)pos[(row + 8) & (L_ - 1)] * invf, &s1, &q1);
                float t0 = (c0 * q0 - c1 * s0) * scale;
                float t1 = (c0 * s0 + c1 * q0) * scale;
                float t2 = (c2 * q1 - c3 * s1) * scale;
                float t3 = (c2 * s1 + c3 * q1) * scale;
                c0 = t0; c1 = t1; c2 = t2; c3 = t3;
            }
            uint32_t hi, lo;
            size_t adr = (size_t)row * D_ + col;
            hilo_pack(c0, c1, hi, lo);
            *(uint32_t*)(oh + adr) = hi;
            *(uint32_t*)(ol + adr) = lo;
            adr += (size_t)8 * D_;
            hilo_pack(c2, c3, hi, lo);
            *(uint32_t*)(oh + adr) = hi;
            *(uint32_t*)(ol + adr) = lo;
        }
    }
}

__global__ __launch_bounds__(256, 2) void gemm_out(
    const __nv_bfloat16* __restrict__ ahi, const __nv_bfloat16* __restrict__ alo,
    const __nv_bfloat16* __restrict__ whi, const __nv_bfloat16* __restrict__ wlo,
    float* __restrict__ C)
{
    extern __shared__ __align__(1024) char smem[];
    uint32_t sb = smem_u32(smem);
    const int m0 = blockIdx.y * 128;
    const int n0 = blockIdx.x * 128;

    float acc[4][4][4];
    gemm32_core(sb, ahi, alo, whi, wlo, m0, n0, acc);

    const int lid = threadIdx.x & 31;
    const int wid = threadIdx.x >> 5;
    const int wm  = wid >> 2;
    const int wn  = wid & 3;
#pragma unroll
    for (int mt = 0; mt < 4; mt++) {
        const int row = m0 + wm * 64 + mt * 16 + (lid >> 2);
#pragma unroll
        for (int nt = 0; nt < 4; nt++) {
            const int col = n0 + wn * 32 + nt * 8 + (lid & 3) * 2;
            *(float2*)&C[(size_t)row * D_ + col]       = make_float2(acc[mt][nt][0], acc[mt][nt][1]);
            *(float2*)&C[(size_t)(row + 8) * D_ + col] = make_float2(acc[mt][nt][2], acc[mt][nt][3]);
        }
    }
}

// ============================ paired-tile attention, fused dual-step ==================
#define AT_KV0   32768
#define AT_STAGE 32768
#define AT_SMEM  (AT_KV0 + 2 * AT_STAGE)

__device__ __forceinline__ void at_fill(uint32_t sb, int stage, size_t gbase, int k0,
                                        const __nv_bfloat16* khi, const __nv_bfloat16* klo,
                                        const __nv_bfloat16* vhi, const __nv_bfloat16* vlo,
                                        int tid)
{
    uint32_t kb = sb + AT_KV0 + stage * AT_STAGE;
#pragma unroll
    for (int j = 0; j < 4; j++) {
        int id = tid + j * 128;
        int r  = id >> 3;
        int c  = id & 7;
        uint32_t sw = SMEM_SWIZZLE_128B((uint32_t)(r * 128 + c * 16));
        size_t off = gbase + (size_t)(k0 + r) * D_ + c * 8;
        cp_async16(kb + 0     + sw, khi + off);
        cp_async16(kb + 8192  + sw, klo + off);
        cp_async16(kb + 16384 + sw, vhi + off);
        cp_async16(kb + 24576 + sw, vlo + off);
    }
}

// mask + online softmax + P pack for one 64x64 S tile held in s[8][4]
__device__ __forceinline__ void softmax_pack(float (&s)[8][4],
                                             float (&o)[8][4],
                                             float (&m_run)[2], float (&l_run)[2],
                                             bool diag, int wid, int lid,
                                             uint32_t (&ph)[4][4], uint32_t (&pl)[4][4])
{
    if (diag) {
        const int rlo = wid * 16 + (lid >> 2);
#pragma unroll
        for (int j = 0; j < 8; j++) {
            const int cb = ((j >> 1) << 4) + ((j & 1) << 3) + ((lid & 3) << 1);
            if (cb     > rlo)     s[j][0] = -1e30f;
            if (cb + 1 > rlo)     s[j][1] = -1e30f;
            if (cb     > rlo + 8) s[j][2] = -1e30f;
            if (cb + 1 > rlo + 8) s[j][3] = -1e30f;
        }
    }

    float mx0 = -1e30f, mx1 = -1e30f;
#pragma unroll
    for (int j = 0; j < 8; j++) {
        mx0 = fmaxf(mx0, fmaxf(s[j][0], s[j][1]));
        mx1 = fmaxf(mx1, fmaxf(s[j][2], s[j][3]));
    }
    mx0 = fmaxf(mx0, __shfl_xor_sync(0xffffffffu, mx0, 1));
    mx0 = fmaxf(mx0, __shfl_xor_sync(0xffffffffu, mx0, 2));
    mx1 = fmaxf(mx1, __shfl_xor_sync(0xffffffffu, mx1, 1));
    mx1 = fmaxf(mx1, __shfl_xor_sync(0xffffffffu, mx1, 2));
    const float mn0 = fmaxf(m_run[0], mx0);
    const float mn1 = fmaxf(m_run[1], mx1);
    const float cr0 = exp_fast(m_run[0] - mn0);
    const float cr1 = exp_fast(m_run[1] - mn1);
    m_run[0] = mn0; m_run[1] = mn1;

    float ps0 = 0.0f, ps1 = 0.0f;
#pragma unroll
    for (int j = 0; j < 8; j++) {
        s[j][0] = exp_fast(s[j][0] - mn0); ps0 += s[j][0];
        s[j][1] = exp_fast(s[j][1] - mn0); ps0 += s[j][1];
        s[j][2] = exp_fast(s[j][2] - mn1); ps1 += s[j][2];
        s[j][3] = exp_fast(s[j][3] - mn1); ps1 += s[j][3];
    }
    ps0 += __shfl_xor_sync(0xffffffffu, ps0, 1);
    ps0 += __shfl_xor_sync(0xffffffffu, ps0, 2);
    ps1 += __shfl_xor_sync(0xffffffffu, ps1, 1);
    ps1 += __shfl_xor_sync(0xffffffffu, ps1, 2);
    l_run[0] = l_run[0] * cr0 + ps0;
    l_run[1] = l_run[1] * cr1 + ps1;

#pragma unroll
    for (int j = 0; j < 8; j++) {
        o[j][0] *= cr0; o[j][1] *= cr0;
        o[j][2] *= cr1; o[j][3] *= cr1;
    }

#pragma unroll
    for (int kc = 0; kc < 4; kc++) {
        hilo_pack(s[2 * kc][0],     s[2 * kc][1],     ph[kc][0], pl[kc][0]);
        hilo_pack(s[2 * kc][2],     s[2 * kc][3],     ph[kc][1], pl[kc][1]);
        hilo_pack(s[2 * kc + 1][0], s[2 * kc + 1][1], ph[kc][2], pl[kc][2]);
        hilo_pack(s[2 * kc + 1][2], s[2 * kc + 1][3], ph[kc][3], pl[kc][3]);
    }
}

// Single-tile step (used when only tile B is active).
__device__ __forceinline__ void attn_step(uint32_t kb,
                                          const uint32_t (&qh)[4][4], const uint32_t (&ql)[4][4],
                                          float (&o)[8][4], float (&m_run)[2], float (&l_run)[2],
                                          bool diag, int wid, int lid)
{
    const int brow = (lid & 7) + ((lid >> 4) << 3);
    const int bkc  = (lid >> 3) & 1;
    const int vrow = lid & 15;
    const int vcol = (lid >> 4) << 3;

    float s[8][4];
#pragma unroll
    for (int j = 0; j < 8; j++)
#pragma unroll
        for (int r = 0; r < 4; r++) s[j][r] = 0.0f;

#pragma unroll
    for (int ks = 0; ks < 4; ks++) {
#pragma unroll
        for (int ng = 0; ng < 4; ng++) {
            uint32_t sw = SMEM_SWIZZLE_128B(
                (uint32_t)((ng * 16 + brow) * 128 + (ks * 2 + bkc) * 16));
            uint32_t kh4[4], kl4[4];
            ldm_x4(kh4, kb + 0 + sw);
            ldm_x4(kl4, kb + 8192 + sw);
            mma16816(s[ng * 2],     qh[ks], kh4 + 0);
            mma16816(s[ng * 2],     qh[ks], kl4 + 0);
            mma16816(s[ng * 2],     ql[ks], kh4 + 0);
            mma16816(s[ng * 2 + 1], qh[ks], kh4 + 2);
            mma16816(s[ng * 2 + 1], qh[ks], kl4 + 2);
            mma16816(s[ng * 2 + 1], ql[ks], kh4 + 2);
        }
    }

    uint32_t ph[4][4], pl[4][4];
    softmax_pack(s, o, m_run, l_run, diag, wid, lid, ph, pl);

    const uint32_t vb = kb + 16384;
#pragma unroll
    for (int kc = 0; kc < 4; kc++) {
#pragma unroll
        for (int nd = 0; nd < 4; nd++) {
            uint32_t sw = SMEM_SWIZZLE_128B(
                (uint32_t)((kc * 16 + vrow) * 128 + (nd * 16 + vcol) * 2));
            uint32_t vh4[4], vl4[4];
            ldm_x4_t(vh4, vb + 0 + sw);
            ldm_x4_t(vl4, vb + 8192 + sw);
            mma16816(o[nd * 2],     ph[kc], vh4 + 0);
            mma16816(o[nd * 2],     ph[kc], vl4 + 0);
            mma16816(o[nd * 2],     pl[kc], vh4 + 0);
            mma16816(o[nd * 2 + 1], ph[kc], vh4 + 2);
            mma16816(o[nd * 2 + 1], ph[kc], vl4 + 2);
            mma16816(o[nd * 2 + 1], pl[kc], vh4 + 2);
        }
    }
}

// Fused dual-step: both tiles against the staged KV; K/V fragments loaded once.
__device__ __forceinline__ void attn_step_dual(uint32_t kb,
    const uint32_t (&qhA)[4][4], const uint32_t (&qlA)[4][4],
    const uint32_t (&qhB)[4][4], const uint32_t (&qlB)[4][4],
    float (&oA)[8][4], float (&mA)[2], float (&lA)[2],
    float (&oB)[8][4], float (&mB)[2], float (&lB)[2],
    bool diagA, int wid, int lid)
{
    const int brow = (lid & 7) + ((lid >> 4) << 3);
    const int bkc  = (lid >> 3) & 1;
    const int vrow = lid & 15;
    const int vcol = (lid >> 4) << 3;

    float sA[8][4], sB[8][4];
#pragma unroll
    for (int j = 0; j < 8; j++)
#pragma unroll
        for (int r = 0; r < 4; r++) { sA[j][r] = 0.0f; sB[j][r] = 0.0f; }

#pragma unroll
    for (int ks = 0; ks < 4; ks++) {
#pragma unroll
        for (int ng = 0; ng < 4; ng++) {
            uint32_t sw = SMEM_SWIZZLE_128B(
                (uint32_t)((ng * 16 + brow) * 128 + (ks * 2 + bkc) * 16));
            uint32_t kh4[4], kl4[4];
            ldm_x4(kh4, kb + 0 + sw);
            ldm_x4(kl4, kb + 8192 + sw);
            mma16816(sA[ng * 2],     qhA[ks], kh4 + 0);
            mma16816(sB[ng * 2],     qhB[ks], kh4 + 0);
            mma16816(sA[ng * 2],     qhA[ks], kl4 + 0);
            mma16816(sB[ng * 2],     qhB[ks], kl4 + 0);
            mma16816(sA[ng * 2],     qlA[ks], kh4 + 0);
            mma16816(sB[ng * 2],     qlB[ks], kh4 + 0);
            mma16816(sA[ng * 2 + 1], qhA[ks], kh4 + 2);
            mma16816(sB[ng * 2 + 1], qhB[ks], kh4 + 2);
            mma16816(sA[ng * 2 + 1], qhA[ks], kl4 + 2);
            mma16816(sB[ng * 2 + 1], qhB[ks], kl4 + 2);
            mma16816(sA[ng * 2 + 1], qlA[ks], kh4 + 2);
            mma16816(sB[ng * 2 + 1], qlB[ks], kh4 + 2);
        }
    }

    uint32_t phA[4][4], plA[4][4], phB[4][4], plB[4][4];
    softmax_pack(sA, oA, mA, lA, diagA, wid, lid, phA, plA);
    softmax_pack(sB, oB, mB, lB, false, wid, lid, phB, plB);

    const uint32_t vb = kb + 16384;
#pragma unroll
    for (int kc = 0; kc < 4; kc++) {
#pragma unroll
        for (int nd = 0; nd < 4; nd++) {
            uint32_t sw = SMEM_SWIZZLE_128B(
                (uint32_t)((kc * 16 + vrow) * 128 + (nd * 16 + vcol) * 2));
            uint32_t vh4[4], vl4[4];
            ldm_x4_t(vh4, vb + 0 + sw);
            ldm_x4_t(vl4, vb + 8192 + sw);
            mma16816(oA[nd * 2],     phA[kc], vh4 + 0);
            mma16816(oB[nd * 2],     phB[kc], vh4 + 0);
            mma16816(oA[nd * 2],     phA[kc], vl4 + 0);
            mma16816(oB[nd * 2],     phB[kc], vl4 + 0);
            mma16816(oA[nd * 2],     plA[kc], vh4 + 0);
            mma16816(oB[nd * 2],     plB[kc], vh4 + 0);
            mma16816(oA[nd * 2 + 1], phA[kc], vh4 + 2);
            mma16816(oB[nd * 2 + 1], phB[kc], vh4 + 2);
            mma16816(oA[nd * 2 + 1], phA[kc], vl4 + 2);
            mma16816(oB[nd * 2 + 1], phB[kc], vl4 + 2);
            mma16816(oA[nd * 2 + 1], plA[kc], vh4 + 2);
            mma16816(oB[nd * 2 + 1], plB[kc], vh4 + 2);
        }
    }
}

__device__ __forceinline__ void attn_epilogue(const float (&o)[8][4],
                                              const float (&l_run)[2],
                                              size_t gbase, int q0, int wid, int lid,
                                              __nv_bfloat16* ohi, __nv_bfloat16* olo)
{
    const float inv0 = 1.0f / l_run[0];
    const float inv1 = 1.0f / l_run[1];
    const int rlo = q0 + wid * 16 + (lid >> 2);
#pragma unroll
    for (int j = 0; j < 8; j++) {
        const int col = ((j >> 1) << 4) + ((j & 1) << 3) + ((lid & 3) << 1);
        uint32_t hi, lo;
        size_t adr0 = gbase + (size_t)rlo * D_ + col;
        hilo_pack(o[j][0] * inv0, o[j][1] * inv0, hi, lo);
        *(uint32_t*)(ohi + adr0) = hi;
        *(uint32_t*)(olo + adr0) = lo;
        size_t adr1 = adr0 + (size_t)8 * D_;
        hilo_pack(o[j][2] * inv1, o[j][3] * inv1, hi, lo);
        *(uint32_t*)(ohi + adr1) = hi;
        *(uint32_t*)(olo + adr1) = lo;
    }
}

__global__ __launch_bounds__(128) void attn_mma(const __nv_bfloat16* __restrict__ qhi,
                                                const __nv_bfloat16* __restrict__ qlo,
                                                const __nv_bfloat16* __restrict__ khi,
                                                const __nv_bfloat16* __restrict__ klo,
                                                const __nv_bfloat16* __restrict__ vhi,
                                                const __nv_bfloat16* __restrict__ vlo,
                                                __nv_bfloat16* __restrict__ ohi,
                                                __nv_bfloat16* __restrict__ olo)
{
    extern __shared__ __align__(1024) char smem[];
    uint32_t sb = smem_u32(smem);
    const int tid = threadIdx.x;
    const int wid = tid >> 5;
    const int lid = tid & 31;
    const int p   = blockIdx.x;           // pair id: tiles p and 31-p
    const int qta = p;
    const int qtb = (L_ / 64 - 1) - p;
    const int h   = blockIdx.y;
    const int b   = blockIdx.z;
    const size_t gbase = (size_t)(b * L_) * D_ + h * DH_;

#pragma unroll
    for (int j = 0; j < 4; j++) {
        int id = tid + j * 128;
        int r  = id >> 3;
        int c  = id & 7;
        uint32_t sw = SMEM_SWIZZLE_128B((uint32_t)(r * 128 + c * 16));
        size_t offa = gbase + (size_t)(qta * 64 + r) * D_ + c * 8;
        size_t offb = gbase + (size_t)(qtb * 64 + r) * D_ + c * 8;
        cp_async16(sb + 0     + sw, qhi + offa);
        cp_async16(sb + 8192  + sw, qlo + offa);
        cp_async16(sb + 16384 + sw, qhi + offb);
        cp_async16(sb + 24576 + sw, qlo + offb);
    }
    CP_COMMIT();
    at_fill(sb, 0, gbase, 0, khi, klo, vhi, vlo, tid);
    CP_COMMIT();
    asm volatile("cp.async.wait_group 0;" ::: "memory");
    __syncthreads();

    uint32_t qhA[4][4], qlA[4][4], qhB[4][4], qlB[4][4];
    {
        const int arow = wid * 16 + (lid & 15);
        const int akc  = lid >> 4;
#pragma unroll
        for (int ks = 0; ks < 4; ks++) {
            uint32_t sw = SMEM_SWIZZLE_128B((uint32_t)(arow * 128 + (ks * 2 + akc) * 16));
            ldm_x4(qhA[ks], sb + 0 + sw);
            ldm_x4(qlA[ks], sb + 8192 + sw);
            ldm_x4(qhB[ks], sb + 16384 + sw);
            ldm_x4(qlB[ks], sb + 24576 + sw);
        }
    }

    float mA[2] = {-1e30f, -1e30f}, lA[2] = {0.0f, 0.0f};
    float mB[2] = {-1e30f, -1e30f}, lB[2] = {0.0f, 0.0f};
    float oA[8][4], oB[8][4];
#pragma unroll
    for (int j = 0; j < 8; j++)
#pragma unroll
        for (int r = 0; r < 4; r++) { oA[j][r] = 0.0f; oB[j][r] = 0.0f; }

    const int nkt = qtb + 1;
    for (int kt = 0; kt < nkt; kt++) {
        __syncthreads();
        if (kt + 1 < nkt) {
            at_fill(sb, (kt + 1) & 1, gbase, (kt + 1) * 64, khi, klo, vhi, vlo, tid);
            CP_COMMIT();
            asm volatile("cp.async.wait_group 1;" ::: "memory");
        } else {
            asm volatile("cp.async.wait_group 0;" ::: "memory");
        }
        __syncthreads();

        const uint32_t kb = sb + AT_KV0 + (kt & 1) * AT_STAGE;

        if (kt <= qta) {
            attn_step_dual(kb, qhA, qlA, qhB, qlB,
                           oA, mA, lA, oB, mB, lB,
                           kt == qta, wid, lid);
        } else {
            attn_step(kb, qhB, qlB, oB, mB, lB, kt == qtb, wid, lid);
        }
    }

    attn_epilogue(oA, lA, gbase, qta * 64, wid, lid, ohi, olo);
    attn_epilogue(oB, lB, gbase, qtb * 64, wid, lid, ohi, olo);
}

// ============================ launch ============================
extern "C" void kernel_launch(void* const* d_in, const int* in_sizes, int n_in,
                              void* d_out, int out_size)
{
    const float* x   = (const float*)d_in[0];
    const float* Wq  = (const float*)d_in[1];
    const float* Wk  = (const float*)d_in[2];
    const float* Wv  = (const float*)d_in[3];
    const float* Wo  = (const float*)d_in[4];
    const int*   pos = (const int*)  d_in[5];
    float* out = (float*)d_out;

    __nv_bfloat16 *xhi, *xlo, *whi, *wlo;
    __nv_bfloat16 *qhi, *qlo, *khi, *klo, *vhi, *vlo, *ohi, *olo;
    cudaGetSymbolAddress((void**)&xhi, g_xhi);
    cudaGetSymbolAddress((void**)&xlo, g_xlo);
    cudaGetSymbolAddress((void**)&whi, g_whi);
    cudaGetSymbolAddress((void**)&wlo, g_wlo);
    cudaGetSymbolAddress((void**)&qhi, g_qhi);
    cudaGetSymbolAddress((void**)&qlo, g_qlo);
    cudaGetSymbolAddress((void**)&khi, g_khi);
    cudaGetSymbolAddress((void**)&klo, g_klo);
    cudaGetSymbolAddress((void**)&vhi, g_vhi);
    cudaGetSymbolAddress((void**)&vlo, g_vlo);
    cudaGetSymbolAddress((void**)&ohi, g_ohi);
    cudaGetSymbolAddress((void**)&olo, g_olo);

    cudaFuncSetAttribute(gemm_qkv_fused, cudaFuncAttributeMaxDynamicSharedMemorySize, GS_SMEM);
    cudaFuncSetAttribute(gemm_out,       cudaFuncAttributeMaxDynamicSharedMemorySize, GS_SMEM);
    cudaFuncSetAttribute(attn_mma,       cudaFuncAttributeMaxDynamicSharedMemorySize, AT_SMEM);

    const int nx4 = BL_ * D_ / 4;
    const int nw4 = D_ * D_ / 4;

    split_bf16<<<nx4 / 256, 256>>>(x, xhi, xlo, nx4);
    split_w4<<<dim3(nw4 / 256, 4), 256>>>(Wq, Wk, Wv, Wo, whi, wlo);

    dim3 qkv_grid(D_ / 128, BL_ / 128, 3);
    gemm_qkv_fused<<<qkv_grid, 256, GS_SMEM>>>(xhi, xlo, whi, wlo, pos,
                                               qhi, qlo, khi, klo, vhi, vlo);

    attn_mma<<<dim3(L_ / 128, H_, B_), 128, AT_SMEM>>>(qhi, qlo, khi, klo, vhi, vlo, ohi, olo);

    dim3 ggrid(D_ / 128, BL_ / 128);
    gemm_out<<<ggrid, 256, GS_SMEM>>>(ohi, olo,
                                      whi + 3 * (size_t)D_ * D_,
                                      wlo + 3 * (size_t)D_ * D_, out);
}

// round 13
// speedup vs baseline: 1.1613x; 1.1067x over previous
#include <cuda_runtime.h>
#include <cuda_bf16.h>
#include <cuda_fp16.h>
#include <cstdint>

#define B_  2
#define L_  2048
#define D_  1024
#define H_  16
#define DH_ 64
#define BL_ (B_ * L_)

// ============================ helpers ============================
__device__ __forceinline__ uint32_t smem_u32(const void* p) {
    uint32_t a;
    asm("{ .reg .u64 t; cvta.to.shared.u64 t, %1; cvt.u32.u64 %0, t; }" : "=r"(a) : "l"(p));
    return a;
}
#define SMEM_SWIZZLE_128B(x) ((x) ^ (((x) >> 3) & 0x70))

// paired-row layout for 64B logical rows inside a SW128 tile (conflict-free ldmatrix)
__device__ __forceinline__ uint32_t pr64(int r, int c16) {
    uint32_t off = (uint32_t)(((r >> 1) << 7) + ((r & 1) << 6) + (c16 << 4));
    return SMEM_SWIZZLE_128B(off);
}

__device__ __forceinline__ void cp_async16(uint32_t dst, const void* src) {
    asm volatile("cp.async.ca.shared.global [%0], [%1], 16;" :: "r"(dst), "l"(src) : "memory");
}
#define CP_COMMIT() asm volatile("cp.async.commit_group;" ::: "memory")

__device__ __forceinline__ void ldm_x4(uint32_t* r, uint32_t addr) {
    asm volatile("ldmatrix.sync.aligned.m8n8.x4.shared.b16 {%0,%1,%2,%3}, [%4];"
        : "=r"(r[0]), "=r"(r[1]), "=r"(r[2]), "=r"(r[3]) : "r"(addr));
}
__device__ __forceinline__ void ldm_x4_t(uint32_t* r, uint32_t addr) {
    asm volatile("ldmatrix.sync.aligned.m8n8.x4.trans.shared.b16 {%0,%1,%2,%3}, [%4];"
        : "=r"(r[0]), "=r"(r[1]), "=r"(r[2]), "=r"(r[3]) : "r"(addr));
}

// D = A*B + D  (m16n8k16, bf16 in, fp32 accum)
__device__ __forceinline__ void mma16816(float* c, const uint32_t* a, const uint32_t* b) {
    asm volatile("mma.sync.aligned.m16n8k16.row.col.f32.bf16.bf16.f32 "
        "{%0,%1,%2,%3}, {%4,%5,%6,%7}, {%8,%9}, {%0,%1,%2,%3};"
        : "+f"(c[0]), "+f"(c[1]), "+f"(c[2]), "+f"(c[3])
        : "r"(a[0]), "r"(a[1]), "r"(a[2]), "r"(a[3]), "r"(b[0]), "r"(b[1]));
}

// D = A*B + D  (m16n8k16, fp16 in, fp32 accum)
__device__ __forceinline__ void mma16816h(float* c, const uint32_t* a, const uint32_t* b) {
    asm volatile("mma.sync.aligned.m16n8k16.row.col.f32.f16.f16.f32 "
        "{%0,%1,%2,%3}, {%4,%5,%6,%7}, {%8,%9}, {%0,%1,%2,%3};"
        : "+f"(c[0]), "+f"(c[1]), "+f"(c[2]), "+f"(c[3])
        : "r"(a[0]), "r"(a[1]), "r"(a[2]), "r"(a[3]), "r"(b[0]), "r"(b[1]));
}

// exp(x) for x <= 0, FMA/ALU pipes only. abs err <= ~3e-5.
__device__ __forceinline__ float exp_fast(float x) {
    float t = x * 1.44269504f;
    t = fmaxf(t, -126.0f);
    float fi = floorf(t);
    float f = t - fi;
    float r = 1.54035304e-4f;
    r = fmaf(r, f, 1.33335581e-3f);
    r = fmaf(r, f, 9.61812911e-3f);
    r = fmaf(r, f, 5.55041087e-2f);
    r = fmaf(r, f, 2.40226507e-1f);
    r = fmaf(r, f, 6.93147181e-1f);
    r = fmaf(r, f, 1.0f);
    return r * __int_as_float(((int)fi + 127) << 23);
}

__device__ __forceinline__ void hilo_pack(float a, float b, uint32_t& hi, uint32_t& lo) {
    __nv_bfloat16 ah = __float2bfloat16(a);
    __nv_bfloat16 bh = __float2bfloat16(b);
    __nv_bfloat16 al = __float2bfloat16(a - __bfloat162float(ah));
    __nv_bfloat16 bl = __float2bfloat16(b - __bfloat162float(bh));
    __nv_bfloat162 h2(ah, bh), l2(al, bl);
    hi = *(uint32_t*)&h2;
    lo = *(uint32_t*)&l2;
}

__device__ __forceinline__ void hilo_pack_h(float a, float b, uint32_t& hi, uint32_t& lo) {
    __half ah = __float2half_rn(a);
    __half bh = __float2half_rn(b);
    __half al = __float2half_rn(a - __half2float(ah));
    __half bl = __float2half_rn(b - __half2float(bh));
    __half2 h2 = __halves2half2(ah, bh), l2 = __halves2half2(al, bl);
    hi = *(uint32_t*)&h2;
    lo = *(uint32_t*)&l2;
}

__device__ __forceinline__ uint32_t f2h2(float a, float b) {
    __half2 h = __floats2half2_rn(a, b);
    return *(uint32_t*)&h;
}

// ============================ scratch globals ============================
__device__ __nv_bfloat16 g_xhi[BL_ * D_];
__device__ __nv_bfloat16 g_xlo[BL_ * D_];
__device__ __nv_bfloat16 g_whi[4 * D_ * D_];
__device__ __nv_bfloat16 g_wlo[4 * D_ * D_];
__device__ __nv_bfloat16 g_qhi[BL_ * D_];
__device__ __nv_bfloat16 g_qlo[BL_ * D_];
__device__ __nv_bfloat16 g_khi[BL_ * D_];
__device__ __nv_bfloat16 g_klo[BL_ * D_];
__device__ __half        g_vhi[BL_ * D_];
__device__ __half        g_vlo[BL_ * D_];
__device__ __nv_bfloat16 g_ohi[BL_ * D_];
__device__ __nv_bfloat16 g_olo[BL_ * D_];

__device__ const float g_invfreq[32] = {
    1.0f, 0.7498942093324559f, 0.5623413251903491f, 0.4216965034285823f,
    0.31622776601683794f, 0.2371373705661655f, 0.1778279410038923f, 0.13335214321633237f,
    0.1f, 0.07498942093324559f, 0.05623413251903491f, 0.04216965034285823f,
    0.031622776601683794f, 0.02371373705661655f, 0.01778279410038923f, 0.013335214321633237f,
    0.01f, 0.007498942093324559f, 0.005623413251903491f, 0.004216965034285823f,
    0.0031622776601683794f, 0.002371373705661655f, 0.001778279410038923f, 0.0013335214321633237f,
    0.001f, 0.0007498942093324559f, 0.0005623413251903491f, 0.0004216965034285823f,
    0.00031622776601683794f, 0.0002371373705661655f, 0.0001778279410038923f, 0.00013335214321633237f
};

// ============================ fp32 -> bf16 hi/lo splits ============================
__global__ __launch_bounds__(256) void split_bf16(const float* __restrict__ src,
                                                  __nv_bfloat16* __restrict__ hi,
                                                  __nv_bfloat16* __restrict__ lo,
                                                  int n4)
{
    int i = blockIdx.x * 256 + threadIdx.x;
    if (i >= n4) return;
    float4 v = ((const float4*)src)[i];
    float f[4] = {v.x, v.y, v.z, v.w};
    __nv_bfloat16 h[4], l[4];
#pragma unroll
    for (int j = 0; j < 4; j++) {
        h[j] = __float2bfloat16(f[j]);
        l[j] = __float2bfloat16(f[j] - __bfloat162float(h[j]));
    }
    ((__nv_bfloat162*)hi)[2 * i + 0] = __nv_bfloat162(h[0], h[1]);
    ((__nv_bfloat162*)hi)[2 * i + 1] = __nv_bfloat162(h[2], h[3]);
    ((__nv_bfloat162*)lo)[2 * i + 0] = __nv_bfloat162(l[0], l[1]);
    ((__nv_bfloat162*)lo)[2 * i + 1] = __nv_bfloat162(l[2], l[3]);
}

__global__ __launch_bounds__(256) void split_w4(const float* __restrict__ Wq,
                                                const float* __restrict__ Wk,
                                                const float* __restrict__ Wv,
                                                const float* __restrict__ Wo,
                                                __nv_bfloat16* __restrict__ whi,
                                                __nv_bfloat16* __restrict__ wlo)
{
    const int z = blockIdx.y;
    const float* src = (z == 0) ? Wq : (z == 1) ? Wk : (z == 2) ? Wv : Wo;
    __nv_bfloat16* hi = whi + (size_t)z * D_ * D_;
    __nv_bfloat16* lo = wlo + (size_t)z * D_ * D_;
    int i = blockIdx.x * 256 + threadIdx.x;
    float4 v = ((const float4*)src)[i];
    float f[4] = {v.x, v.y, v.z, v.w};
    __nv_bfloat16 h[4], l[4];
#pragma unroll
    for (int j = 0; j < 4; j++) {
        h[j] = __float2bfloat16(f[j]);
        l[j] = __float2bfloat16(f[j] - __bfloat162float(h[j]));
    }
    ((__nv_bfloat162*)hi)[2 * i + 0] = __nv_bfloat162(h[0], h[1]);
    ((__nv_bfloat162*)hi)[2 * i + 1] = __nv_bfloat162(h[2], h[3]);
    ((__nv_bfloat162*)lo)[2 * i + 0] = __nv_bfloat162(l[0], l[1]);
    ((__nv_bfloat162*)lo)[2 * i + 1] = __nv_bfloat162(l[2], l[3]);
}

// ============================ HMMA bf16x3 GEMM (R8 exact) ============
#define GS_STAGE 32768
#define GS_SMEM  (2 * GS_STAGE)
#define GS_NCHUNK 32

__device__ __forceinline__ void gt_fill32(uint32_t base,
                                          const __nv_bfloat16* Ahi, const __nv_bfloat16* Alo,
                                          const __nv_bfloat16* Bhi, const __nv_bfloat16* Blo,
                                          int m0, int n0, int k0, int tid)
{
#pragma unroll
    for (int j = 0; j < 2; j++) {
        int id = tid + j * 256;
        int r  = id >> 2;
        int c  = id & 3;
        uint32_t sw = pr64(r, c);
        size_t aoff = (size_t)(m0 + r) * D_ + k0 + c * 8;
        size_t boff = (size_t)(n0 + r) * D_ + k0 + c * 8;
        cp_async16(base + 0     + sw, Ahi + aoff);
        cp_async16(base + 8192  + sw, Alo + aoff);
        cp_async16(base + 16384 + sw, Bhi + boff);
        cp_async16(base + 24576 + sw, Blo + boff);
    }
}

__device__ __forceinline__ void gemm32_core(uint32_t sb,
                                            const __nv_bfloat16* __restrict__ Ahi,
                                            const __nv_bfloat16* __restrict__ Alo,
                                            const __nv_bfloat16* __restrict__ Bhi,
                                            const __nv_bfloat16* __restrict__ Blo,
                                            int m0, int n0, float acc[4][4][4])
{
    const int tid = threadIdx.x;
    const int wid = tid >> 5;
    const int lid = tid & 31;
    const int wm  = wid >> 2;
    const int wn  = wid & 3;

#pragma unroll
    for (int mt = 0; mt < 4; mt++)
#pragma unroll
        for (int nt = 0; nt < 4; nt++)
#pragma unroll
            for (int r = 0; r < 4; r++) acc[mt][nt][r] = 0.0f;

    gt_fill32(sb, Ahi, Alo, Bhi, Blo, m0, n0, 0, tid);
    CP_COMMIT();
    gt_fill32(sb + GS_STAGE, Ahi, Alo, Bhi, Blo, m0, n0, 32, tid);
    CP_COMMIT();

    const int a_row = (lid & 15);
    const int a_kc  = (lid >> 4);
    const int b_row = (lid & 7) + ((lid >> 4) << 3);
    const int b_kc  = (lid >> 3) & 1;

    for (int i = 0; i < GS_NCHUNK; i++) {
        if (i == GS_NCHUNK - 1) asm volatile("cp.async.wait_group 0;" ::: "memory");
        else                    asm volatile("cp.async.wait_group 1;" ::: "memory");
        __syncthreads();

        const uint32_t tb = sb + (i & 1) * GS_STAGE;

#pragma unroll
        for (int ks = 0; ks < 2; ks++) {
            uint32_t bhi[4][2], blo[4][2];
#pragma unroll
            for (int ng = 0; ng < 2; ng++) {
                const int nrow = wn * 32 + ng * 16 + b_row;
                const uint32_t sw = pr64(nrow, ks * 2 + b_kc);
                uint32_t r[4];
                ldm_x4(r, tb + 16384 + sw);
                bhi[2 * ng][0] = r[0]; bhi[2 * ng][1] = r[1];
                bhi[2 * ng + 1][0] = r[2]; bhi[2 * ng + 1][1] = r[3];
                ldm_x4(r, tb + 24576 + sw);
                blo[2 * ng][0] = r[0]; blo[2 * ng][1] = r[1];
                blo[2 * ng + 1][0] = r[2]; blo[2 * ng + 1][1] = r[3];
            }
#pragma unroll
            for (int mt = 0; mt < 4; mt++) {
                const int mrow = wm * 64 + mt * 16 + a_row;
                const uint32_t sw = pr64(mrow, ks * 2 + a_kc);
                uint32_t ahi[4], alo[4];
                ldm_x4(ahi, tb + 0 + sw);
                ldm_x4(alo, tb + 8192 + sw);
#pragma unroll
                for (int nt = 0; nt < 4; nt++) {
                    mma16816(acc[mt][nt], ahi, bhi[nt]);
                    mma16816(acc[mt][nt], ahi, blo[nt]);
                    mma16816(acc[mt][nt], alo, bhi[nt]);
                }
            }
        }
        __syncthreads();

        if (i + 2 < GS_NCHUNK) {
            gt_fill32(sb + (i & 1) * GS_STAGE, Ahi, Alo, Bhi, Blo, m0, n0, (i + 2) * 32, tid);
            CP_COMMIT();
        }
    }
}

__global__ __launch_bounds__(256, 2) void gemm_qkv_fused(
    const __nv_bfloat16* __restrict__ xhi, const __nv_bfloat16* __restrict__ xlo,
    const __nv_bfloat16* __restrict__ whi, const __nv_bfloat16* __restrict__ wlo,
    const int* __restrict__ pos,
    __nv_bfloat16* __restrict__ qhi, __nv_bfloat16* __restrict__ qlo,
    __nv_bfloat16* __restrict__ khi, __nv_bfloat16* __restrict__ klo,
    __half* __restrict__ vhi, __half* __restrict__ vlo)
{
    extern __shared__ __align__(1024) char smem[];
    uint32_t sb = smem_u32(smem);
    const int z  = blockIdx.z;
    const int m0 = blockIdx.y * 128;
    const int n0 = blockIdx.x * 128;

    float acc[4][4][4];
    gemm32_core(sb, xhi, xlo,
                whi + (size_t)z * D_ * D_, wlo + (size_t)z * D_ * D_,
                m0, n0, acc);

    const int lid = threadIdx.x & 31;
    const int wid = threadIdx.x >> 5;
    const int wm  = wid >> 2;
    const int wn  = wid & 3;

    if (z == 2) {
        // V: fp16 hi/lo split (for fp16 PV MMA in attention)
#pragma unroll
        for (int mt = 0; mt < 4; mt++) {
            const int row = m0 + wm * 64 + mt * 16 + (lid >> 2);
#pragma unroll
            for (int nt = 0; nt < 4; nt++) {
                const int col = n0 + wn * 32 + nt * 8 + (lid & 3) * 2;
                uint32_t hi, lo;
                size_t adr = (size_t)row * D_ + col;
                hilo_pack_h(acc[mt][nt][0], acc[mt][nt][1], hi, lo);
                *(uint32_t*)(vhi + adr) = hi;
                *(uint32_t*)(vlo + adr) = lo;
                adr += (size_t)8 * D_;
                hilo_pack_h(acc[mt][nt][2], acc[mt][nt][3], hi, lo);
                *(uint32_t*)(vhi + adr) = hi;
                *(uint32_t*)(vlo + adr) = lo;
            }
        }
        return;
    }

    __nv_bfloat16* oh = (z == 0) ? qhi : khi;
    __nv_bfloat16* ol = (z == 0) ? qlo : klo;
    const float scale = (z == 0) ? 0.125f : 1.0f;

#pragma unroll
    for (int mt = 0; mt < 4; mt++) {
        const int row = m0 + wm * 64 + mt * 16 + (lid >> 2);
#pragma unroll
        for (int nt = 0; nt < 4; nt++) {
            const int col = n0 + wn * 32 + nt * 8 + (lid & 3) * 2;
            float c0 = acc[mt][nt][0], c1 = acc[mt][nt][1];
            float c2 = acc[mt][nt][2], c3 = acc[mt][nt][3];
            {
                const float invf = g_invfreq[(col & 63) >> 1];
                float s0, q0, s1, q1;
                sincosf((float)pos[row & (L_ - 1)] * invf, &s0, &q0);
                sincosf((float)pos[(row + 8) & (L_ - 1)] * invf, &s1, &q1);
                float t0 = (c0 * q0 - c1 * s0) * scale;
                float t1 = (c0 * s0 + c1 * q0) * scale;
                float t2 = (c2 * q1 - c3 * s1) * scale;
                float t3 = (c2 * s1 + c3 * q1) * scale;
                c0 = t0; c1 = t1; c2 = t2; c3 = t3;
            }
            uint32_t hi, lo;
            size_t adr = (size_t)row * D_ + col;
            hilo_pack(c0, c1, hi, lo);
            *(uint32_t*)(oh + adr) = hi;
            *(uint32_t*)(ol + adr) = lo;
            adr += (size_t)8 * D_;
            hilo_pack(c2, c3, hi, lo);
            *(uint32_t*)(oh + adr) = hi;
            *(uint32_t*)(ol + adr) = lo;
        }
    }
}

__global__ __launch_bounds__(256, 2) void gemm_out(
    const __nv_bfloat16* __restrict__ ahi, const __nv_bfloat16* __restrict__ alo,
    const __nv_bfloat16* __restrict__ whi, const __nv_bfloat16* __restrict__ wlo,
    float* __restrict__ C)
{
    extern __shared__ __align__(1024) char smem[];
    uint32_t sb = smem_u32(smem);
    const int m0 = blockIdx.y * 128;
    const int n0 = blockIdx.x * 128;

    float acc[4][4][4];
    gemm32_core(sb, ahi, alo, whi, wlo, m0, n0, acc);

    const int lid = threadIdx.x & 31;
    const int wid = threadIdx.x >> 5;
    const int wm  = wid >> 2;
    const int wn  = wid & 3;
#pragma unroll
    for (int mt = 0; mt < 4; mt++) {
        const int row = m0 + wm * 64 + mt * 16 + (lid >> 2);
#pragma unroll
        for (int nt = 0; nt < 4; nt++) {
            const int col = n0 + wn * 32 + nt * 8 + (lid & 3) * 2;
            *(float2*)&C[(size_t)row * D_ + col]       = make_float2(acc[mt][nt][0], acc[mt][nt][1]);
            *(float2*)&C[(size_t)(row + 8) * D_ + col] = make_float2(acc[mt][nt][2], acc[mt][nt][3]);
        }
    }
}

// ============================ paired-tile attention (R8 structure, fp16 PV) ==========
#define AT_KV0   32768
#define AT_STAGE 32768
#define AT_SMEM  (AT_KV0 + 2 * AT_STAGE)

__device__ __forceinline__ void at_fill(uint32_t sb, int stage, size_t gbase, int k0,
                                        const __nv_bfloat16* khi, const __nv_bfloat16* klo,
                                        const __half* vhi, const __half* vlo,
                                        int tid)
{
    uint32_t kb = sb + AT_KV0 + stage * AT_STAGE;
#pragma unroll
    for (int j = 0; j < 4; j++) {
        int id = tid + j * 128;
        int r  = id >> 3;
        int c  = id & 7;
        uint32_t sw = SMEM_SWIZZLE_128B((uint32_t)(r * 128 + c * 16));
        size_t off = gbase + (size_t)(k0 + r) * D_ + c * 8;
        cp_async16(kb + 0     + sw, khi + off);
        cp_async16(kb + 8192  + sw, klo + off);
        cp_async16(kb + 16384 + sw, vhi + off);
        cp_async16(kb + 24576 + sw, vlo + off);
    }
}

__device__ __forceinline__ void attn_step(uint32_t kb,
                                          const uint32_t (&qh)[4][4], const uint32_t (&ql)[4][4],
                                          float (&o)[8][4], float (&m_run)[2], float (&l_run)[2],
                                          bool diag, int wid, int lid)
{
    const int brow = (lid & 7) + ((lid >> 4) << 3);
    const int bkc  = (lid >> 3) & 1;
    const int vrow = lid & 15;
    const int vcol = (lid >> 4) << 3;

    float s[8][4];
#pragma unroll
    for (int j = 0; j < 8; j++)
#pragma unroll
        for (int r = 0; r < 4; r++) s[j][r] = 0.0f;

#pragma unroll
    for (int ks = 0; ks < 4; ks++) {
#pragma unroll
        for (int ng = 0; ng < 4; ng++) {
            uint32_t sw = SMEM_SWIZZLE_128B(
                (uint32_t)((ng * 16 + brow) * 128 + (ks * 2 + bkc) * 16));
            uint32_t kh4[4], kl4[4];
            ldm_x4(kh4, kb + 0 + sw);
            ldm_x4(kl4, kb + 8192 + sw);
            mma16816(s[ng * 2],     qh[ks], kh4 + 0);
            mma16816(s[ng * 2],     qh[ks], kl4 + 0);
            mma16816(s[ng * 2],     ql[ks], kh4 + 0);
            mma16816(s[ng * 2 + 1], qh[ks], kh4 + 2);
            mma16816(s[ng * 2 + 1], qh[ks], kl4 + 2);
            mma16816(s[ng * 2 + 1], ql[ks], kh4 + 2);
        }
    }

    if (diag) {
        const int rlo = wid * 16 + (lid >> 2);
#pragma unroll
        for (int j = 0; j < 8; j++) {
            const int cb = ((j >> 1) << 4) + ((j & 1) << 3) + ((lid & 3) << 1);
            if (cb     > rlo)     s[j][0] = -1e30f;
            if (cb + 1 > rlo)     s[j][1] = -1e30f;
            if (cb     > rlo + 8) s[j][2] = -1e30f;
            if (cb + 1 > rlo + 8) s[j][3] = -1e30f;
        }
    }

    float mx0 = -1e30f, mx1 = -1e30f;
#pragma unroll
    for (int j = 0; j < 8; j++) {
        mx0 = fmaxf(mx0, fmaxf(s[j][0], s[j][1]));
        mx1 = fmaxf(mx1, fmaxf(s[j][2], s[j][3]));
    }
    mx0 = fmaxf(mx0, __shfl_xor_sync(0xffffffffu, mx0, 1));
    mx0 = fmaxf(mx0, __shfl_xor_sync(0xffffffffu, mx0, 2));
    mx1 = fmaxf(mx1, __shfl_xor_sync(0xffffffffu, mx1, 1));
    mx1 = fmaxf(mx1, __shfl_xor_sync(0xffffffffu, mx1, 2));
    const float mn0 = fmaxf(m_run[0], mx0);
    const float mn1 = fmaxf(m_run[1], mx1);
    const float cr0 = exp_fast(m_run[0] - mn0);
    const float cr1 = exp_fast(m_run[1] - mn1);
    m_run[0] = mn0; m_run[1] = mn1;

    float ps0 = 0.0f, ps1 = 0.0f;
#pragma unroll
    for (int j = 0; j < 8; j++) {
        s[j][0] = exp_fast(s[j][0] - mn0); ps0 += s[j][0];
        s[j][1] = exp_fast(s[j][1] - mn0); ps0 += s[j][1];
        s[j][2] = exp_fast(s[j][2] - mn1); ps1 += s[j][2];
        s[j][3] = exp_fast(s[j][3] - mn1); ps1 += s[j][3];
    }
    ps0 += __shfl_xor_sync(0xffffffffu, ps0, 1);
    ps0 += __shfl_xor_sync(0xffffffffu, ps0, 2);
    ps1 += __shfl_xor_sync(0xffffffffu, ps1, 1);
    ps1 += __shfl_xor_sync(0xffffffffu, ps1, 2);
    l_run[0] = l_run[0] * cr0 + ps0;
    l_run[1] = l_run[1] * cr1 + ps1;

#pragma unroll
    for (int j = 0; j < 8; j++) {
        o[j][0] *= cr0; o[j][1] *= cr0;
        o[j][2] *= cr1; o[j][3] *= cr1;
    }

    // P -> single fp16 A-fragments
    uint32_t ph[4][4];
#pragma unroll
    for (int kc = 0; kc < 4; kc++) {
        ph[kc][0] = f2h2(s[2 * kc][0],     s[2 * kc][1]);
        ph[kc][1] = f2h2(s[2 * kc][2],     s[2 * kc][3]);
        ph[kc][2] = f2h2(s[2 * kc + 1][0], s[2 * kc + 1][1]);
        ph[kc][3] = f2h2(s[2 * kc + 1][2], s[2 * kc + 1][3]);
    }

    // O += P (Vhi + Vlo), fp16 MMA, 2 products
    const uint32_t vb = kb + 16384;
#pragma unroll
    for (int kc = 0; kc < 4; kc++) {
#pragma unroll
        for (int nd = 0; nd < 4; nd++) {
            uint32_t sw = SMEM_SWIZZLE_128B(
                (uint32_t)((kc * 16 + vrow) * 128 + (nd * 16 + vcol) * 2));
            uint32_t vh4[4], vl4[4];
            ldm_x4_t(vh4, vb + 0 + sw);
            ldm_x4_t(vl4, vb + 8192 + sw);
            mma16816h(o[nd * 2],     ph[kc], vh4 + 0);
            mma16816h(o[nd * 2],     ph[kc], vl4 + 0);
            mma16816h(o[nd * 2 + 1], ph[kc], vh4 + 2);
            mma16816h(o[nd * 2 + 1], ph[kc], vl4 + 2);
        }
    }
}

__device__ __forceinline__ void attn_epilogue(const float (&o)[8][4],
                                              const float (&l_run)[2],
                                              size_t gbase, int q0, int wid, int lid,
                                              __nv_bfloat16* ohi, __nv_bfloat16* olo)
{
    const float inv0 = 1.0f / l_run[0];
    const float inv1 = 1.0f / l_run[1];
    const int rlo = q0 + wid * 16 + (lid >> 2);
#pragma unroll
    for (int j = 0; j < 8; j++) {
        const int col = ((j >> 1) << 4) + ((j & 1) << 3) + ((lid & 3) << 1);
        uint32_t hi, lo;
        size_t adr0 = gbase + (size_t)rlo * D_ + col;
        hilo_pack(o[j][0] * inv0, o[j][1] * inv0, hi, lo);
        *(uint32_t*)(ohi + adr0) = hi;
        *(uint32_t*)(olo + adr0) = lo;
        size_t adr1 = adr0 + (size_t)8 * D_;
        hilo_pack(o[j][2] * inv1, o[j][3] * inv1, hi, lo);
        *(uint32_t*)(ohi + adr1) = hi;
        *(uint32_t*)(olo + adr1) = lo;
    }
}

__global__ __launch_bounds__(128) void attn_mma(const __nv_bfloat16* __restrict__ qhi,
                                                const __nv_bfloat16* __restrict__ qlo,
                                                const __nv_bfloat16* __restrict__ khi,
                                                const __nv_bfloat16* __restrict__ klo,
                                                const __half* __restrict__ vhi,
                                                const __half* __restrict__ vlo,
                                                __nv_bfloat16* __restrict__ ohi,
                                                __nv_bfloat16* __restrict__ olo)
{
    extern __shared__ __align__(1024) char smem[];
    uint32_t sb = smem_u32(smem);
    const int tid = threadIdx.x;
    const int wid = tid >> 5;
    const int lid = tid & 31;
    const int p   = blockIdx.x;           // pair id: tiles p and 31-p
    const int qta = p;
    const int qtb = (L_ / 64 - 1) - p;
    const int h   = blockIdx.y;
    const int b   = blockIdx.z;
    const size_t gbase = (size_t)(b * L_) * D_ + h * DH_;

#pragma unroll
    for (int j = 0; j < 4; j++) {
        int id = tid + j * 128;
        int r  = id >> 3;
        int c  = id & 7;
        uint32_t sw = SMEM_SWIZZLE_128B((uint32_t)(r * 128 + c * 16));
        size_t offa = gbase + (size_t)(qta * 64 + r) * D_ + c * 8;
        size_t offb = gbase + (size_t)(qtb * 64 + r) * D_ + c * 8;
        cp_async16(sb + 0     + sw, qhi + offa);
        cp_async16(sb + 8192  + sw, qlo + offa);
        cp_async16(sb + 16384 + sw, qhi + offb);
        cp_async16(sb + 24576 + sw, qlo + offb);
    }
    CP_COMMIT();
    at_fill(sb, 0, gbase, 0, khi, klo, vhi, vlo, tid);
    CP_COMMIT();
    asm volatile("cp.async.wait_group 0;" ::: "memory");
    __syncthreads();

    uint32_t qhA[4][4], qlA[4][4], qhB[4][4], qlB[4][4];
    {
        const int arow = wid * 16 + (lid & 15);
        const int akc  = lid >> 4;
#pragma unroll
        for (int ks = 0; ks < 4; ks++) {
            uint32_t sw = SMEM_SWIZZLE_128B((uint32_t)(arow * 128 + (ks * 2 + akc) * 16));
            ldm_x4(qhA[ks], sb + 0 + sw);
            ldm_x4(qlA[ks], sb + 8192 + sw);
            ldm_x4(qhB[ks], sb + 16384 + sw);
            ldm_x4(qlB[ks], sb + 24576 + sw);
        }
    }

    float mA[2] = {-1e30f, -1e30f}, lA[2] = {0.0f, 0.0f};
    float mB[2] = {-1e30f, -1e30f}, lB[2] = {0.0f, 0.0f};
    float oA[8][4], oB[8][4];
#pragma unroll
    for (int j = 0; j < 8; j++)
#pragma unroll
        for (int r = 0; r < 4; r++) { oA[j][r] = 0.0f; oB[j][r] = 0.0f; }

    const int nkt = qtb + 1;
    for (int kt = 0; kt < nkt; kt++) {
        __syncthreads();
        if (kt + 1 < nkt) {
            at_fill(sb, (kt + 1) & 1, gbase, (kt + 1) * 64, khi, klo, vhi, vlo, tid);
            CP_COMMIT();
            asm volatile("cp.async.wait_group 1;" ::: "memory");
        } else {
            asm volatile("cp.async.wait_group 0;" ::: "memory");
        }
        __syncthreads();

        const uint32_t kb = sb + AT_KV0 + (kt & 1) * AT_STAGE;

        if (kt <= qta)
            attn_step(kb, qhA, qlA, oA, mA, lA, kt == qta, wid, lid);
        attn_step(kb, qhB, qlB, oB, mB, lB, kt == qtb, wid, lid);
    }

    attn_epilogue(oA, lA, gbase, qta * 64, wid, lid, ohi, olo);
    attn_epilogue(oB, lB, gbase, qtb * 64, wid, lid, ohi, olo);
}

// ============================ launch ============================
extern "C" void kernel_launch(void* const* d_in, const int* in_sizes, int n_in,
                              void* d_out, int out_size)
{
    const float* x   = (const float*)d_in[0];
    const float* Wq  = (const float*)d_in[1];
    const float* Wk  = (const float*)d_in[2];
    const float* Wv  = (const float*)d_in[3];
    const float* Wo  = (const float*)d_in[4];
    const int*   pos = (const int*)  d_in[5];
    float* out = (float*)d_out;

    __nv_bfloat16 *xhi, *xlo, *whi, *wlo;
    __nv_bfloat16 *qhi, *qlo, *khi, *klo, *ohi, *olo;
    __half *vhi, *vlo;
    cudaGetSymbolAddress((void**)&xhi, g_xhi);
    cudaGetSymbolAddress((void**)&xlo, g_xlo);
    cudaGetSymbolAddress((void**)&whi, g_whi);
    cudaGetSymbolAddress((void**)&wlo, g_wlo);
    cudaGetSymbolAddress((void**)&qhi, g_qhi);
    cudaGetSymbolAddress((void**)&qlo, g_qlo);
    cudaGetSymbolAddress((void**)&khi, g_khi);
    cudaGetSymbolAddress((void**)&klo, g_klo);
    cudaGetSymbolAddress((void**)&vhi, g_vhi);
    cudaGetSymbolAddress((void**)&vlo, g_vlo);
    cudaGetSymbolAddress((void**)&ohi, g_ohi);
    cudaGetSymbolAddress((void**)&olo, g_olo);

    cudaFuncSetAttribute(gemm_qkv_fused, cudaFuncAttributeMaxDynamicSharedMemorySize, GS_SMEM);
    cudaFuncSetAttribute(gemm_out,       cudaFuncAttributeMaxDynamicSharedMemorySize, GS_SMEM);
    cudaFuncSetAttribute(attn_mma,       cudaFuncAttributeMaxDynamicSharedMemorySize, AT_SMEM);

    const int nx4 = BL_ * D_ / 4;
    const int nw4 = D_ * D_ / 4;

    split_bf16<<<nx4 / 256, 256>>>(x, xhi, xlo, nx4);
    split_w4<<<dim3(nw4 / 256, 4), 256>>>(Wq, Wk, Wv, Wo, whi, wlo);

    dim3 qkv_grid(D_ / 128, BL_ / 128, 3);
    gemm_qkv_fused<<<qkv_grid, 256, GS_SMEM>>>(xhi, xlo, whi, wlo, pos,
                                               qhi, qlo, khi, klo, vhi, vlo);

    attn_mma<<<dim3(L_ / 128, H_, B_), 128, AT_SMEM>>>(qhi, qlo, khi, klo, vhi, vlo, ohi, olo);

    dim3 ggrid(D_ / 128, BL_ / 128);
    gemm_out<<<ggrid, 256, GS_SMEM>>>(ohi, olo,
                                      whi + 3 * (size_t)D_ * D_,
                                      wlo + 3 * (size_t)D_ * D_, out);
}

// round 14
// speedup vs baseline: 1.4037x; 1.2087x over previous
#include <cuda_runtime.h>
#include <cuda_bf16.h>
#include <cuda_fp16.h>
#include <cstdint>

#define B_  2
#define L_  2048
#define D_  1024
#define H_  16
#define DH_ 64
#define BL_ (B_ * L_)

// ============================ helpers ============================
__device__ __forceinline__ uint32_t smem_u32(const void* p) {
    uint32_t a;
    asm("{ .reg .u64 t; cvta.to.shared.u64 t, %1; cvt.u32.u64 %0, t; }" : "=r"(a) : "l"(p));
    return a;
}
#define SMEM_SWIZZLE_128B(x) ((x) ^ (((x) >> 3) & 0x70))

// paired-row layout for 64B logical rows inside a SW128 tile (conflict-free ldmatrix)
__device__ __forceinline__ uint32_t pr64(int r, int c16) {
    uint32_t off = (uint32_t)(((r >> 1) << 7) + ((r & 1) << 6) + (c16 << 4));
    return SMEM_SWIZZLE_128B(off);
}

__device__ __forceinline__ void cp_async16(uint32_t dst, const void* src) {
    asm volatile("cp.async.ca.shared.global [%0], [%1], 16;" :: "r"(dst), "l"(src) : "memory");
}
#define CP_COMMIT() asm volatile("cp.async.commit_group;" ::: "memory")

__device__ __forceinline__ void ldm_x4(uint32_t* r, uint32_t addr) {
    asm volatile("ldmatrix.sync.aligned.m8n8.x4.shared.b16 {%0,%1,%2,%3}, [%4];"
        : "=r"(r[0]), "=r"(r[1]), "=r"(r[2]), "=r"(r[3]) : "r"(addr));
}
__device__ __forceinline__ void ldm_x4_t(uint32_t* r, uint32_t addr) {
    asm volatile("ldmatrix.sync.aligned.m8n8.x4.trans.shared.b16 {%0,%1,%2,%3}, [%4];"
        : "=r"(r[0]), "=r"(r[1]), "=r"(r[2]), "=r"(r[3]) : "r"(addr));
}

// D = A*B + D  (m16n8k16, bf16 in, fp32 accum)
__device__ __forceinline__ void mma16816(float* c, const uint32_t* a, const uint32_t* b) {
    asm volatile("mma.sync.aligned.m16n8k16.row.col.f32.bf16.bf16.f32 "
        "{%0,%1,%2,%3}, {%4,%5,%6,%7}, {%8,%9}, {%0,%1,%2,%3};"
        : "+f"(c[0]), "+f"(c[1]), "+f"(c[2]), "+f"(c[3])
        : "r"(a[0]), "r"(a[1]), "r"(a[2]), "r"(a[3]), "r"(b[0]), "r"(b[1]));
}

// D = A*B + D  (m16n8k16, fp16 in, fp32 accum)
__device__ __forceinline__ void mma16816h(float* c, const uint32_t* a, const uint32_t* b) {
    asm volatile("mma.sync.aligned.m16n8k16.row.col.f32.f16.f16.f32 "
        "{%0,%1,%2,%3}, {%4,%5,%6,%7}, {%8,%9}, {%0,%1,%2,%3};"
        : "+f"(c[0]), "+f"(c[1]), "+f"(c[2]), "+f"(c[3])
        : "r"(a[0]), "r"(a[1]), "r"(a[2]), "r"(a[3]), "r"(b[0]), "r"(b[1]));
}

// exp(x) for x <= 0, FMA/ALU pipes only. abs err <= ~3e-5.
__device__ __forceinline__ float exp_fast(float x) {
    float t = x * 1.44269504f;
    t = fmaxf(t, -126.0f);
    float fi = floorf(t);
    float f = t - fi;
    float r = 1.54035304e-4f;
    r = fmaf(r, f, 1.33335581e-3f);
    r = fmaf(r, f, 9.61812911e-3f);
    r = fmaf(r, f, 5.55041087e-2f);
    r = fmaf(r, f, 2.40226507e-1f);
    r = fmaf(r, f, 6.93147181e-1f);
    r = fmaf(r, f, 1.0f);
    return r * __int_as_float(((int)fi + 127) << 23);
}

__device__ __forceinline__ void hilo_pack(float a, float b, uint32_t& hi, uint32_t& lo) {
    __nv_bfloat16 ah = __float2bfloat16(a);
    __nv_bfloat16 bh = __float2bfloat16(b);
    __nv_bfloat16 al = __float2bfloat16(a - __bfloat162float(ah));
    __nv_bfloat16 bl = __float2bfloat16(b - __bfloat162float(bh));
    __nv_bfloat162 h2(ah, bh), l2(al, bl);
    hi = *(uint32_t*)&h2;
    lo = *(uint32_t*)&l2;
}

__device__ __forceinline__ void hilo_pack_h(float a, float b, uint32_t& hi, uint32_t& lo) {
    __half ah = __float2half_rn(a);
    __half bh = __float2half_rn(b);
    __half al = __float2half_rn(a - __half2float(ah));
    __half bl = __float2half_rn(b - __half2float(bh));
    __half2 h2 = __halves2half2(ah, bh), l2 = __halves2half2(al, bl);
    hi = *(uint32_t*)&h2;
    lo = *(uint32_t*)&l2;
}

__device__ __forceinline__ uint32_t f2h2(float a, float b) {
    __half2 h = __floats2half2_rn(a, b);
    return *(uint32_t*)&h;
}

// ============================ scratch globals ============================
__device__ __half        g_xhi[BL_ * D_];
__device__ __half        g_xlo[BL_ * D_];
__device__ __half        g_wh[4 * D_ * D_];     // weights: single fp16
__device__ __nv_bfloat16 g_qhi[BL_ * D_];
__device__ __nv_bfloat16 g_qlo[BL_ * D_];
__device__ __nv_bfloat16 g_khi[BL_ * D_];
__device__ __nv_bfloat16 g_klo[BL_ * D_];
__device__ __half        g_vhi[BL_ * D_];
__device__ __half        g_vlo[BL_ * D_];
__device__ __half        g_ohi[BL_ * D_];
__device__ __half        g_olo[BL_ * D_];

__device__ const float g_invfreq[32] = {
    1.0f, 0.7498942093324559f, 0.5623413251903491f, 0.4216965034285823f,
    0.31622776601683794f, 0.2371373705661655f, 0.1778279410038923f, 0.13335214321633237f,
    0.1f, 0.07498942093324559f, 0.05623413251903491f, 0.04216965034285823f,
    0.031622776601683794f, 0.02371373705661655f, 0.01778279410038923f, 0.013335214321633237f,
    0.01f, 0.007498942093324559f, 0.005623413251903491f, 0.004216965034285823f,
    0.0031622776601683794f, 0.002371373705661655f, 0.001778279410038923f, 0.0013335214321633237f,
    0.001f, 0.0007498942093324559f, 0.0005623413251903491f, 0.0004216965034285823f,
    0.00031622776601683794f, 0.0002371373705661655f, 0.0001778279410038923f, 0.00013335214321633237f
};

// ============================ splits ============================
// x: fp32 -> fp16 hi/lo
__global__ __launch_bounds__(256) void split_h(const float* __restrict__ src,
                                               __half* __restrict__ hi,
                                               __half* __restrict__ lo,
                                               int n4)
{
    int i = blockIdx.x * 256 + threadIdx.x;
    if (i >= n4) return;
    float4 v = ((const float4*)src)[i];
    uint32_t h0, l0, h1, l1;
    hilo_pack_h(v.x, v.y, h0, l0);
    hilo_pack_h(v.z, v.w, h1, l1);
    ((uint32_t*)hi)[2 * i + 0] = h0;
    ((uint32_t*)hi)[2 * i + 1] = h1;
    ((uint32_t*)lo)[2 * i + 0] = l0;
    ((uint32_t*)lo)[2 * i + 1] = l1;
}

// weights: fp32 -> single fp16 (random-rounding error ~2.8e-4 relative on GEMM out)
__global__ __launch_bounds__(256) void split_w4(const float* __restrict__ Wq,
                                                const float* __restrict__ Wk,
                                                const float* __restrict__ Wv,
                                                const float* __restrict__ Wo,
                                                __half* __restrict__ wh)
{
    const int z = blockIdx.y;
    const float* src = (z == 0) ? Wq : (z == 1) ? Wk : (z == 2) ? Wv : Wo;
    __half* dst = wh + (size_t)z * D_ * D_;
    int i = blockIdx.x * 256 + threadIdx.x;
    float4 v = ((const float4*)src)[i];
    ((uint32_t*)dst)[2 * i + 0] = f2h2(v.x, v.y);
    ((uint32_t*)dst)[2 * i + 1] = f2h2(v.z, v.w);
}

// ============================ fp16 2-product GEMM ============
// C = (Ah + Al) * W^T, A fp16 hi/lo (22-bit exact), W single fp16.
// Stage: Ah(8K) | Al(8K) | W(8K) = 24KB; double buffered = 48KB; 2 CTA/SM.
#define GS_STAGE 24576
#define GS_SMEM  (2 * GS_STAGE)
#define GS_NCHUNK 32

__device__ __forceinline__ void gt_fill32(uint32_t base,
                                          const __half* Ahi, const __half* Alo,
                                          const __half* W,
                                          int m0, int n0, int k0, int tid)
{
#pragma unroll
    for (int j = 0; j < 2; j++) {
        int id = tid + j * 256;
        int r  = id >> 2;
        int c  = id & 3;
        uint32_t sw = pr64(r, c);
        size_t aoff = (size_t)(m0 + r) * D_ + k0 + c * 8;
        size_t boff = (size_t)(n0 + r) * D_ + k0 + c * 8;
        cp_async16(base + 0     + sw, Ahi + aoff);
        cp_async16(base + 8192  + sw, Alo + aoff);
        cp_async16(base + 16384 + sw, W + boff);
    }
}

__device__ __forceinline__ void gemm32_core(uint32_t sb,
                                            const __half* __restrict__ Ahi,
                                            const __half* __restrict__ Alo,
                                            const __half* __restrict__ W,
                                            int m0, int n0, float acc[4][4][4])
{
    const int tid = threadIdx.x;
    const int wid = tid >> 5;
    const int lid = tid & 31;
    const int wm  = wid >> 2;
    const int wn  = wid & 3;

#pragma unroll
    for (int mt = 0; mt < 4; mt++)
#pragma unroll
        for (int nt = 0; nt < 4; nt++)
#pragma unroll
            for (int r = 0; r < 4; r++) acc[mt][nt][r] = 0.0f;

    gt_fill32(sb, Ahi, Alo, W, m0, n0, 0, tid);
    CP_COMMIT();
    gt_fill32(sb + GS_STAGE, Ahi, Alo, W, m0, n0, 32, tid);
    CP_COMMIT();

    const int a_row = (lid & 15);
    const int a_kc  = (lid >> 4);
    const int b_row = (lid & 7) + ((lid >> 4) << 3);
    const int b_kc  = (lid >> 3) & 1;

    for (int i = 0; i < GS_NCHUNK; i++) {
        if (i == GS_NCHUNK - 1) asm volatile("cp.async.wait_group 0;" ::: "memory");
        else                    asm volatile("cp.async.wait_group 1;" ::: "memory");
        __syncthreads();

        const uint32_t tb = sb + (i & 1) * GS_STAGE;

#pragma unroll
        for (int ks = 0; ks < 2; ks++) {
            uint32_t bw[4][2];
#pragma unroll
            for (int ng = 0; ng < 2; ng++) {
                const int nrow = wn * 32 + ng * 16 + b_row;
                const uint32_t sw = pr64(nrow, ks * 2 + b_kc);
                uint32_t r[4];
                ldm_x4(r, tb + 16384 + sw);
                bw[2 * ng][0] = r[0]; bw[2 * ng][1] = r[1];
                bw[2 * ng + 1][0] = r[2]; bw[2 * ng + 1][1] = r[3];
            }
#pragma unroll
            for (int mt = 0; mt < 4; mt++) {
                const int mrow = wm * 64 + mt * 16 + a_row;
                const uint32_t sw = pr64(mrow, ks * 2 + a_kc);
                uint32_t ahi[4], alo[4];
                ldm_x4(ahi, tb + 0 + sw);
                ldm_x4(alo, tb + 8192 + sw);
#pragma unroll
                for (int nt = 0; nt < 4; nt++) {
                    mma16816h(acc[mt][nt], ahi, bw[nt]);
                    mma16816h(acc[mt][nt], alo, bw[nt]);
                }
            }
        }
        __syncthreads();

        if (i + 2 < GS_NCHUNK) {
            gt_fill32(sb + (i & 1) * GS_STAGE, Ahi, Alo, W, m0, n0, (i + 2) * 32, tid);
            CP_COMMIT();
        }
    }
}

__global__ __launch_bounds__(256, 2) void gemm_qkv_fused(
    const __half* __restrict__ xhi, const __half* __restrict__ xlo,
    const __half* __restrict__ wh,
    const int* __restrict__ pos,
    __nv_bfloat16* __restrict__ qhi, __nv_bfloat16* __restrict__ qlo,
    __nv_bfloat16* __restrict__ khi, __nv_bfloat16* __restrict__ klo,
    __half* __restrict__ vhi, __half* __restrict__ vlo)
{
    extern __shared__ __align__(1024) char smem[];
    uint32_t sb = smem_u32(smem);
    const int z  = blockIdx.z;
    const int m0 = blockIdx.y * 128;
    const int n0 = blockIdx.x * 128;

    float acc[4][4][4];
    gemm32_core(sb, xhi, xlo, wh + (size_t)z * D_ * D_, m0, n0, acc);

    const int lid = threadIdx.x & 31;
    const int wid = threadIdx.x >> 5;
    const int wm  = wid >> 2;
    const int wn  = wid & 3;

    if (z == 2) {
        // V: fp16 hi/lo split (for fp16 PV MMA in attention)
#pragma unroll
        for (int mt = 0; mt < 4; mt++) {
            const int row = m0 + wm * 64 + mt * 16 + (lid >> 2);
#pragma unroll
            for (int nt = 0; nt < 4; nt++) {
                const int col = n0 + wn * 32 + nt * 8 + (lid & 3) * 2;
                uint32_t hi, lo;
                size_t adr = (size_t)row * D_ + col;
                hilo_pack_h(acc[mt][nt][0], acc[mt][nt][1], hi, lo);
                *(uint32_t*)(vhi + adr) = hi;
                *(uint32_t*)(vlo + adr) = lo;
                adr += (size_t)8 * D_;
                hilo_pack_h(acc[mt][nt][2], acc[mt][nt][3], hi, lo);
                *(uint32_t*)(vhi + adr) = hi;
                *(uint32_t*)(vlo + adr) = lo;
            }
        }
        return;
    }

    __nv_bfloat16* oh = (z == 0) ? qhi : khi;
    __nv_bfloat16* ol = (z == 0) ? qlo : klo;
    const float scale = (z == 0) ? 0.125f : 1.0f;

#pragma unroll
    for (int mt = 0; mt < 4; mt++) {
        const int row = m0 + wm * 64 + mt * 16 + (lid >> 2);
#pragma unroll
        for (int nt = 0; nt < 4; nt++) {
            const int col = n0 + wn * 32 + nt * 8 + (lid & 3) * 2;
            float c0 = acc[mt][nt][0], c1 = acc[mt][nt][1];
            float c2 = acc[mt][nt][2], c3 = acc[mt][nt][3];
            {
                const float invf = g_invfreq[(col & 63) >> 1];
                float s0, q0, s1, q1;
                sincosf((float)pos[row & (L_ - 1)] * invf, &s0, &q0);
                sincosf((float)pos[(row + 8) & (L_ - 1)] * invf, &s1, &q1);
                float t0 = (c0 * q0 - c1 * s0) * scale;
                float t1 = (c0 * s0 + c1 * q0) * scale;
                float t2 = (c2 * q1 - c3 * s1) * scale;
                float t3 = (c2 * s1 + c3 * q1) * scale;
                c0 = t0; c1 = t1; c2 = t2; c3 = t3;
            }
            uint32_t hi, lo;
            size_t adr = (size_t)row * D_ + col;
            hilo_pack(c0, c1, hi, lo);
            *(uint32_t*)(oh + adr) = hi;
            *(uint32_t*)(ol + adr) = lo;
            adr += (size_t)8 * D_;
            hilo_pack(c2, c3, hi, lo);
            *(uint32_t*)(oh + adr) = hi;
            *(uint32_t*)(ol + adr) = lo;
        }
    }
}

__global__ __launch_bounds__(256, 2) void gemm_out(
    const __half* __restrict__ ahi, const __half* __restrict__ alo,
    const __half* __restrict__ wh,
    float* __restrict__ C)
{
    extern __shared__ __align__(1024) char smem[];
    uint32_t sb = smem_u32(smem);
    const int m0 = blockIdx.y * 128;
    const int n0 = blockIdx.x * 128;

    float acc[4][4][4];
    gemm32_core(sb, ahi, alo, wh, m0, n0, acc);

    const int lid = threadIdx.x & 31;
    const int wid = threadIdx.x >> 5;
    const int wm  = wid >> 2;
    const int wn  = wid & 3;
#pragma unroll
    for (int mt = 0; mt < 4; mt++) {
        const int row = m0 + wm * 64 + mt * 16 + (lid >> 2);
#pragma unroll
        for (int nt = 0; nt < 4; nt++) {
            const int col = n0 + wn * 32 + nt * 8 + (lid & 3) * 2;
            *(float2*)&C[(size_t)row * D_ + col]       = make_float2(acc[mt][nt][0], acc[mt][nt][1]);
            *(float2*)&C[(size_t)(row + 8) * D_ + col] = make_float2(acc[mt][nt][2], acc[mt][nt][3]);
        }
    }
}

// ============================ paired-tile attention (R13 exact, fp16 O out) ==========
#define AT_KV0   32768
#define AT_STAGE 32768
#define AT_SMEM  (AT_KV0 + 2 * AT_STAGE)

__device__ __forceinline__ void at_fill(uint32_t sb, int stage, size_t gbase, int k0,
                                        const __nv_bfloat16* khi, const __nv_bfloat16* klo,
                                        const __half* vhi, const __half* vlo,
                                        int tid)
{
    uint32_t kb = sb + AT_KV0 + stage * AT_STAGE;
#pragma unroll
    for (int j = 0; j < 4; j++) {
        int id = tid + j * 128;
        int r  = id >> 3;
        int c  = id & 7;
        uint32_t sw = SMEM_SWIZZLE_128B((uint32_t)(r * 128 + c * 16));
        size_t off = gbase + (size_t)(k0 + r) * D_ + c * 8;
        cp_async16(kb + 0     + sw, khi + off);
        cp_async16(kb + 8192  + sw, klo + off);
        cp_async16(kb + 16384 + sw, vhi + off);
        cp_async16(kb + 24576 + sw, vlo + off);
    }
}

__device__ __forceinline__ void attn_step(uint32_t kb,
                                          const uint32_t (&qh)[4][4], const uint32_t (&ql)[4][4],
                                          float (&o)[8][4], float (&m_run)[2], float (&l_run)[2],
                                          bool diag, int wid, int lid)
{
    const int brow = (lid & 7) + ((lid >> 4) << 3);
    const int bkc  = (lid >> 3) & 1;
    const int vrow = lid & 15;
    const int vcol = (lid >> 4) << 3;

    float s[8][4];
#pragma unroll
    for (int j = 0; j < 8; j++)
#pragma unroll
        for (int r = 0; r < 4; r++) s[j][r] = 0.0f;

#pragma unroll
    for (int ks = 0; ks < 4; ks++) {
#pragma unroll
        for (int ng = 0; ng < 4; ng++) {
            uint32_t sw = SMEM_SWIZZLE_128B(
                (uint32_t)((ng * 16 + brow) * 128 + (ks * 2 + bkc) * 16));
            uint32_t kh4[4], kl4[4];
            ldm_x4(kh4, kb + 0 + sw);
            ldm_x4(kl4, kb + 8192 + sw);
            mma16816(s[ng * 2],     qh[ks], kh4 + 0);
            mma16816(s[ng * 2],     qh[ks], kl4 + 0);
            mma16816(s[ng * 2],     ql[ks], kh4 + 0);
            mma16816(s[ng * 2 + 1], qh[ks], kh4 + 2);
            mma16816(s[ng * 2 + 1], qh[ks], kl4 + 2);
            mma16816(s[ng * 2 + 1], ql[ks], kh4 + 2);
        }
    }

    if (diag) {
        const int rlo = wid * 16 + (lid >> 2);
#pragma unroll
        for (int j = 0; j < 8; j++) {
            const int cb = ((j >> 1) << 4) + ((j & 1) << 3) + ((lid & 3) << 1);
            if (cb     > rlo)     s[j][0] = -1e30f;
            if (cb + 1 > rlo)     s[j][1] = -1e30f;
            if (cb     > rlo + 8) s[j][2] = -1e30f;
            if (cb + 1 > rlo + 8) s[j][3] = -1e30f;
        }
    }

    float mx0 = -1e30f, mx1 = -1e30f;
#pragma unroll
    for (int j = 0; j < 8; j++) {
        mx0 = fmaxf(mx0, fmaxf(s[j][0], s[j][1]));
        mx1 = fmaxf(mx1, fmaxf(s[j][2], s[j][3]));
    }
    mx0 = fmaxf(mx0, __shfl_xor_sync(0xffffffffu, mx0, 1));
    mx0 = fmaxf(mx0, __shfl_xor_sync(0xffffffffu, mx0, 2));
    mx1 = fmaxf(mx1, __shfl_xor_sync(0xffffffffu, mx1, 1));
    mx1 = fmaxf(mx1, __shfl_xor_sync(0xffffffffu, mx1, 2));
    const float mn0 = fmaxf(m_run[0], mx0);
    const float mn1 = fmaxf(m_run[1], mx1);
    const float cr0 = exp_fast(m_run[0] - mn0);
    const float cr1 = exp_fast(m_run[1] - mn1);
    m_run[0] = mn0; m_run[1] = mn1;

    float ps0 = 0.0f, ps1 = 0.0f;
#pragma unroll
    for (int j = 0; j < 8; j++) {
        s[j][0] = exp_fast(s[j][0] - mn0); ps0 += s[j][0];
        s[j][1] = exp_fast(s[j][1] - mn0); ps0 += s[j][1];
        s[j][2] = exp_fast(s[j][2] - mn1); ps1 += s[j][2];
        s[j][3] = exp_fast(s[j][3] - mn1); ps1 += s[j][3];
    }
    ps0 += __shfl_xor_sync(0xffffffffu, ps0, 1);
    ps0 += __shfl_xor_sync(0xffffffffu, ps0, 2);
    ps1 += __shfl_xor_sync(0xffffffffu, ps1, 1);
    ps1 += __shfl_xor_sync(0xffffffffu, ps1, 2);
    l_run[0] = l_run[0] * cr0 + ps0;
    l_run[1] = l_run[1] * cr1 + ps1;

#pragma unroll
    for (int j = 0; j < 8; j++) {
        o[j][0] *= cr0; o[j][1] *= cr0;
        o[j][2] *= cr1; o[j][3] *= cr1;
    }

    uint32_t ph[4][4];
#pragma unroll
    for (int kc = 0; kc < 4; kc++) {
        ph[kc][0] = f2h2(s[2 * kc][0],     s[2 * kc][1]);
        ph[kc][1] = f2h2(s[2 * kc][2],     s[2 * kc][3]);
        ph[kc][2] = f2h2(s[2 * kc + 1][0], s[2 * kc + 1][1]);
        ph[kc][3] = f2h2(s[2 * kc + 1][2], s[2 * kc + 1][3]);
    }

    const uint32_t vb = kb + 16384;
#pragma unroll
    for (int kc = 0; kc < 4; kc++) {
#pragma unroll
        for (int nd = 0; nd < 4; nd++) {
            uint32_t sw = SMEM_SWIZZLE_128B(
                (uint32_t)((kc * 16 + vrow) * 128 + (nd * 16 + vcol) * 2));
            uint32_t vh4[4], vl4[4];
            ldm_x4_t(vh4, vb + 0 + sw);
            ldm_x4_t(vl4, vb + 8192 + sw);
            mma16816h(o[nd * 2],     ph[kc], vh4 + 0);
            mma16816h(o[nd * 2],     ph[kc], vl4 + 0);
            mma16816h(o[nd * 2 + 1], ph[kc], vh4 + 2);
            mma16816h(o[nd * 2 + 1], ph[kc], vl4 + 2);
        }
    }
}

__device__ __forceinline__ void attn_epilogue(const float (&o)[8][4],
                                              const float (&l_run)[2],
                                              size_t gbase, int q0, int wid, int lid,
                                              __half* ohi, __half* olo)
{
    const float inv0 = 1.0f / l_run[0];
    const float inv1 = 1.0f / l_run[1];
    const int rlo = q0 + wid * 16 + (lid >> 2);
#pragma unroll
    for (int j = 0; j < 8; j++) {
        const int col = ((j >> 1) << 4) + ((j & 1) << 3) + ((lid & 3) << 1);
        uint32_t hi, lo;
        size_t adr0 = gbase + (size_t)rlo * D_ + col;
        hilo_pack_h(o[j][0] * inv0, o[j][1] * inv0, hi, lo);
        *(uint32_t*)(ohi + adr0) = hi;
        *(uint32_t*)(olo + adr0) = lo;
        size_t adr1 = adr0 + (size_t)8 * D_;
        hilo_pack_h(o[j][2] * inv1, o[j][3] * inv1, hi, lo);
        *(uint32_t*)(ohi + adr1) = hi;
        *(uint32_t*)(olo + adr1) = lo;
    }
}

__global__ __launch_bounds__(128) void attn_mma(const __nv_bfloat16* __restrict__ qhi,
                                                const __nv_bfloat16* __restrict__ qlo,
                                                const __nv_bfloat16* __restrict__ khi,
                                                const __nv_bfloat16* __restrict__ klo,
                                                const __half* __restrict__ vhi,
                                                const __half* __restrict__ vlo,
                                                __half* __restrict__ ohi,
                                                __half* __restrict__ olo)
{
    extern __shared__ __align__(1024) char smem[];
    uint32_t sb = smem_u32(smem);
    const int tid = threadIdx.x;
    const int wid = tid >> 5;
    const int lid = tid & 31;
    const int p   = blockIdx.x;           // pair id: tiles p and 31-p
    const int qta = p;
    const int qtb = (L_ / 64 - 1) - p;
    const int h   = blockIdx.y;
    const int b   = blockIdx.z;
    const size_t gbase = (size_t)(b * L_) * D_ + h * DH_;

#pragma unroll
    for (int j = 0; j < 4; j++) {
        int id = tid + j * 128;
        int r  = id >> 3;
        int c  = id & 7;
        uint32_t sw = SMEM_SWIZZLE_128B((uint32_t)(r * 128 + c * 16));
        size_t offa = gbase + (size_t)(qta * 64 + r) * D_ + c * 8;
        size_t offb = gbase + (size_t)(qtb * 64 + r) * D_ + c * 8;
        cp_async16(sb + 0     + sw, qhi + offa);
        cp_async16(sb + 8192  + sw, qlo + offa);
        cp_async16(sb + 16384 + sw, qhi + offb);
        cp_async16(sb + 24576 + sw, qlo + offb);
    }
    CP_COMMIT();
    at_fill(sb, 0, gbase, 0, khi, klo, vhi, vlo, tid);
    CP_COMMIT();
    asm volatile("cp.async.wait_group 0;" ::: "memory");
    __syncthreads();

    uint32_t qhA[4][4], qlA[4][4], qhB[4][4], qlB[4][4];
    {
        const int arow = wid * 16 + (lid & 15);
        const int akc  = lid >> 4;
#pragma unroll
        for (int ks = 0; ks < 4; ks++) {
            uint32_t sw = SMEM_SWIZZLE_128B((uint32_t)(arow * 128 + (ks * 2 + akc) * 16));
            ldm_x4(qhA[ks], sb + 0 + sw);
            ldm_x4(qlA[ks], sb + 8192 + sw);
            ldm_x4(qhB[ks], sb + 16384 + sw);
            ldm_x4(qlB[ks], sb + 24576 + sw);
        }
    }

    float mA[2] = {-1e30f, -1e30f}, lA[2] = {0.0f, 0.0f};
    float mB[2] = {-1e30f, -1e30f}, lB[2] = {0.0f, 0.0f};
    float oA[8][4], oB[8][4];
#pragma unroll
    for (int j = 0; j < 8; j++)
#pragma unroll
        for (int r = 0; r < 4; r++) { oA[j][r] = 0.0f; oB[j][r] = 0.0f; }

    const int nkt = qtb + 1;
    for (int kt = 0; kt < nkt; kt++) {
        __syncthreads();
        if (kt + 1 < nkt) {
            at_fill(sb, (kt + 1) & 1, gbase, (kt + 1) * 64, khi, klo, vhi, vlo, tid);
            CP_COMMIT();
            asm volatile("cp.async.wait_group 1;" ::: "memory");
        } else {
            asm volatile("cp.async.wait_group 0;" ::: "memory");
        }
        __syncthreads();

        const uint32_t kb = sb + AT_KV0 + (kt & 1) * AT_STAGE;

        if (kt <= qta)
            attn_step(kb, qhA, qlA, oA, mA, lA, kt == qta, wid, lid);
        attn_step(kb, qhB, qlB, oB, mB, lB, kt == qtb, wid, lid);
    }

    attn_epilogue(oA, lA, gbase, qta * 64, wid, lid, ohi, olo);
    attn_epilogue(oB, lB, gbase, qtb * 64, wid, lid, ohi, olo);
}

// ============================ launch ============================
extern "C" void kernel_launch(void* const* d_in, const int* in_sizes, int n_in,
                              void* d_out, int out_size)
{
    const float* x   = (const float*)d_in[0];
    const float* Wq  = (const float*)d_in[1];
    const float* Wk  = (const float*)d_in[2];
    const float* Wv  = (const float*)d_in[3];
    const float* Wo  = (const float*)d_in[4];
    const int*   pos = (const int*)  d_in[5];
    float* out = (float*)d_out;

    __half *xhi, *xlo, *wh, *vhi, *vlo, *ohi, *olo;
    __nv_bfloat16 *qhi, *qlo, *khi, *klo;
    cudaGetSymbolAddress((void**)&xhi, g_xhi);
    cudaGetSymbolAddress((void**)&xlo, g_xlo);
    cudaGetSymbolAddress((void**)&wh,  g_wh);
    cudaGetSymbolAddress((void**)&qhi, g_qhi);
    cudaGetSymbolAddress((void**)&qlo, g_qlo);
    cudaGetSymbolAddress((void**)&khi, g_khi);
    cudaGetSymbolAddress((void**)&klo, g_klo);
    cudaGetSymbolAddress((void**)&vhi, g_vhi);
    cudaGetSymbolAddress((void**)&vlo, g_vlo);
    cudaGetSymbolAddress((void**)&ohi, g_ohi);
    cudaGetSymbolAddress((void**)&olo, g_olo);

    cudaFuncSetAttribute(gemm_qkv_fused, cudaFuncAttributeMaxDynamicSharedMemorySize, GS_SMEM);
    cudaFuncSetAttribute(gemm_out,       cudaFuncAttributeMaxDynamicSharedMemorySize, GS_SMEM);
    cudaFuncSetAttribute(attn_mma,       cudaFuncAttributeMaxDynamicSharedMemorySize, AT_SMEM);

    const int nx4 = BL_ * D_ / 4;
    const int nw4 = D_ * D_ / 4;

    split_h<<<nx4 / 256, 256>>>(x, xhi, xlo, nx4);
    split_w4<<<dim3(nw4 / 256, 4), 256>>>(Wq, Wk, Wv, Wo, wh);

    dim3 qkv_grid(D_ / 128, BL_ / 128, 3);
    gemm_qkv_fused<<<qkv_grid, 256, GS_SMEM>>>(xhi, xlo, wh, pos,
                                               qhi, qlo, khi, klo, vhi, vlo);

    attn_mma<<<dim3(L_ / 128, H_, B_), 128, AT_SMEM>>>(qhi, qlo, khi, klo, vhi, vlo, ohi, olo);

    dim3 ggrid(D_ / 128, BL_ / 128);
    gemm_out<<<ggrid, 256, GS_SMEM>>>(ohi, olo, wh + 3 * (size_t)D_ * D_, out);
}

// round 15
// speedup vs baseline: 1.4889x; 1.0608x over previous
#include <cuda_runtime.h>
#include <cuda_bf16.h>
#include <cuda_fp16.h>
#include <cstdint>

#define B_  2
#define L_  2048
#define D_  1024
#define H_  16
#define DH_ 64
#define BL_ (B_ * L_)

// ============================ helpers ============================
__device__ __forceinline__ uint32_t smem_u32(const void* p) {
    uint32_t a;
    asm("{ .reg .u64 t; cvta.to.shared.u64 t, %1; cvt.u32.u64 %0, t; }" : "=r"(a) : "l"(p));
    return a;
}
#define SMEM_SWIZZLE_128B(x) ((x) ^ (((x) >> 3) & 0x70))

// paired-row layout for 64B logical rows inside a SW128 tile (conflict-free ldmatrix)
__device__ __forceinline__ uint32_t pr64(int r, int c16) {
    uint32_t off = (uint32_t)(((r >> 1) << 7) + ((r & 1) << 6) + (c16 << 4));
    return SMEM_SWIZZLE_128B(off);
}

__device__ __forceinline__ void cp_async16(uint32_t dst, const void* src) {
    asm volatile("cp.async.ca.shared.global [%0], [%1], 16;" :: "r"(dst), "l"(src) : "memory");
}
#define CP_COMMIT() asm volatile("cp.async.commit_group;" ::: "memory")

__device__ __forceinline__ void ldm_x4(uint32_t* r, uint32_t addr) {
    asm volatile("ldmatrix.sync.aligned.m8n8.x4.shared.b16 {%0,%1,%2,%3}, [%4];"
        : "=r"(r[0]), "=r"(r[1]), "=r"(r[2]), "=r"(r[3]) : "r"(addr));
}
__device__ __forceinline__ void ldm_x4_t(uint32_t* r, uint32_t addr) {
    asm volatile("ldmatrix.sync.aligned.m8n8.x4.trans.shared.b16 {%0,%1,%2,%3}, [%4];"
        : "=r"(r[0]), "=r"(r[1]), "=r"(r[2]), "=r"(r[3]) : "r"(addr));
}

// D = A*B + D  (m16n8k16, fp16 in, fp32 accum)
__device__ __forceinline__ void mma16816h(float* c, const uint32_t* a, const uint32_t* b) {
    asm volatile("mma.sync.aligned.m16n8k16.row.col.f32.f16.f16.f32 "
        "{%0,%1,%2,%3}, {%4,%5,%6,%7}, {%8,%9}, {%0,%1,%2,%3};"
        : "+f"(c[0]), "+f"(c[1]), "+f"(c[2]), "+f"(c[3])
        : "r"(a[0]), "r"(a[1]), "r"(a[2]), "r"(a[3]), "r"(b[0]), "r"(b[1]));
}

// exp(x) for x <= 0, FMA/ALU pipes only. abs err <= ~3e-5.
__device__ __forceinline__ float exp_fast(float x) {
    float t = x * 1.44269504f;
    t = fmaxf(t, -126.0f);
    float fi = floorf(t);
    float f = t - fi;
    float r = 1.54035304e-4f;
    r = fmaf(r, f, 1.33335581e-3f);
    r = fmaf(r, f, 9.61812911e-3f);
    r = fmaf(r, f, 5.55041087e-2f);
    r = fmaf(r, f, 2.40226507e-1f);
    r = fmaf(r, f, 6.93147181e-1f);
    r = fmaf(r, f, 1.0f);
    return r * __int_as_float(((int)fi + 127) << 23);
}

__device__ __forceinline__ void hilo_pack_h(float a, float b, uint32_t& hi, uint32_t& lo) {
    __half ah = __float2half_rn(a);
    __half bh = __float2half_rn(b);
    __half al = __float2half_rn(a - __half2float(ah));
    __half bl = __float2half_rn(b - __half2float(bh));
    __half2 h2 = __halves2half2(ah, bh), l2 = __halves2half2(al, bl);
    hi = *(uint32_t*)&h2;
    lo = *(uint32_t*)&l2;
}

__device__ __forceinline__ uint32_t f2h2(float a, float b) {
    __half2 h = __floats2half2_rn(a, b);
    return *(uint32_t*)&h;
}

// ============================ scratch globals ============================
__device__ __half g_xhi[BL_ * D_];
__device__ __half g_xlo[BL_ * D_];
__device__ __half g_wh[4 * D_ * D_];     // weights: single fp16
__device__ __half g_qhi[BL_ * D_];
__device__ __half g_qlo[BL_ * D_];
__device__ __half g_kh[BL_ * D_];        // K: single fp16
__device__ __half g_vhi[BL_ * D_];
__device__ __half g_vlo[BL_ * D_];
__device__ __half g_ohi[BL_ * D_];
__device__ __half g_olo[BL_ * D_];

__device__ const float g_invfreq[32] = {
    1.0f, 0.7498942093324559f, 0.5623413251903491f, 0.4216965034285823f,
    0.31622776601683794f, 0.2371373705661655f, 0.1778279410038923f, 0.13335214321633237f,
    0.1f, 0.07498942093324559f, 0.05623413251903491f, 0.04216965034285823f,
    0.031622776601683794f, 0.02371373705661655f, 0.01778279410038923f, 0.013335214321633237f,
    0.01f, 0.007498942093324559f, 0.005623413251903491f, 0.004216965034285823f,
    0.0031622776601683794f, 0.002371373705661655f, 0.001778279410038923f, 0.0013335214321633237f,
    0.001f, 0.0007498942093324559f, 0.0005623413251903491f, 0.0004216965034285823f,
    0.00031622776601683794f, 0.0002371373705661655f, 0.0001778279410038923f, 0.00013335214321633237f
};

// ============================ splits ============================
__global__ __launch_bounds__(256) void split_h(const float* __restrict__ src,
                                               __half* __restrict__ hi,
                                               __half* __restrict__ lo,
                                               int n4)
{
    int i = blockIdx.x * 256 + threadIdx.x;
    if (i >= n4) return;
    float4 v = ((const float4*)src)[i];
    uint32_t h0, l0, h1, l1;
    hilo_pack_h(v.x, v.y, h0, l0);
    hilo_pack_h(v.z, v.w, h1, l1);
    ((uint32_t*)hi)[2 * i + 0] = h0;
    ((uint32_t*)hi)[2 * i + 1] = h1;
    ((uint32_t*)lo)[2 * i + 0] = l0;
    ((uint32_t*)lo)[2 * i + 1] = l1;
}

__global__ __launch_bounds__(256) void split_w4(const float* __restrict__ Wq,
                                                const float* __restrict__ Wk,
                                                const float* __restrict__ Wv,
                                                const float* __restrict__ Wo,
                                                __half* __restrict__ wh)
{
    const int z = blockIdx.y;
    const float* src = (z == 0) ? Wq : (z == 1) ? Wk : (z == 2) ? Wv : Wo;
    __half* dst = wh + (size_t)z * D_ * D_;
    int i = blockIdx.x * 256 + threadIdx.x;
    float4 v = ((const float4*)src)[i];
    ((uint32_t*)dst)[2 * i + 0] = f2h2(v.x, v.y);
    ((uint32_t*)dst)[2 * i + 1] = f2h2(v.z, v.w);
}

// ============================ fp16 2-product GEMM (R14 exact) ============
#define GS_STAGE 24576
#define GS_SMEM  (2 * GS_STAGE)
#define GS_NCHUNK 32

__device__ __forceinline__ void gt_fill32(uint32_t base,
                                          const __half* Ahi, const __half* Alo,
                                          const __half* W,
                                          int m0, int n0, int k0, int tid)
{
#pragma unroll
    for (int j = 0; j < 2; j++) {
        int id = tid + j * 256;
        int r  = id >> 2;
        int c  = id & 3;
        uint32_t sw = pr64(r, c);
        size_t aoff = (size_t)(m0 + r) * D_ + k0 + c * 8;
        size_t boff = (size_t)(n0 + r) * D_ + k0 + c * 8;
        cp_async16(base + 0     + sw, Ahi + aoff);
        cp_async16(base + 8192  + sw, Alo + aoff);
        cp_async16(base + 16384 + sw, W + boff);
    }
}

__device__ __forceinline__ void gemm32_core(uint32_t sb,
                                            const __half* __restrict__ Ahi,
                                            const __half* __restrict__ Alo,
                                            const __half* __restrict__ W,
                                            int m0, int n0, float acc[4][4][4])
{
    const int tid = threadIdx.x;
    const int wid = tid >> 5;
    const int lid = tid & 31;
    const int wm  = wid >> 2;
    const int wn  = wid & 3;

#pragma unroll
    for (int mt = 0; mt < 4; mt++)
#pragma unroll
        for (int nt = 0; nt < 4; nt++)
#pragma unroll
            for (int r = 0; r < 4; r++) acc[mt][nt][r] = 0.0f;

    gt_fill32(sb, Ahi, Alo, W, m0, n0, 0, tid);
    CP_COMMIT();
    gt_fill32(sb + GS_STAGE, Ahi, Alo, W, m0, n0, 32, tid);
    CP_COMMIT();

    const int a_row = (lid & 15);
    const int a_kc  = (lid >> 4);
    const int b_row = (lid & 7) + ((lid >> 4) << 3);
    const int b_kc  = (lid >> 3) & 1;

    for (int i = 0; i < GS_NCHUNK; i++) {
        if (i == GS_NCHUNK - 1) asm volatile("cp.async.wait_group 0;" ::: "memory");
        else                    asm volatile("cp.async.wait_group 1;" ::: "memory");
        __syncthreads();

        const uint32_t tb = sb + (i & 1) * GS_STAGE;

#pragma unroll
        for (int ks = 0; ks < 2; ks++) {
            uint32_t bw[4][2];
#pragma unroll
            for (int ng = 0; ng < 2; ng++) {
                const int nrow = wn * 32 + ng * 16 + b_row;
                const uint32_t sw = pr64(nrow, ks * 2 + b_kc);
                uint32_t r[4];
                ldm_x4(r, tb + 16384 + sw);
                bw[2 * ng][0] = r[0]; bw[2 * ng][1] = r[1];
                bw[2 * ng + 1][0] = r[2]; bw[2 * ng + 1][1] = r[3];
            }
#pragma unroll
            for (int mt = 0; mt < 4; mt++) {
                const int mrow = wm * 64 + mt * 16 + a_row;
                const uint32_t sw = pr64(mrow, ks * 2 + a_kc);
                uint32_t ahi[4], alo[4];
                ldm_x4(ahi, tb + 0 + sw);
                ldm_x4(alo, tb + 8192 + sw);
#pragma unroll
                for (int nt = 0; nt < 4; nt++) {
                    mma16816h(acc[mt][nt], ahi, bw[nt]);
                    mma16816h(acc[mt][nt], alo, bw[nt]);
                }
            }
        }
        __syncthreads();

        if (i + 2 < GS_NCHUNK) {
            gt_fill32(sb + (i & 1) * GS_STAGE, Ahi, Alo, W, m0, n0, (i + 2) * 32, tid);
            CP_COMMIT();
        }
    }
}

__global__ __launch_bounds__(256, 2) void gemm_qkv_fused(
    const __half* __restrict__ xhi, const __half* __restrict__ xlo,
    const __half* __restrict__ wh,
    const int* __restrict__ pos,
    __half* __restrict__ qhi, __half* __restrict__ qlo,
    __half* __restrict__ kh,
    __half* __restrict__ vhi, __half* __restrict__ vlo)
{
    extern __shared__ __align__(1024) char smem[];
    uint32_t sb = smem_u32(smem);
    const int z  = blockIdx.z;
    const int m0 = blockIdx.y * 128;
    const int n0 = blockIdx.x * 128;

    float acc[4][4][4];
    gemm32_core(sb, xhi, xlo, wh + (size_t)z * D_ * D_, m0, n0, acc);

    const int lid = threadIdx.x & 31;
    const int wid = threadIdx.x >> 5;
    const int wm  = wid >> 2;
    const int wn  = wid & 3;

    if (z == 1) {
        // K: single fp16
#pragma unroll
        for (int mt = 0; mt < 4; mt++) {
            const int row = m0 + wm * 64 + mt * 16 + (lid >> 2);
#pragma unroll
            for (int nt = 0; nt < 4; nt++) {
                const int col = n0 + wn * 32 + nt * 8 + (lid & 3) * 2;
                size_t adr = (size_t)row * D_ + col;
                *(uint32_t*)(kh + adr) = f2h2(acc[mt][nt][0], acc[mt][nt][1]);
                adr += (size_t)8 * D_;
                *(uint32_t*)(kh + adr) = f2h2(acc[mt][nt][2], acc[mt][nt][3]);
            }
        }
        return;
    }
    if (z == 2) {
        // V: fp16 hi/lo
#pragma unroll
        for (int mt = 0; mt < 4; mt++) {
            const int row = m0 + wm * 64 + mt * 16 + (lid >> 2);
#pragma unroll
            for (int nt = 0; nt < 4; nt++) {
                const int col = n0 + wn * 32 + nt * 8 + (lid & 3) * 2;
                uint32_t hi, lo;
                size_t adr = (size_t)row * D_ + col;
                hilo_pack_h(acc[mt][nt][0], acc[mt][nt][1], hi, lo);
                *(uint32_t*)(vhi + adr) = hi;
                *(uint32_t*)(vlo + adr) = lo;
                adr += (size_t)8 * D_;
                hilo_pack_h(acc[mt][nt][2], acc[mt][nt][3], hi, lo);
                *(uint32_t*)(vhi + adr) = hi;
                *(uint32_t*)(vlo + adr) = lo;
            }
        }
        return;
    }

    // Q: RoPE + 0.125 scale + fp16 hi/lo
#pragma unroll
    for (int mt = 0; mt < 4; mt++) {
        const int row = m0 + wm * 64 + mt * 16 + (lid >> 2);
#pragma unroll
        for (int nt = 0; nt < 4; nt++) {
            const int col = n0 + wn * 32 + nt * 8 + (lid & 3) * 2;
            float c0 = acc[mt][nt][0], c1 = acc[mt][nt][1];
            float c2 = acc[mt][nt][2], c3 = acc[mt][nt][3];
            {
                const float invf = g_invfreq[(col & 63) >> 1];
                float s0, q0, s1, q1;
                sincosf((float)pos[row & (L_ - 1)] * invf, &s0, &q0);
                sincosf((float)pos[(row + 8) & (L_ - 1)] * invf, &s1, &q1);
                float t0 = (c0 * q0 - c1 * s0) * 0.125f;
                float t1 = (c0 * s0 + c1 * q0) * 0.125f;
                float t2 = (c2 * q1 - c3 * s1) * 0.125f;
                float t3 = (c2 * s1 + c3 * q1) * 0.125f;
                c0 = t0; c1 = t1; c2 = t2; c3 = t3;
            }
            uint32_t hi, lo;
            size_t adr = (size_t)row * D_ + col;
            hilo_pack_h(c0, c1, hi, lo);
            *(uint32_t*)(qhi + adr) = hi;
            *(uint32_t*)(qlo + adr) = lo;
            adr += (size_t)8 * D_;
            hilo_pack_h(c2, c3, hi, lo);
            *(uint32_t*)(qhi + adr) = hi;
            *(uint32_t*)(qlo + adr) = lo;
        }
    }
}

// NOTE: K for attention also needs RoPE! Apply it in the K epilogue path.
// (handled below via a dedicated kernel variant — see gemm_qkv_fused z==1 fix)

__global__ __launch_bounds__(256, 2) void gemm_out(
    const __half* __restrict__ ahi, const __half* __restrict__ alo,
    const __half* __restrict__ wh,
    float* __restrict__ C)
{
    extern __shared__ __align__(1024) char smem[];
    uint32_t sb = smem_u32(smem);
    const int m0 = blockIdx.y * 128;
    const int n0 = blockIdx.x * 128;

    float acc[4][4][4];
    gemm32_core(sb, ahi, alo, wh, m0, n0, acc);

    const int lid = threadIdx.x & 31;
    const int wid = threadIdx.x >> 5;
    const int wm  = wid >> 2;
    const int wn  = wid & 3;
#pragma unroll
    for (int mt = 0; mt < 4; mt++) {
        const int row = m0 + wm * 64 + mt * 16 + (lid >> 2);
#pragma unroll
        for (int nt = 0; nt < 4; nt++) {
            const int col = n0 + wn * 32 + nt * 8 + (lid & 3) * 2;
            *(float2*)&C[(size_t)row * D_ + col]       = make_float2(acc[mt][nt][0], acc[mt][nt][1]);
            *(float2*)&C[(size_t)(row + 8) * D_ + col] = make_float2(acc[mt][nt][2], acc[mt][nt][3]);
        }
    }
}

// ============================ paired-tile attention (fp16 S + fp16 PV) ==========
#define AT_KV0   32768
#define AT_STAGE 24576
#define AT_SMEM  (AT_KV0 + 2 * AT_STAGE)

__device__ __forceinline__ void at_fill(uint32_t sb, int stage, size_t gbase, int k0,
                                        const __half* kh,
                                        const __half* vhi, const __half* vlo,
                                        int tid)
{
    uint32_t kb = sb + AT_KV0 + stage * AT_STAGE;
#pragma unroll
    for (int j = 0; j < 4; j++) {
        int id = tid + j * 128;
        int r  = id >> 3;
        int c  = id & 7;
        uint32_t sw = SMEM_SWIZZLE_128B((uint32_t)(r * 128 + c * 16));
        size_t off = gbase + (size_t)(k0 + r) * D_ + c * 8;
        cp_async16(kb + 0     + sw, kh + off);
        cp_async16(kb + 8192  + sw, vhi + off);
        cp_async16(kb + 16384 + sw, vlo + off);
    }
}

__device__ __forceinline__ void attn_step(uint32_t kb,
                                          const uint32_t (&qh)[4][4], const uint32_t (&ql)[4][4],
                                          float (&o)[8][4], float (&m_run)[2], float (&l_run)[2],
                                          bool diag, int wid, int lid)
{
    const int brow = (lid & 7) + ((lid >> 4) << 3);
    const int bkc  = (lid >> 3) & 1;
    const int vrow = lid & 15;
    const int vcol = (lid >> 4) << 3;

    float s[8][4];
#pragma unroll
    for (int j = 0; j < 8; j++)
#pragma unroll
        for (int r = 0; r < 4; r++) s[j][r] = 0.0f;

#pragma unroll
    for (int ks = 0; ks < 4; ks++) {
#pragma unroll
        for (int ng = 0; ng < 4; ng++) {
            uint32_t sw = SMEM_SWIZZLE_128B(
                (uint32_t)((ng * 16 + brow) * 128 + (ks * 2 + bkc) * 16));
            uint32_t kh4[4];
            ldm_x4(kh4, kb + 0 + sw);
            mma16816h(s[ng * 2],     qh[ks], kh4 + 0);
            mma16816h(s[ng * 2],     ql[ks], kh4 + 0);
            mma16816h(s[ng * 2 + 1], qh[ks], kh4 + 2);
            mma16816h(s[ng * 2 + 1], ql[ks], kh4 + 2);
        }
    }

    if (diag) {
        const int rlo = wid * 16 + (lid >> 2);
#pragma unroll
        for (int j = 0; j < 8; j++) {
            const int cb = ((j >> 1) << 4) + ((j & 1) << 3) + ((lid & 3) << 1);
            if (cb     > rlo)     s[j][0] = -1e30f;
            if (cb + 1 > rlo)     s[j][1] = -1e30f;
            if (cb     > rlo + 8) s[j][2] = -1e30f;
            if (cb + 1 > rlo + 8) s[j][3] = -1e30f;
        }
    }

    float mx0 = -1e30f, mx1 = -1e30f;
#pragma unroll
    for (int j = 0; j < 8; j++) {
        mx0 = fmaxf(mx0, fmaxf(s[j][0], s[j][1]));
        mx1 = fmaxf(mx1, fmaxf(s[j][2], s[j][3]));
    }
    mx0 = fmaxf(mx0, __shfl_xor_sync(0xffffffffu, mx0, 1));
    mx0 = fmaxf(mx0, __shfl_xor_sync(0xffffffffu, mx0, 2));
    mx1 = fmaxf(mx1, __shfl_xor_sync(0xffffffffu, mx1, 1));
    mx1 = fmaxf(mx1, __shfl_xor_sync(0xffffffffu, mx1, 2));
    const float mn0 = fmaxf(m_run[0], mx0);
    const float mn1 = fmaxf(m_run[1], mx1);
    const float cr0 = exp_fast(m_run[0] - mn0);
    const float cr1 = exp_fast(m_run[1] - mn1);
    m_run[0] = mn0; m_run[1] = mn1;

    float ps0 = 0.0f, ps1 = 0.0f;
#pragma unroll
    for (int j = 0; j < 8; j++) {
        s[j][0] = exp_fast(s[j][0] - mn0); ps0 += s[j][0];
        s[j][1] = exp_fast(s[j][1] - mn0); ps0 += s[j][1];
        s[j][2] = exp_fast(s[j][2] - mn1); ps1 += s[j][2];
        s[j][3] = exp_fast(s[j][3] - mn1); ps1 += s[j][3];
    }
    ps0 += __shfl_xor_sync(0xffffffffu, ps0, 1);
    ps0 += __shfl_xor_sync(0xffffffffu, ps0, 2);
    ps1 += __shfl_xor_sync(0xffffffffu, ps1, 1);
    ps1 += __shfl_xor_sync(0xffffffffu, ps1, 2);
    l_run[0] = l_run[0] * cr0 + ps0;
    l_run[1] = l_run[1] * cr1 + ps1;

#pragma unroll
    for (int j = 0; j < 8; j++) {
        o[j][0] *= cr0; o[j][1] *= cr0;
        o[j][2] *= cr1; o[j][3] *= cr1;
    }

    uint32_t ph[4][4];
#pragma unroll
    for (int kc = 0; kc < 4; kc++) {
        ph[kc][0] = f2h2(s[2 * kc][0],     s[2 * kc][1]);
        ph[kc][1] = f2h2(s[2 * kc][2],     s[2 * kc][3]);
        ph[kc][2] = f2h2(s[2 * kc + 1][0], s[2 * kc + 1][1]);
        ph[kc][3] = f2h2(s[2 * kc + 1][2], s[2 * kc + 1][3]);
    }

    const uint32_t vb = kb + 8192;
#pragma unroll
    for (int kc = 0; kc < 4; kc++) {
#pragma unroll
        for (int nd = 0; nd < 4; nd++) {
            uint32_t sw = SMEM_SWIZZLE_128B(
                (uint32_t)((kc * 16 + vrow) * 128 + (nd * 16 + vcol) * 2));
            uint32_t vh4[4], vl4[4];
            ldm_x4_t(vh4, vb + 0 + sw);
            ldm_x4_t(vl4, vb + 8192 + sw);
            mma16816h(o[nd * 2],     ph[kc], vh4 + 0);
            mma16816h(o[nd * 2],     ph[kc], vl4 + 0);
            mma16816h(o[nd * 2 + 1], ph[kc], vh4 + 2);
            mma16816h(o[nd * 2 + 1], ph[kc], vl4 + 2);
        }
    }
}

__device__ __forceinline__ void attn_epilogue(const float (&o)[8][4],
                                              const float (&l_run)[2],
                                              size_t gbase, int q0, int wid, int lid,
                                              __half* ohi, __half* olo)
{
    const float inv0 = 1.0f / l_run[0];
    const float inv1 = 1.0f / l_run[1];
    const int rlo = q0 + wid * 16 + (lid >> 2);
#pragma unroll
    for (int j = 0; j < 8; j++) {
        const int col = ((j >> 1) << 4) + ((j & 1) << 3) + ((lid & 3) << 1);
        uint32_t hi, lo;
        size_t adr0 = gbase + (size_t)rlo * D_ + col;
        hilo_pack_h(o[j][0] * inv0, o[j][1] * inv0, hi, lo);
        *(uint32_t*)(ohi + adr0) = hi;
        *(uint32_t*)(olo + adr0) = lo;
        size_t adr1 = adr0 + (size_t)8 * D_;
        hilo_pack_h(o[j][2] * inv1, o[j][3] * inv1, hi, lo);
        *(uint32_t*)(ohi + adr1) = hi;
        *(uint32_t*)(olo + adr1) = lo;
    }
}

__global__ __launch_bounds__(128) void attn_mma(const __half* __restrict__ qhi,
                                                const __half* __restrict__ qlo,
                                                const __half* __restrict__ kh,
                                                const __half* __restrict__ vhi,
                                                const __half* __restrict__ vlo,
                                                __half* __restrict__ ohi,
                                                __half* __restrict__ olo)
{
    extern __shared__ __align__(1024) char smem[];
    uint32_t sb = smem_u32(smem);
    const int tid = threadIdx.x;
    const int wid = tid >> 5;
    const int lid = tid & 31;
    const int p   = blockIdx.x;           // pair id: tiles p and 31-p
    const int qta = p;
    const int qtb = (L_ / 64 - 1) - p;
    const int h   = blockIdx.y;
    const int b   = blockIdx.z;
    const size_t gbase = (size_t)(b * L_) * D_ + h * DH_;

#pragma unroll
    for (int j = 0; j < 4; j++) {
        int id = tid + j * 128;
        int r  = id >> 3;
        int c  = id & 7;
        uint32_t sw = SMEM_SWIZZLE_128B((uint32_t)(r * 128 + c * 16));
        size_t offa = gbase + (size_t)(qta * 64 + r) * D_ + c * 8;
        size_t offb = gbase + (size_t)(qtb * 64 + r) * D_ + c * 8;
        cp_async16(sb + 0     + sw, qhi + offa);
        cp_async16(sb + 8192  + sw, qlo + offa);
        cp_async16(sb + 16384 + sw, qhi + offb);
        cp_async16(sb + 24576 + sw, qlo + offb);
    }
    CP_COMMIT();
    at_fill(sb, 0, gbase, 0, kh, vhi, vlo, tid);
    CP_COMMIT();
    asm volatile("cp.async.wait_group 0;" ::: "memory");
    __syncthreads();

    uint32_t qhA[4][4], qlA[4][4], qhB[4][4], qlB[4][4];
    {
        const int arow = wid * 16 + (lid & 15);
        const int akc  = lid >> 4;
#pragma unroll
        for (int ks = 0; ks < 4; ks++) {
            uint32_t sw = SMEM_SWIZZLE_128B((uint32_t)(arow * 128 + (ks * 2 + akc) * 16));
            ldm_x4(qhA[ks], sb + 0 + sw);
            ldm_x4(qlA[ks], sb + 8192 + sw);
            ldm_x4(qhB[ks], sb + 16384 + sw);
            ldm_x4(qlB[ks], sb + 24576 + sw);
        }
    }

    float mA[2] = {-1e30f, -1e30f}, lA[2] = {0.0f, 0.0f};
    float mB[2] = {-1e30f, -1e30f}, lB[2] = {0.0f, 0.0f};
    float oA[8][4], oB[8][4];
#pragma unroll
    for (int j = 0; j < 8; j++)
#pragma unroll
        for (int r = 0; r < 4; r++) { oA[j][r] = 0.0f; oB[j][r] = 0.0f; }

    const int nkt = qtb + 1;
    for (int kt = 0; kt < nkt; kt++) {
        __syncthreads();
        if (kt + 1 < nkt) {
            at_fill(sb, (kt + 1) & 1, gbase, (kt + 1) * 64, kh, vhi, vlo, tid);
            CP_COMMIT();
            asm volatile("cp.async.wait_group 1;" ::: "memory");
        } else {
            asm volatile("cp.async.wait_group 0;" ::: "memory");
        }
        __syncthreads();

        const uint32_t kb = sb + AT_KV0 + (kt & 1) * AT_STAGE;

        if (kt <= qta)
            attn_step(kb, qhA, qlA, oA, mA, lA, kt == qta, wid, lid);
        attn_step(kb, qhB, qlB, oB, mB, lB, kt == qtb, wid, lid);
    }

    attn_epilogue(oA, lA, gbase, qta * 64, wid, lid, ohi, olo);
    attn_epilogue(oB, lB, gbase, qtb * 64, wid, lid, ohi, olo);
}

// ============================ K RoPE fix in QKV epilogue ============================
// The z==1 path above writes raw K; RoPE must be applied. Patch via a small kernel
// would add a pass; instead we fold RoPE into the K epilogue directly here by
// re-defining the z==1 branch — implemented inline in gemm_qkv_fused above is raw,
// so we apply RoPE in a lightweight elementwise kernel over K (fp16 in/out).
__global__ __launch_bounds__(256) void rope_k(__half* __restrict__ kh,
                                              const int* __restrict__ pos)
{
    const int t = blockIdx.x * 256 + threadIdx.x;   // pair index
    if (t >= BL_ * (D_ / 2)) return;
    const int e2 = t & 511;
    const int pp = e2 & 31;
    const int l  = (t >> 9) & (L_ - 1);
    const float ang = (float)pos[l] * g_invfreq[pp];
    float s, c;
    sincosf(ang, &s, &c);
    uint32_t w = ((uint32_t*)kh)[t];
    __half2 hv = *(__half2*)&w;
    float a = __half2float(__low2half(hv));
    float b2 = __half2float(__high2half(hv));
    ((uint32_t*)kh)[t] = f2h2(a * c - b2 * s, a * s + b2 * c);
}

// ============================ launch ============================
extern "C" void kernel_launch(void* const* d_in, const int* in_sizes, int n_in,
                              void* d_out, int out_size)
{
    const float* x   = (const float*)d_in[0];
    const float* Wq  = (const float*)d_in[1];
    const float* Wk  = (const float*)d_in[2];
    const float* Wv  = (const float*)d_in[3];
    const float* Wo  = (const float*)d_in[4];
    const int*   pos = (const int*)  d_in[5];
    float* out = (float*)d_out;

    __half *xhi, *xlo, *wh, *qhi, *qlo, *kh, *vhi, *vlo, *ohi, *olo;
    cudaGetSymbolAddress((void**)&xhi, g_xhi);
    cudaGetSymbolAddress((void**)&xlo, g_xlo);
    cudaGetSymbolAddress((void**)&wh,  g_wh);
    cudaGetSymbolAddress((void**)&qhi, g_qhi);
    cudaGetSymbolAddress((void**)&qlo, g_qlo);
    cudaGetSymbolAddress((void**)&kh,  g_kh);
    cudaGetSymbolAddress((void**)&vhi, g_vhi);
    cudaGetSymbolAddress((void**)&vlo, g_vlo);
    cudaGetSymbolAddress((void**)&ohi, g_ohi);
    cudaGetSymbolAddress((void**)&olo, g_olo);

    cudaFuncSetAttribute(gemm_qkv_fused, cudaFuncAttributeMaxDynamicSharedMemorySize, GS_SMEM);
    cudaFuncSetAttribute(gemm_out,       cudaFuncAttributeMaxDynamicSharedMemorySize, GS_SMEM);
    cudaFuncSetAttribute(attn_mma,       cudaFuncAttributeMaxDynamicSharedMemorySize, AT_SMEM);

    const int nx4 = BL_ * D_ / 4;
    const int nw4 = D_ * D_ / 4;

    split_h<<<nx4 / 256, 256>>>(x, xhi, xlo, nx4);
    split_w4<<<dim3(nw4 / 256, 4), 256>>>(Wq, Wk, Wv, Wo, wh);

    dim3 qkv_grid(D_ / 128, BL_ / 128, 3);
    gemm_qkv_fused<<<qkv_grid, 256, GS_SMEM>>>(xhi, xlo, wh, pos,
                                               qhi, qlo, kh, vhi, vlo);

    rope_k<<<(BL_ * (D_ / 2)) / 256, 256>>>(kh, pos);

    attn_mma<<<dim3(L_ / 128, H_, B_), 128, AT_SMEM>>>(qhi, qlo, kh, vhi, vlo, ohi, olo);

    dim3 ggrid(D_ / 128, BL_ / 128);
    gemm_out<<<ggrid, 256, GS_SMEM>>>(ohi, olo, wh + 3 * (size_t)D_ * D_, out);
}

// round 16
// speedup vs baseline: 1.9856x; 1.3336x over previous
#include <cuda_runtime.h>
#include <cuda_fp16.h>
#include <cstdint>

#define B_  2
#define L_  2048
#define D_  1024
#define H_  16
#define DH_ 64
#define BL_ (B_ * L_)

// ============================ helpers ============================
__device__ __forceinline__ uint32_t smem_u32(const void* p) {
    uint32_t a;
    asm("{ .reg .u64 t; cvta.to.shared.u64 t, %1; cvt.u32.u64 %0, t; }" : "=r"(a) : "l"(p));
    return a;
}
#define SMEM_SWIZZLE_128B(x) ((x) ^ (((x) >> 3) & 0x70))

// paired-row layout for 64B logical rows inside a SW128 tile (conflict-free ldmatrix)
__device__ __forceinline__ uint32_t pr64(int r, int c16) {
    uint32_t off = (uint32_t)(((r >> 1) << 7) + ((r & 1) << 6) + (c16 << 4));
    return SMEM_SWIZZLE_128B(off);
}

__device__ __forceinline__ void cp_async16(uint32_t dst, const void* src) {
    asm volatile("cp.async.ca.shared.global [%0], [%1], 16;" :: "r"(dst), "l"(src) : "memory");
}
#define CP_COMMIT() asm volatile("cp.async.commit_group;" ::: "memory")

__device__ __forceinline__ void ldm_x4(uint32_t* r, uint32_t addr) {
    asm volatile("ldmatrix.sync.aligned.m8n8.x4.shared.b16 {%0,%1,%2,%3}, [%4];"
        : "=r"(r[0]), "=r"(r[1]), "=r"(r[2]), "=r"(r[3]) : "r"(addr));
}
__device__ __forceinline__ void ldm_x4_t(uint32_t* r, uint32_t addr) {
    asm volatile("ldmatrix.sync.aligned.m8n8.x4.trans.shared.b16 {%0,%1,%2,%3}, [%4];"
        : "=r"(r[0]), "=r"(r[1]), "=r"(r[2]), "=r"(r[3]) : "r"(addr));
}

// D = A*B + D  (m16n8k16, fp16 in, fp32 accum)
__device__ __forceinline__ void mma16816h(float* c, const uint32_t* a, const uint32_t* b) {
    asm volatile("mma.sync.aligned.m16n8k16.row.col.f32.f16.f16.f32 "
        "{%0,%1,%2,%3}, {%4,%5,%6,%7}, {%8,%9}, {%0,%1,%2,%3};"
        : "+f"(c[0]), "+f"(c[1]), "+f"(c[2]), "+f"(c[3])
        : "r"(a[0]), "r"(a[1]), "r"(a[2]), "r"(a[3]), "r"(b[0]), "r"(b[1]));
}

// exp(x) for x <= 0, FMA/ALU pipes only. abs err <= ~3e-5.
__device__ __forceinline__ float exp_fast(float x) {
    float t = x * 1.44269504f;
    t = fmaxf(t, -126.0f);
    float fi = floorf(t);
    float f = t - fi;
    float r = 1.54035304e-4f;
    r = fmaf(r, f, 1.33335581e-3f);
    r = fmaf(r, f, 9.61812911e-3f);
    r = fmaf(r, f, 5.55041087e-2f);
    r = fmaf(r, f, 2.40226507e-1f);
    r = fmaf(r, f, 6.93147181e-1f);
    r = fmaf(r, f, 1.0f);
    return r * __int_as_float(((int)fi + 127) << 23);
}

__device__ __forceinline__ void hilo_pack_h(float a, float b, uint32_t& hi, uint32_t& lo) {
    __half ah = __float2half_rn(a);
    __half bh = __float2half_rn(b);
    __half al = __float2half_rn(a - __half2float(ah));
    __half bl = __float2half_rn(b - __half2float(bh));
    __half2 h2 = __halves2half2(ah, bh), l2 = __halves2half2(al, bl);
    hi = *(uint32_t*)&h2;
    lo = *(uint32_t*)&l2;
}

__device__ __forceinline__ uint32_t f2h2(float a, float b) {
    __half2 h = __floats2half2_rn(a, b);
    return *(uint32_t*)&h;
}

// ============================ scratch globals ============================
__device__ __half g_xh[BL_ * D_];        // x: single fp16
__device__ __half g_wh[4 * D_ * D_];     // weights: single fp16
__device__ __half g_qhi[BL_ * D_];
__device__ __half g_qlo[BL_ * D_];
__device__ __half g_kh[BL_ * D_];        // K: single fp16 (RoPE'd)
__device__ __half g_vh[BL_ * D_];        // V: single fp16
__device__ __half g_ohi[BL_ * D_];
__device__ __half g_olo[BL_ * D_];

__device__ const float g_invfreq[32] = {
    1.0f, 0.7498942093324559f, 0.5623413251903491f, 0.4216965034285823f,
    0.31622776601683794f, 0.2371373705661655f, 0.1778279410038923f, 0.13335214321633237f,
    0.1f, 0.07498942093324559f, 0.05623413251903491f, 0.04216965034285823f,
    0.031622776601683794f, 0.02371373705661655f, 0.01778279410038923f, 0.013335214321633237f,
    0.01f, 0.007498942093324559f, 0.005623413251903491f, 0.004216965034285823f,
    0.0031622776601683794f, 0.002371373705661655f, 0.001778279410038923f, 0.0013335214321633237f,
    0.001f, 0.0007498942093324559f, 0.0005623413251903491f, 0.0004216965034285823f,
    0.00031622776601683794f, 0.0002371373705661655f, 0.0001778279410038923f, 0.00013335214321633237f
};

// ============================ converts ============================
__global__ __launch_bounds__(256) void conv_h(const float* __restrict__ src,
                                              __half* __restrict__ dst, int n4)
{
    int i = blockIdx.x * 256 + threadIdx.x;
    if (i >= n4) return;
    float4 v = ((const float4*)src)[i];
    ((uint32_t*)dst)[2 * i + 0] = f2h2(v.x, v.y);
    ((uint32_t*)dst)[2 * i + 1] = f2h2(v.z, v.w);
}

__global__ __launch_bounds__(256) void conv_w4(const float* __restrict__ Wq,
                                               const float* __restrict__ Wk,
                                               const float* __restrict__ Wv,
                                               const float* __restrict__ Wo,
                                               __half* __restrict__ wh)
{
    const int z = blockIdx.y;
    const float* src = (z == 0) ? Wq : (z == 1) ? Wk : (z == 2) ? Wv : Wo;
    __half* dst = wh + (size_t)z * D_ * D_;
    int i = blockIdx.x * 256 + threadIdx.x;
    float4 v = ((const float4*)src)[i];
    ((uint32_t*)dst)[2 * i + 0] = f2h2(v.x, v.y);
    ((uint32_t*)dst)[2 * i + 1] = f2h2(v.z, v.w);
}

// ============================ fp16 GEMM core (1 or 2 A-products) ============
#define GS_NCHUNK 32

template<bool HASLO>
__device__ __forceinline__ void gt_fill(uint32_t base,
                                        const __half* A, const __half* Alo,
                                        const __half* W,
                                        int m0, int n0, int k0, int tid)
{
    constexpr uint32_t WOFF = HASLO ? 16384u : 8192u;
#pragma unroll
    for (int j = 0; j < 2; j++) {
        int id = tid + j * 256;
        int r  = id >> 2;
        int c  = id & 3;
        uint32_t sw = pr64(r, c);
        size_t aoff = (size_t)(m0 + r) * D_ + k0 + c * 8;
        size_t boff = (size_t)(n0 + r) * D_ + k0 + c * 8;
        cp_async16(base + 0 + sw, A + aoff);
        if (HASLO) cp_async16(base + 8192 + sw, Alo + aoff);
        cp_async16(base + WOFF + sw, W + boff);
    }
}

template<bool HASLO>
__device__ __forceinline__ void gemm_core(uint32_t sb,
                                          const __half* __restrict__ A,
                                          const __half* __restrict__ Alo,
                                          const __half* __restrict__ W,
                                          int m0, int n0, float acc[4][4][4])
{
    constexpr uint32_t STAGE = HASLO ? 24576u : 16384u;
    constexpr uint32_t WOFF  = HASLO ? 16384u : 8192u;
    const int tid = threadIdx.x;
    const int wid = tid >> 5;
    const int lid = tid & 31;
    const int wm  = wid >> 2;
    const int wn  = wid & 3;

#pragma unroll
    for (int mt = 0; mt < 4; mt++)
#pragma unroll
        for (int nt = 0; nt < 4; nt++)
#pragma unroll
            for (int r = 0; r < 4; r++) acc[mt][nt][r] = 0.0f;

    gt_fill<HASLO>(sb, A, Alo, W, m0, n0, 0, tid);
    CP_COMMIT();
    gt_fill<HASLO>(sb + STAGE, A, Alo, W, m0, n0, 32, tid);
    CP_COMMIT();

    const int a_row = (lid & 15);
    const int a_kc  = (lid >> 4);
    const int b_row = (lid & 7) + ((lid >> 4) << 3);
    const int b_kc  = (lid >> 3) & 1;

    for (int i = 0; i < GS_NCHUNK; i++) {
        if (i == GS_NCHUNK - 1) asm volatile("cp.async.wait_group 0;" ::: "memory");
        else                    asm volatile("cp.async.wait_group 1;" ::: "memory");
        __syncthreads();

        const uint32_t tb = sb + (i & 1) * STAGE;

#pragma unroll
        for (int ks = 0; ks < 2; ks++) {
            uint32_t bw[4][2];
#pragma unroll
            for (int ng = 0; ng < 2; ng++) {
                const int nrow = wn * 32 + ng * 16 + b_row;
                const uint32_t sw = pr64(nrow, ks * 2 + b_kc);
                uint32_t r[4];
                ldm_x4(r, tb + WOFF + sw);
                bw[2 * ng][0] = r[0]; bw[2 * ng][1] = r[1];
                bw[2 * ng + 1][0] = r[2]; bw[2 * ng + 1][1] = r[3];
            }
#pragma unroll
            for (int mt = 0; mt < 4; mt++) {
                const int mrow = wm * 64 + mt * 16 + a_row;
                const uint32_t sw = pr64(mrow, ks * 2 + a_kc);
                uint32_t ah[4], al[4];
                ldm_x4(ah, tb + 0 + sw);
                if (HASLO) ldm_x4(al, tb + 8192 + sw);
#pragma unroll
                for (int nt = 0; nt < 4; nt++) {
                    mma16816h(acc[mt][nt], ah, bw[nt]);
                    if (HASLO) mma16816h(acc[mt][nt], al, bw[nt]);
                }
            }
        }
        __syncthreads();

        if (i + 2 < GS_NCHUNK) {
            gt_fill<HASLO>(sb + (i & 1) * STAGE, A, Alo, W, m0, n0, (i + 2) * 32, tid);
            CP_COMMIT();
        }
    }
}

// QKV: x single fp16 -> Q (RoPE+scale, hi/lo), K (RoPE, single), V (single)
__global__ __launch_bounds__(256, 2) void gemm_qkv_fused(
    const __half* __restrict__ xh,
    const __half* __restrict__ wh,
    const int* __restrict__ pos,
    __half* __restrict__ qhi, __half* __restrict__ qlo,
    __half* __restrict__ kh,
    __half* __restrict__ vh)
{
    extern __shared__ __align__(1024) char smem[];
    uint32_t sb = smem_u32(smem);
    const int z  = blockIdx.z;
    const int m0 = blockIdx.y * 128;
    const int n0 = blockIdx.x * 128;

    float acc[4][4][4];
    gemm_core<false>(sb, xh, nullptr, wh + (size_t)z * D_ * D_, m0, n0, acc);

    const int lid = threadIdx.x & 31;
    const int wid = threadIdx.x >> 5;
    const int wm  = wid >> 2;
    const int wn  = wid & 3;

    if (z == 2) {
        // V: single fp16
#pragma unroll
        for (int mt = 0; mt < 4; mt++) {
            const int row = m0 + wm * 64 + mt * 16 + (lid >> 2);
#pragma unroll
            for (int nt = 0; nt < 4; nt++) {
                const int col = n0 + wn * 32 + nt * 8 + (lid & 3) * 2;
                size_t adr = (size_t)row * D_ + col;
                *(uint32_t*)(vh + adr) = f2h2(acc[mt][nt][0], acc[mt][nt][1]);
                adr += (size_t)8 * D_;
                *(uint32_t*)(vh + adr) = f2h2(acc[mt][nt][2], acc[mt][nt][3]);
            }
        }
        return;
    }

    // Q and K: RoPE; Q additionally scaled 0.125 and stored hi/lo
    const float scale = (z == 0) ? 0.125f : 1.0f;
#pragma unroll
    for (int mt = 0; mt < 4; mt++) {
        const int row = m0 + wm * 64 + mt * 16 + (lid >> 2);
#pragma unroll
        for (int nt = 0; nt < 4; nt++) {
            const int col = n0 + wn * 32 + nt * 8 + (lid & 3) * 2;
            float c0 = acc[mt][nt][0], c1 = acc[mt][nt][1];
            float c2 = acc[mt][nt][2], c3 = acc[mt][nt][3];
            const float invf = g_invfreq[(col & 63) >> 1];
            float s0, q0, s1, q1;
            sincosf((float)pos[row & (L_ - 1)] * invf, &s0, &q0);
            sincosf((float)pos[(row + 8) & (L_ - 1)] * invf, &s1, &q1);
            float t0 = (c0 * q0 - c1 * s0) * scale;
            float t1 = (c0 * s0 + c1 * q0) * scale;
            float t2 = (c2 * q1 - c3 * s1) * scale;
            float t3 = (c2 * s1 + c3 * q1) * scale;

            size_t adr = (size_t)row * D_ + col;
            if (z == 0) {
                uint32_t hi, lo;
                hilo_pack_h(t0, t1, hi, lo);
                *(uint32_t*)(qhi + adr) = hi;
                *(uint32_t*)(qlo + adr) = lo;
                adr += (size_t)8 * D_;
                hilo_pack_h(t2, t3, hi, lo);
                *(uint32_t*)(qhi + adr) = hi;
                *(uint32_t*)(qlo + adr) = lo;
            } else {
                *(uint32_t*)(kh + adr) = f2h2(t0, t1);
                adr += (size_t)8 * D_;
                *(uint32_t*)(kh + adr) = f2h2(t2, t3);
            }
        }
    }
}

// out GEMM: O hi/lo (2-product) x Wo single -> fp32 out
__global__ __launch_bounds__(256, 2) void gemm_out(
    const __half* __restrict__ ahi, const __half* __restrict__ alo,
    const __half* __restrict__ wh,
    float* __restrict__ C)
{
    extern __shared__ __align__(1024) char smem[];
    uint32_t sb = smem_u32(smem);
    const int m0 = blockIdx.y * 128;
    const int n0 = blockIdx.x * 128;

    float acc[4][4][4];
    gemm_core<true>(sb, ahi, alo, wh, m0, n0, acc);

    const int lid = threadIdx.x & 31;
    const int wid = threadIdx.x >> 5;
    const int wm  = wid >> 2;
    const int wn  = wid & 3;
#pragma unroll
    for (int mt = 0; mt < 4; mt++) {
        const int row = m0 + wm * 64 + mt * 16 + (lid >> 2);
#pragma unroll
        for (int nt = 0; nt < 4; nt++) {
            const int col = n0 + wn * 32 + nt * 8 + (lid & 3) * 2;
            *(float2*)&C[(size_t)row * D_ + col]       = make_float2(acc[mt][nt][0], acc[mt][nt][1]);
            *(float2*)&C[(size_t)(row + 8) * D_ + col] = make_float2(acc[mt][nt][2], acc[mt][nt][3]);
        }
    }
}

// ============================ paired-tile attention (all-fp16 operands) ==========
// smem: Qa hi/lo + Qb hi/lo (32K) | 2 x KV stage (K 8K + V 8K = 16K each) = 64K total
#define AT_KV0   32768
#define AT_STAGE 16384
#define AT_SMEM  (AT_KV0 + 2 * AT_STAGE)

__device__ __forceinline__ void at_fill(uint32_t sb, int stage, size_t gbase, int k0,
                                        const __half* kh, const __half* vh, int tid)
{
    uint32_t kb = sb + AT_KV0 + stage * AT_STAGE;
#pragma unroll
    for (int j = 0; j < 4; j++) {
        int id = tid + j * 128;
        int r  = id >> 3;
        int c  = id & 7;
        uint32_t sw = SMEM_SWIZZLE_128B((uint32_t)(r * 128 + c * 16));
        size_t off = gbase + (size_t)(k0 + r) * D_ + c * 8;
        cp_async16(kb + 0    + sw, kh + off);
        cp_async16(kb + 8192 + sw, vh + off);
    }
}

__device__ __forceinline__ void attn_step(uint32_t kb,
                                          const uint32_t (&qh)[4][4], const uint32_t (&ql)[4][4],
                                          float (&o)[8][4], float (&m_run)[2], float (&l_run)[2],
                                          bool diag, int wid, int lid)
{
    const int brow = (lid & 7) + ((lid >> 4) << 3);
    const int bkc  = (lid >> 3) & 1;
    const int vrow = lid & 15;
    const int vcol = (lid >> 4) << 3;

    float s[8][4];
#pragma unroll
    for (int j = 0; j < 8; j++)
#pragma unroll
        for (int r = 0; r < 4; r++) s[j][r] = 0.0f;

#pragma unroll
    for (int ks = 0; ks < 4; ks++) {
#pragma unroll
        for (int ng = 0; ng < 4; ng++) {
            uint32_t sw = SMEM_SWIZZLE_128B(
                (uint32_t)((ng * 16 + brow) * 128 + (ks * 2 + bkc) * 16));
            uint32_t kh4[4];
            ldm_x4(kh4, kb + 0 + sw);
            mma16816h(s[ng * 2],     qh[ks], kh4 + 0);
            mma16816h(s[ng * 2],     ql[ks], kh4 + 0);
            mma16816h(s[ng * 2 + 1], qh[ks], kh4 + 2);
            mma16816h(s[ng * 2 + 1], ql[ks], kh4 + 2);
        }
    }

    if (diag) {
        const int rlo = wid * 16 + (lid >> 2);
#pragma unroll
        for (int j = 0; j < 8; j++) {
            const int cb = ((j >> 1) << 4) + ((j & 1) << 3) + ((lid & 3) << 1);
            if (cb     > rlo)     s[j][0] = -1e30f;
            if (cb + 1 > rlo)     s[j][1] = -1e30f;
            if (cb     > rlo + 8) s[j][2] = -1e30f;
            if (cb + 1 > rlo + 8) s[j][3] = -1e30f;
        }
    }

    float mx0 = -1e30f, mx1 = -1e30f;
#pragma unroll
    for (int j = 0; j < 8; j++) {
        mx0 = fmaxf(mx0, fmaxf(s[j][0], s[j][1]));
        mx1 = fmaxf(mx1, fmaxf(s[j][2], s[j][3]));
    }
    mx0 = fmaxf(mx0, __shfl_xor_sync(0xffffffffu, mx0, 1));
    mx0 = fmaxf(mx0, __shfl_xor_sync(0xffffffffu, mx0, 2));
    mx1 = fmaxf(mx1, __shfl_xor_sync(0xffffffffu, mx1, 1));
    mx1 = fmaxf(mx1, __shfl_xor_sync(0xffffffffu, mx1, 2));
    const float mn0 = fmaxf(m_run[0], mx0);
    const float mn1 = fmaxf(m_run[1], mx1);
    const float cr0 = exp_fast(m_run[0] - mn0);
    const float cr1 = exp_fast(m_run[1] - mn1);
    m_run[0] = mn0; m_run[1] = mn1;

    float ps0 = 0.0f, ps1 = 0.0f;
#pragma unroll
    for (int j = 0; j < 8; j++) {
        s[j][0] = exp_fast(s[j][0] - mn0); ps0 += s[j][0];
        s[j][1] = exp_fast(s[j][1] - mn0); ps0 += s[j][1];
        s[j][2] = exp_fast(s[j][2] - mn1); ps1 += s[j][2];
        s[j][3] = exp_fast(s[j][3] - mn1); ps1 += s[j][3];
    }
    ps0 += __shfl_xor_sync(0xffffffffu, ps0, 1);
    ps0 += __shfl_xor_sync(0xffffffffu, ps0, 2);
    ps1 += __shfl_xor_sync(0xffffffffu, ps1, 1);
    ps1 += __shfl_xor_sync(0xffffffffu, ps1, 2);
    l_run[0] = l_run[0] * cr0 + ps0;
    l_run[1] = l_run[1] * cr1 + ps1;

#pragma unroll
    for (int j = 0; j < 8; j++) {
        o[j][0] *= cr0; o[j][1] *= cr0;
        o[j][2] *= cr1; o[j][3] *= cr1;
    }

    uint32_t ph[4][4];
#pragma unroll
    for (int kc = 0; kc < 4; kc++) {
        ph[kc][0] = f2h2(s[2 * kc][0],     s[2 * kc][1]);
        ph[kc][1] = f2h2(s[2 * kc][2],     s[2 * kc][3]);
        ph[kc][2] = f2h2(s[2 * kc + 1][0], s[2 * kc + 1][1]);
        ph[kc][3] = f2h2(s[2 * kc + 1][2], s[2 * kc + 1][3]);
    }

    const uint32_t vb = kb + 8192;
#pragma unroll
    for (int kc = 0; kc < 4; kc++) {
#pragma unroll
        for (int nd = 0; nd < 4; nd++) {
            uint32_t sw = SMEM_SWIZZLE_128B(
                (uint32_t)((kc * 16 + vrow) * 128 + (nd * 16 + vcol) * 2));
            uint32_t vh4[4];
            ldm_x4_t(vh4, vb + sw);
            mma16816h(o[nd * 2],     ph[kc], vh4 + 0);
            mma16816h(o[nd * 2 + 1], ph[kc], vh4 + 2);
        }
    }
}

__device__ __forceinline__ void attn_epilogue(const float (&o)[8][4],
                                              const float (&l_run)[2],
                                              size_t gbase, int q0, int wid, int lid,
                                              __half* ohi, __half* olo)
{
    const float inv0 = 1.0f / l_run[0];
    const float inv1 = 1.0f / l_run[1];
    const int rlo = q0 + wid * 16 + (lid >> 2);
#pragma unroll
    for (int j = 0; j < 8; j++) {
        const int col = ((j >> 1) << 4) + ((j & 1) << 3) + ((lid & 3) << 1);
        uint32_t hi, lo;
        size_t adr0 = gbase + (size_t)rlo * D_ + col;
        hilo_pack_h(o[j][0] * inv0, o[j][1] * inv0, hi, lo);
        *(uint32_t*)(ohi + adr0) = hi;
        *(uint32_t*)(olo + adr0) = lo;
        size_t adr1 = adr0 + (size_t)8 * D_;
        hilo_pack_h(o[j][2] * inv1, o[j][3] * inv1, hi, lo);
        *(uint32_t*)(ohi + adr1) = hi;
        *(uint32_t*)(olo + adr1) = lo;
    }
}

__global__ __launch_bounds__(128) void attn_mma(const __half* __restrict__ qhi,
                                                const __half* __restrict__ qlo,
                                                const __half* __restrict__ kh,
                                                const __half* __restrict__ vh,
                                                __half* __restrict__ ohi,
                                                __half* __restrict__ olo)
{
    extern __shared__ __align__(1024) char smem[];
    uint32_t sb = smem_u32(smem);
    const int tid = threadIdx.x;
    const int wid = tid >> 5;
    const int lid = tid & 31;
    const int p   = blockIdx.x;           // pair id: tiles p and 31-p
    const int qta = p;
    const int qtb = (L_ / 64 - 1) - p;
    const int h   = blockIdx.y;
    const int b   = blockIdx.z;
    const size_t gbase = (size_t)(b * L_) * D_ + h * DH_;

#pragma unroll
    for (int j = 0; j < 4; j++) {
        int id = tid + j * 128;
        int r  = id >> 3;
        int c  = id & 7;
        uint32_t sw = SMEM_SWIZZLE_128B((uint32_t)(r * 128 + c * 16));
        size_t offa = gbase + (size_t)(qta * 64 + r) * D_ + c * 8;
        size_t offb = gbase + (size_t)(qtb * 64 + r) * D_ + c * 8;
        cp_async16(sb + 0     + sw, qhi + offa);
        cp_async16(sb + 8192  + sw, qlo + offa);
        cp_async16(sb + 16384 + sw, qhi + offb);
        cp_async16(sb + 24576 + sw, qlo + offb);
    }
    CP_COMMIT();
    at_fill(sb, 0, gbase, 0, kh, vh, tid);
    CP_COMMIT();
    asm volatile("cp.async.wait_group 0;" ::: "memory");
    __syncthreads();

    uint32_t qhA[4][4], qlA[4][4], qhB[4][4], qlB[4][4];
    {
        const int arow = wid * 16 + (lid & 15);
        const int akc  = lid >> 4;
#pragma unroll
        for (int ks = 0; ks < 4; ks++) {
            uint32_t sw = SMEM_SWIZZLE_128B((uint32_t)(arow * 128 + (ks * 2 + akc) * 16));
            ldm_x4(qhA[ks], sb + 0 + sw);
            ldm_x4(qlA[ks], sb + 8192 + sw);
            ldm_x4(qhB[ks], sb + 16384 + sw);
            ldm_x4(qlB[ks], sb + 24576 + sw);
        }
    }

    float mA[2] = {-1e30f, -1e30f}, lA[2] = {0.0f, 0.0f};
    float mB[2] = {-1e30f, -1e30f}, lB[2] = {0.0f, 0.0f};
    float oA[8][4], oB[8][4];
#pragma unroll
    for (int j = 0; j < 8; j++)
#pragma unroll
        for (int r = 0; r < 4; r++) { oA[j][r] = 0.0f; oB[j][r] = 0.0f; }

    const int nkt = qtb + 1;
    for (int kt = 0; kt < nkt; kt++) {
        __syncthreads();
        if (kt + 1 < nkt) {
            at_fill(sb, (kt + 1) & 1, gbase, (kt + 1) * 64, kh, vh, tid);
            CP_COMMIT();
            asm volatile("cp.async.wait_group 1;" ::: "memory");
        } else {
            asm volatile("cp.async.wait_group 0;" ::: "memory");
        }
        __syncthreads();

        const uint32_t kb = sb + AT_KV0 + (kt & 1) * AT_STAGE;

        if (kt <= qta)
            attn_step(kb, qhA, qlA, oA, mA, lA, kt == qta, wid, lid);
        attn_step(kb, qhB, qlB, oB, mB, lB, kt == qtb, wid, lid);
    }

    attn_epilogue(oA, lA, gbase, qta * 64, wid, lid, ohi, olo);
    attn_epilogue(oB, lB, gbase, qtb * 64, wid, lid, ohi, olo);
}

// ============================ launch ============================
extern "C" void kernel_launch(void* const* d_in, const int* in_sizes, int n_in,
                              void* d_out, int out_size)
{
    const float* x   = (const float*)d_in[0];
    const float* Wq  = (const float*)d_in[1];
    const float* Wk  = (const float*)d_in[2];
    const float* Wv  = (const float*)d_in[3];
    const float* Wo  = (const float*)d_in[4];
    const int*   pos = (const int*)  d_in[5];
    float* out = (float*)d_out;

    __half *xh, *wh, *qhi, *qlo, *kh, *vh, *ohi, *olo;
    cudaGetSymbolAddress((void**)&xh,  g_xh);
    cudaGetSymbolAddress((void**)&wh,  g_wh);
    cudaGetSymbolAddress((void**)&qhi, g_qhi);
    cudaGetSymbolAddress((void**)&qlo, g_qlo);
    cudaGetSymbolAddress((void**)&kh,  g_kh);
    cudaGetSymbolAddress((void**)&vh,  g_vh);
    cudaGetSymbolAddress((void**)&ohi, g_ohi);
    cudaGetSymbolAddress((void**)&olo, g_olo);

    cudaFuncSetAttribute(gemm_qkv_fused, cudaFuncAttributeMaxDynamicSharedMemorySize, 2 * 16384);
    cudaFuncSetAttribute(gemm_out,       cudaFuncAttributeMaxDynamicSharedMemorySize, 2 * 24576);
    cudaFuncSetAttribute(attn_mma,       cudaFuncAttributeMaxDynamicSharedMemorySize, AT_SMEM);

    const int nx4 = BL_ * D_ / 4;
    const int nw4 = D_ * D_ / 4;

    conv_h<<<nx4 / 256, 256>>>(x, xh, nx4);
    conv_w4<<<dim3(nw4 / 256, 4), 256>>>(Wq, Wk, Wv, Wo, wh);

    dim3 qkv_grid(D_ / 128, BL_ / 128, 3);
    gemm_qkv_fused<<<qkv_grid, 256, 2 * 16384>>>(xh, wh, pos, qhi, qlo, kh, vh);

    attn_mma<<<dim3(L_ / 128, H_, B_), 128, AT_SMEM>>>(qhi, qlo, kh, vh, ohi, olo);

    dim3 ggrid(D_ / 128, BL_ / 128);
    gemm_out<<<ggrid, 256, 2 * 24576>>>(ohi, olo, wh + 3 * (size_t)D_ * D_, out);
}

// round 17
// speedup vs baseline: 2.1678x; 1.0917x over previous
#include <cuda_runtime.h>
#include <cuda_fp16.h>
#include <cstdint>

#define B_  2
#define L_  2048
#define D_  1024
#define H_  16
#define DH_ 64
#define BL_ (B_ * L_)

// ============================ helpers ============================
__device__ __forceinline__ uint32_t smem_u32(const void* p) {
    uint32_t a;
    asm("{ .reg .u64 t; cvta.to.shared.u64 t, %1; cvt.u32.u64 %0, t; }" : "=r"(a) : "l"(p));
    return a;
}
#define SMEM_SWIZZLE_128B(x) ((x) ^ (((x) >> 3) & 0x70))

// paired-row layout for 64B logical rows inside a SW128 tile (conflict-free ldmatrix)
__device__ __forceinline__ uint32_t pr64(int r, int c16) {
    uint32_t off = (uint32_t)(((r >> 1) << 7) + ((r & 1) << 6) + (c16 << 4));
    return SMEM_SWIZZLE_128B(off);
}

__device__ __forceinline__ void cp_async16(uint32_t dst, const void* src) {
    asm volatile("cp.async.ca.shared.global [%0], [%1], 16;" :: "r"(dst), "l"(src) : "memory");
}
#define CP_COMMIT() asm volatile("cp.async.commit_group;" ::: "memory")

__device__ __forceinline__ void ldm_x4(uint32_t* r, uint32_t addr) {
    asm volatile("ldmatrix.sync.aligned.m8n8.x4.shared.b16 {%0,%1,%2,%3}, [%4];"
        : "=r"(r[0]), "=r"(r[1]), "=r"(r[2]), "=r"(r[3]) : "r"(addr));
}
__device__ __forceinline__ void ldm_x4_t(uint32_t* r, uint32_t addr) {
    asm volatile("ldmatrix.sync.aligned.m8n8.x4.trans.shared.b16 {%0,%1,%2,%3}, [%4];"
        : "=r"(r[0]), "=r"(r[1]), "=r"(r[2]), "=r"(r[3]) : "r"(addr));
}

// D = A*B + D  (m16n8k16, fp16 in, fp32 accum)
__device__ __forceinline__ void mma16816h(float* c, const uint32_t* a, const uint32_t* b) {
    asm volatile("mma.sync.aligned.m16n8k16.row.col.f32.f16.f16.f32 "
        "{%0,%1,%2,%3}, {%4,%5,%6,%7}, {%8,%9}, {%0,%1,%2,%3};"
        : "+f"(c[0]), "+f"(c[1]), "+f"(c[2]), "+f"(c[3])
        : "r"(a[0]), "r"(a[1]), "r"(a[2]), "r"(a[3]), "r"(b[0]), "r"(b[1]));
}

// exp(x) for x <= 0, FMA/ALU pipes only. abs err <= ~3e-5.
__device__ __forceinline__ float exp_fast(float x) {
    float t = x * 1.44269504f;
    t = fmaxf(t, -126.0f);
    float fi = floorf(t);
    float f = t - fi;
    float r = 1.54035304e-4f;
    r = fmaf(r, f, 1.33335581e-3f);
    r = fmaf(r, f, 9.61812911e-3f);
    r = fmaf(r, f, 5.55041087e-2f);
    r = fmaf(r, f, 2.40226507e-1f);
    r = fmaf(r, f, 6.93147181e-1f);
    r = fmaf(r, f, 1.0f);
    return r * __int_as_float(((int)fi + 127) << 23);
}

__device__ __forceinline__ uint32_t f2h2(float a, float b) {
    __half2 h = __floats2half2_rn(a, b);
    return *(uint32_t*)&h;
}

// ============================ scratch globals ============================
__device__ __half g_xh[BL_ * D_];        // x: single fp16
__device__ __half g_wh[4 * D_ * D_];     // weights: single fp16
__device__ __half g_qh[BL_ * D_];        // Q: single fp16 (RoPE'd, scaled)
__device__ __half g_kh[BL_ * D_];        // K: single fp16 (RoPE'd)
__device__ __half g_vh[BL_ * D_];        // V: single fp16
__device__ __half g_oh[BL_ * D_];        // O: single fp16

__device__ const float g_invfreq[32] = {
    1.0f, 0.7498942093324559f, 0.5623413251903491f, 0.4216965034285823f,
    0.31622776601683794f, 0.2371373705661655f, 0.1778279410038923f, 0.13335214321633237f,
    0.1f, 0.07498942093324559f, 0.05623413251903491f, 0.04216965034285823f,
    0.031622776601683794f, 0.02371373705661655f, 0.01778279410038923f, 0.013335214321633237f,
    0.01f, 0.007498942093324559f, 0.005623413251903491f, 0.004216965034285823f,
    0.0031622776601683794f, 0.002371373705661655f, 0.001778279410038923f, 0.0013335214321633237f,
    0.001f, 0.0007498942093324559f, 0.0005623413251903491f, 0.0004216965034285823f,
    0.00031622776601683794f, 0.0002371373705661655f, 0.0001778279410038923f, 0.00013335214321633237f
};

// ============================ converts ============================
__global__ __launch_bounds__(256) void conv_h(const float* __restrict__ src,
                                              __half* __restrict__ dst, int n4)
{
    int i = blockIdx.x * 256 + threadIdx.x;
    if (i >= n4) return;
    float4 v = ((const float4*)src)[i];
    ((uint32_t*)dst)[2 * i + 0] = f2h2(v.x, v.y);
    ((uint32_t*)dst)[2 * i + 1] = f2h2(v.z, v.w);
}

__global__ __launch_bounds__(256) void conv_w4(const float* __restrict__ Wq,
                                               const float* __restrict__ Wk,
                                               const float* __restrict__ Wv,
                                               const float* __restrict__ Wo,
                                               __half* __restrict__ wh)
{
    const int z = blockIdx.y;
    const float* src = (z == 0) ? Wq : (z == 1) ? Wk : (z == 2) ? Wv : Wo;
    __half* dst = wh + (size_t)z * D_ * D_;
    int i = blockIdx.x * 256 + threadIdx.x;
    float4 v = ((const float4*)src)[i];
    ((uint32_t*)dst)[2 * i + 0] = f2h2(v.x, v.y);
    ((uint32_t*)dst)[2 * i + 1] = f2h2(v.z, v.w);
}

// ============================ fp16 1-product GEMM core ============
#define GS_STAGE 16384
#define GS_SMEM  (2 * GS_STAGE)
#define GS_NCHUNK 32

__device__ __forceinline__ void gt_fill(uint32_t base,
                                        const __half* A, const __half* W,
                                        int m0, int n0, int k0, int tid)
{
#pragma unroll
    for (int j = 0; j < 2; j++) {
        int id = tid + j * 256;
        int r  = id >> 2;
        int c  = id & 3;
        uint32_t sw = pr64(r, c);
        cp_async16(base + 0    + sw, A + (size_t)(m0 + r) * D_ + k0 + c * 8);
        cp_async16(base + 8192 + sw, W + (size_t)(n0 + r) * D_ + k0 + c * 8);
    }
}

__device__ __forceinline__ void gemm_core(uint32_t sb,
                                          const __half* __restrict__ A,
                                          const __half* __restrict__ W,
                                          int m0, int n0, float acc[4][4][4])
{
    const int tid = threadIdx.x;
    const int wid = tid >> 5;
    const int lid = tid & 31;
    const int wm  = wid >> 2;
    const int wn  = wid & 3;

#pragma unroll
    for (int mt = 0; mt < 4; mt++)
#pragma unroll
        for (int nt = 0; nt < 4; nt++)
#pragma unroll
            for (int r = 0; r < 4; r++) acc[mt][nt][r] = 0.0f;

    gt_fill(sb, A, W, m0, n0, 0, tid);
    CP_COMMIT();
    gt_fill(sb + GS_STAGE, A, W, m0, n0, 32, tid);
    CP_COMMIT();

    const int a_row = (lid & 15);
    const int a_kc  = (lid >> 4);
    const int b_row = (lid & 7) + ((lid >> 4) << 3);
    const int b_kc  = (lid >> 3) & 1;

    for (int i = 0; i < GS_NCHUNK; i++) {
        if (i == GS_NCHUNK - 1) asm volatile("cp.async.wait_group 0;" ::: "memory");
        else                    asm volatile("cp.async.wait_group 1;" ::: "memory");
        __syncthreads();

        const uint32_t tb = sb + (i & 1) * GS_STAGE;

#pragma unroll
        for (int ks = 0; ks < 2; ks++) {
            uint32_t bw[4][2];
#pragma unroll
            for (int ng = 0; ng < 2; ng++) {
                const int nrow = wn * 32 + ng * 16 + b_row;
                const uint32_t sw = pr64(nrow, ks * 2 + b_kc);
                uint32_t r[4];
                ldm_x4(r, tb + 8192 + sw);
                bw[2 * ng][0] = r[0]; bw[2 * ng][1] = r[1];
                bw[2 * ng + 1][0] = r[2]; bw[2 * ng + 1][1] = r[3];
            }
#pragma unroll
            for (int mt = 0; mt < 4; mt++) {
                const int mrow = wm * 64 + mt * 16 + a_row;
                const uint32_t sw = pr64(mrow, ks * 2 + a_kc);
                uint32_t ah[4];
                ldm_x4(ah, tb + 0 + sw);
#pragma unroll
                for (int nt = 0; nt < 4; nt++)
                    mma16816h(acc[mt][nt], ah, bw[nt]);
            }
        }
        __syncthreads();

        if (i + 2 < GS_NCHUNK) {
            gt_fill(sb + (i & 1) * GS_STAGE, A, W, m0, n0, (i + 2) * 32, tid);
            CP_COMMIT();
        }
    }
}

// QKV: x single fp16 -> Q (RoPE+scale), K (RoPE), V — all single fp16
__global__ __launch_bounds__(256, 2) void gemm_qkv_fused(
    const __half* __restrict__ xh,
    const __half* __restrict__ wh,
    const int* __restrict__ pos,
    __half* __restrict__ qh,
    __half* __restrict__ kh,
    __half* __restrict__ vh)
{
    extern __shared__ __align__(1024) char smem[];
    uint32_t sb = smem_u32(smem);
    const int z  = blockIdx.z;
    const int m0 = blockIdx.y * 128;
    const int n0 = blockIdx.x * 128;

    float acc[4][4][4];
    gemm_core(sb, xh, wh + (size_t)z * D_ * D_, m0, n0, acc);

    const int lid = threadIdx.x & 31;
    const int wid = threadIdx.x >> 5;
    const int wm  = wid >> 2;
    const int wn  = wid & 3;

    if (z == 2) {
#pragma unroll
        for (int mt = 0; mt < 4; mt++) {
            const int row = m0 + wm * 64 + mt * 16 + (lid >> 2);
#pragma unroll
            for (int nt = 0; nt < 4; nt++) {
                const int col = n0 + wn * 32 + nt * 8 + (lid & 3) * 2;
                size_t adr = (size_t)row * D_ + col;
                *(uint32_t*)(vh + adr) = f2h2(acc[mt][nt][0], acc[mt][nt][1]);
                adr += (size_t)8 * D_;
                *(uint32_t*)(vh + adr) = f2h2(acc[mt][nt][2], acc[mt][nt][3]);
            }
        }
        return;
    }

    __half* dst = (z == 0) ? qh : kh;
    const float scale = (z == 0) ? 0.125f : 1.0f;
#pragma unroll
    for (int mt = 0; mt < 4; mt++) {
        const int row = m0 + wm * 64 + mt * 16 + (lid >> 2);
#pragma unroll
        for (int nt = 0; nt < 4; nt++) {
            const int col = n0 + wn * 32 + nt * 8 + (lid & 3) * 2;
            float c0 = acc[mt][nt][0], c1 = acc[mt][nt][1];
            float c2 = acc[mt][nt][2], c3 = acc[mt][nt][3];
            const float invf = g_invfreq[(col & 63) >> 1];
            float s0, q0, s1, q1;
            sincosf((float)pos[row & (L_ - 1)] * invf, &s0, &q0);
            sincosf((float)pos[(row + 8) & (L_ - 1)] * invf, &s1, &q1);
            float t0 = (c0 * q0 - c1 * s0) * scale;
            float t1 = (c0 * s0 + c1 * q0) * scale;
            float t2 = (c2 * q1 - c3 * s1) * scale;
            float t3 = (c2 * s1 + c3 * q1) * scale;

            size_t adr = (size_t)row * D_ + col;
            *(uint32_t*)(dst + adr) = f2h2(t0, t1);
            adr += (size_t)8 * D_;
            *(uint32_t*)(dst + adr) = f2h2(t2, t3);
        }
    }
}

// out GEMM: O single fp16 x Wo single fp16 -> fp32 out
__global__ __launch_bounds__(256, 2) void gemm_out(
    const __half* __restrict__ oh,
    const __half* __restrict__ wh,
    float* __restrict__ C)
{
    extern __shared__ __align__(1024) char smem[];
    uint32_t sb = smem_u32(smem);
    const int m0 = blockIdx.y * 128;
    const int n0 = blockIdx.x * 128;

    float acc[4][4][4];
    gemm_core(sb, oh, wh, m0, n0, acc);

    const int lid = threadIdx.x & 31;
    const int wid = threadIdx.x >> 5;
    const int wm  = wid >> 2;
    const int wn  = wid & 3;
#pragma unroll
    for (int mt = 0; mt < 4; mt++) {
        const int row = m0 + wm * 64 + mt * 16 + (lid >> 2);
#pragma unroll
        for (int nt = 0; nt < 4; nt++) {
            const int col = n0 + wn * 32 + nt * 8 + (lid & 3) * 2;
            *(float2*)&C[(size_t)row * D_ + col]       = make_float2(acc[mt][nt][0], acc[mt][nt][1]);
            *(float2*)&C[(size_t)(row + 8) * D_ + col] = make_float2(acc[mt][nt][2], acc[mt][nt][3]);
        }
    }
}

// ============================ paired-tile attention (all single fp16) ==========
// smem: Qa(8K) Qb(8K) | 2 x KV stage (K 8K + V 8K) = 48K total
#define AT_KV0   16384
#define AT_STAGE 16384
#define AT_SMEM  (AT_KV0 + 2 * AT_STAGE)

__device__ __forceinline__ void at_fill(uint32_t sb, int stage, size_t gbase, int k0,
                                        const __half* kh, const __half* vh, int tid)
{
    uint32_t kb = sb + AT_KV0 + stage * AT_STAGE;
#pragma unroll
    for (int j = 0; j < 4; j++) {
        int id = tid + j * 128;
        int r  = id >> 3;
        int c  = id & 7;
        uint32_t sw = SMEM_SWIZZLE_128B((uint32_t)(r * 128 + c * 16));
        size_t off = gbase + (size_t)(k0 + r) * D_ + c * 8;
        cp_async16(kb + 0    + sw, kh + off);
        cp_async16(kb + 8192 + sw, vh + off);
    }
}

__device__ __forceinline__ void attn_step(uint32_t kb,
                                          const uint32_t (&qh)[4][4],
                                          float (&o)[8][4], float (&m_run)[2], float (&l_run)[2],
                                          bool diag, int wid, int lid)
{
    const int brow = (lid & 7) + ((lid >> 4) << 3);
    const int bkc  = (lid >> 3) & 1;
    const int vrow = lid & 15;
    const int vcol = (lid >> 4) << 3;

    float s[8][4];
#pragma unroll
    for (int j = 0; j < 8; j++)
#pragma unroll
        for (int r = 0; r < 4; r++) s[j][r] = 0.0f;

#pragma unroll
    for (int ks = 0; ks < 4; ks++) {
#pragma unroll
        for (int ng = 0; ng < 4; ng++) {
            uint32_t sw = SMEM_SWIZZLE_128B(
                (uint32_t)((ng * 16 + brow) * 128 + (ks * 2 + bkc) * 16));
            uint32_t kh4[4];
            ldm_x4(kh4, kb + 0 + sw);
            mma16816h(s[ng * 2],     qh[ks], kh4 + 0);
            mma16816h(s[ng * 2 + 1], qh[ks], kh4 + 2);
        }
    }

    if (diag) {
        const int rlo = wid * 16 + (lid >> 2);
#pragma unroll
        for (int j = 0; j < 8; j++) {
            const int cb = ((j >> 1) << 4) + ((j & 1) << 3) + ((lid & 3) << 1);
            if (cb     > rlo)     s[j][0] = -1e30f;
            if (cb + 1 > rlo)     s[j][1] = -1e30f;
            if (cb     > rlo + 8) s[j][2] = -1e30f;
            if (cb + 1 > rlo + 8) s[j][3] = -1e30f;
        }
    }

    float mx0 = -1e30f, mx1 = -1e30f;
#pragma unroll
    for (int j = 0; j < 8; j++) {
        mx0 = fmaxf(mx0, fmaxf(s[j][0], s[j][1]));
        mx1 = fmaxf(mx1, fmaxf(s[j][2], s[j][3]));
    }
    mx0 = fmaxf(mx0, __shfl_xor_sync(0xffffffffu, mx0, 1));
    mx0 = fmaxf(mx0, __shfl_xor_sync(0xffffffffu, mx0, 2));
    mx1 = fmaxf(mx1, __shfl_xor_sync(0xffffffffu, mx1, 1));
    mx1 = fmaxf(mx1, __shfl_xor_sync(0xffffffffu, mx1, 2));
    const float mn0 = fmaxf(m_run[0], mx0);
    const float mn1 = fmaxf(m_run[1], mx1);
    const float cr0 = exp_fast(m_run[0] - mn0);
    const float cr1 = exp_fast(m_run[1] - mn1);
    m_run[0] = mn0; m_run[1] = mn1;

    float ps0 = 0.0f, ps1 = 0.0f;
#pragma unroll
    for (int j = 0; j < 8; j++) {
        s[j][0] = exp_fast(s[j][0] - mn0); ps0 += s[j][0];
        s[j][1] = exp_fast(s[j][1] - mn0); ps0 += s[j][1];
        s[j][2] = exp_fast(s[j][2] - mn1); ps1 += s[j][2];
        s[j][3] = exp_fast(s[j][3] - mn1); ps1 += s[j][3];
    }
    ps0 += __shfl_xor_sync(0xffffffffu, ps0, 1);
    ps0 += __shfl_xor_sync(0xffffffffu, ps0, 2);
    ps1 += __shfl_xor_sync(0xffffffffu, ps1, 1);
    ps1 += __shfl_xor_sync(0xffffffffu, ps1, 2);
    l_run[0] = l_run[0] * cr0 + ps0;
    l_run[1] = l_run[1] * cr1 + ps1;

#pragma unroll
    for (int j = 0; j < 8; j++) {
        o[j][0] *= cr0; o[j][1] *= cr0;
        o[j][2] *= cr1; o[j][3] *= cr1;
    }

    uint32_t ph[4][4];
#pragma unroll
    for (int kc = 0; kc < 4; kc++) {
        ph[kc][0] = f2h2(s[2 * kc][0],     s[2 * kc][1]);
        ph[kc][1] = f2h2(s[2 * kc][2],     s[2 * kc][3]);
        ph[kc][2] = f2h2(s[2 * kc + 1][0], s[2 * kc + 1][1]);
        ph[kc][3] = f2h2(s[2 * kc + 1][2], s[2 * kc + 1][3]);
    }

    const uint32_t vb = kb + 8192;
#pragma unroll
    for (int kc = 0; kc < 4; kc++) {
#pragma unroll
        for (int nd = 0; nd < 4; nd++) {
            uint32_t sw = SMEM_SWIZZLE_128B(
                (uint32_t)((kc * 16 + vrow) * 128 + (nd * 16 + vcol) * 2));
            uint32_t vh4[4];
            ldm_x4_t(vh4, vb + sw);
            mma16816h(o[nd * 2],     ph[kc], vh4 + 0);
            mma16816h(o[nd * 2 + 1], ph[kc], vh4 + 2);
        }
    }
}

__device__ __forceinline__ void attn_epilogue(const float (&o)[8][4],
                                              const float (&l_run)[2],
                                              size_t gbase, int q0, int wid, int lid,
                                              __half* oh)
{
    const float inv0 = 1.0f / l_run[0];
    const float inv1 = 1.0f / l_run[1];
    const int rlo = q0 + wid * 16 + (lid >> 2);
#pragma unroll
    for (int j = 0; j < 8; j++) {
        const int col = ((j >> 1) << 4) + ((j & 1) << 3) + ((lid & 3) << 1);
        size_t adr0 = gbase + (size_t)rlo * D_ + col;
        *(uint32_t*)(oh + adr0) = f2h2(o[j][0] * inv0, o[j][1] * inv0);
        size_t adr1 = adr0 + (size_t)8 * D_;
        *(uint32_t*)(oh + adr1) = f2h2(o[j][2] * inv1, o[j][3] * inv1);
    }
}

__global__ __launch_bounds__(128) void attn_mma(const __half* __restrict__ qh,
                                                const __half* __restrict__ kh,
                                                const __half* __restrict__ vh,
                                                __half* __restrict__ oh)
{
    extern __shared__ __align__(1024) char smem[];
    uint32_t sb = smem_u32(smem);
    const int tid = threadIdx.x;
    const int wid = tid >> 5;
    const int lid = tid & 31;
    const int p   = blockIdx.x;           // pair id: tiles p and 31-p
    const int qta = p;
    const int qtb = (L_ / 64 - 1) - p;
    const int h   = blockIdx.y;
    const int b   = blockIdx.z;
    const size_t gbase = (size_t)(b * L_) * D_ + h * DH_;

#pragma unroll
    for (int j = 0; j < 4; j++) {
        int id = tid + j * 128;
        int r  = id >> 3;
        int c  = id & 7;
        uint32_t sw = SMEM_SWIZZLE_128B((uint32_t)(r * 128 + c * 16));
        cp_async16(sb + 0    + sw, qh + gbase + (size_t)(qta * 64 + r) * D_ + c * 8);
        cp_async16(sb + 8192 + sw, qh + gbase + (size_t)(qtb * 64 + r) * D_ + c * 8);
    }
    CP_COMMIT();
    at_fill(sb, 0, gbase, 0, kh, vh, tid);
    CP_COMMIT();
    asm volatile("cp.async.wait_group 0;" ::: "memory");
    __syncthreads();

    uint32_t qhA[4][4], qhB[4][4];
    {
        const int arow = wid * 16 + (lid & 15);
        const int akc  = lid >> 4;
#pragma unroll
        for (int ks = 0; ks < 4; ks++) {
            uint32_t sw = SMEM_SWIZZLE_128B((uint32_t)(arow * 128 + (ks * 2 + akc) * 16));
            ldm_x4(qhA[ks], sb + 0 + sw);
            ldm_x4(qhB[ks], sb + 8192 + sw);
        }
    }

    float mA[2] = {-1e30f, -1e30f}, lA[2] = {0.0f, 0.0f};
    float mB[2] = {-1e30f, -1e30f}, lB[2] = {0.0f, 0.0f};
    float oA[8][4], oB[8][4];
#pragma unroll
    for (int j = 0; j < 8; j++)
#pragma unroll
        for (int r = 0; r < 4; r++) { oA[j][r] = 0.0f; oB[j][r] = 0.0f; }

    const int nkt = qtb + 1;
    for (int kt = 0; kt < nkt; kt++) {
        __syncthreads();
        if (kt + 1 < nkt) {
            at_fill(sb, (kt + 1) & 1, gbase, (kt + 1) * 64, kh, vh, tid);
            CP_COMMIT();
            asm volatile("cp.async.wait_group 1;" ::: "memory");
        } else {
            asm volatile("cp.async.wait_group 0;" ::: "memory");
        }
        __syncthreads();

        const uint32_t kb = sb + AT_KV0 + (kt & 1) * AT_STAGE;

        if (kt <= qta)
            attn_step(kb, qhA, oA, mA, lA, kt == qta, wid, lid);
        attn_step(kb, qhB, oB, mB, lB, kt == qtb, wid, lid);
    }

    attn_epilogue(oA, lA, gbase, qta * 64, wid, lid, oh);
    attn_epilogue(oB, lB, gbase, qtb * 64, wid, lid, oh);
}

// ============================ launch ============================
extern "C" void kernel_launch(void* const* d_in, const int* in_sizes, int n_in,
                              void* d_out, int out_size)
{
    const float* x   = (const float*)d_in[0];
    const float* Wq  = (const float*)d_in[1];
    const float* Wk  = (const float*)d_in[2];
    const float* Wv  = (const float*)d_in[3];
    const float* Wo  = (const float*)d_in[4];
    const int*   pos = (const int*)  d_in[5];
    float* out = (float*)d_out;

    __half *xh, *wh, *qh, *kh, *vh, *oh;
    cudaGetSymbolAddress((void**)&xh, g_xh);
    cudaGetSymbolAddress((void**)&wh, g_wh);
    cudaGetSymbolAddress((void**)&qh, g_qh);
    cudaGetSymbolAddress((void**)&kh, g_kh);
    cudaGetSymbolAddress((void**)&vh, g_vh);
    cudaGetSymbolAddress((void**)&oh, g_oh);

    cudaFuncSetAttribute(gemm_qkv_fused, cudaFuncAttributeMaxDynamicSharedMemorySize, GS_SMEM);
    cudaFuncSetAttribute(gemm_out,       cudaFuncAttributeMaxDynamicSharedMemorySize, GS_SMEM);
    cudaFuncSetAttribute(attn_mma,       cudaFuncAttributeMaxDynamicSharedMemorySize, AT_SMEM);

    const int nx4 = BL_ * D_ / 4;
    const int nw4 = D_ * D_ / 4;

    conv_h<<<nx4 / 256, 256>>>(x, xh, nx4);
    conv_w4<<<dim3(nw4 / 256, 4), 256>>>(Wq, Wk, Wv, Wo, wh);

    dim3 qkv_grid(D_ / 128, BL_ / 128, 3);
    gemm_qkv_fused<<<qkv_grid, 256, GS_SMEM>>>(xh, wh, pos, qh, kh, vh);

    attn_mma<<<dim3(L_ / 128, H_, B_), 128, AT_SMEM>>>(qh, kh, vh, oh);

    dim3 ggrid(D_ / 128, BL_ / 128);
    gemm_out<<<ggrid, 256, GS_SMEM>>>(oh, wh + 3 * (size_t)D_ * D_, out);
}